// round 3
// baseline (speedup 1.0000x reference)
#include <cuda_runtime.h>
#include <cstddef>

#define NN 32
#define CC 256
#define HH 56
#define WW 56
#define HW (HH*WW)
#define OC2 80
#define NBAND 432
#define INV_SQRT2 0.7071067811865476f

__constant__ int c_di[8] = {1,-1,0,0,1,1,-1,-1};
__constant__ int c_dj[8] = {0,0,1,-1,1,-1,1,-1};

// Scratch (static device globals)
__device__ float g_weff[(size_t)CC*25*CC];        // [c][tap5x5][o]
__device__ float g_wt  [(size_t)8*9*CC*CC];       // [g*9+tap3x3][c][o], scale baked
__device__ float g_xb  [(size_t)NBAND*CC*NN];     // [band][c][n]
__device__ float g_h   [(size_t)NN*CC*HW];        // hidden activations

// Band (width-2 border frame) index <-> position
__device__ __forceinline__ int band_id(int i, int j) {
    if (i < 2)   return i*WW + j;
    if (i >= 54) return 112 + (i-54)*WW + j;
    int k = (j < 2) ? j : (j - 52);
    return 224 + (i-2)*4 + k;
}
__device__ __forceinline__ void band_pos(int id, int& i, int& j) {
    if (id < 112)      { i = id/WW;           j = id%WW; }
    else if (id < 224) { int t = id-112; i = 54 + t/WW; j = t%WW; }
    else               { int t = id-224; i = 2 + t/4; int k = t%4; j = (k<2)?k:(52+k); }
}

// ---- Fold 9-group 3x3 weights into effective 5x5 ----
__global__ void fold_kernel(const float* __restrict__ w1) {
    int idx = blockIdx.x * blockDim.x + threadIdx.x;
    if (idx >= CC*25*CC) return;
    int o   = idx % CC;
    int tap = (idx / CC) % 25;
    int c   = idx / (CC*25);
    int du = tap/5 - 2, dv = tap%5 - 2;
    float t = 0.f;
    if (du >= -1 && du <= 1 && dv >= -1 && dv <= 1) {
        int a = du + 1, b = dv + 1;
        t += w1[(((size_t)o*2304 + c)*3 + a)*3 + b];
        #pragma unroll
        for (int g = 0; g < 8; g++) {
            float s = (g < 4) ? 1.f : INV_SQRT2;
            t += s * w1[(((size_t)o*2304 + (g+1)*CC + c)*3 + a)*3 + b];
        }
    }
    #pragma unroll
    for (int g = 0; g < 8; g++) {
        int a = du + c_di[g] + 1, b = dv + c_dj[g] + 1;
        if (a >= 0 && a < 3 && b >= 0 && b < 3) {
            float s = (g < 4) ? 1.f : INV_SQRT2;
            t -= s * w1[(((size_t)o*2304 + (g+1)*CC + c)*3 + a)*3 + b];
        }
    }
    g_weff[((size_t)c*25 + tap)*CC + o] = t;
}

// ---- Transpose diff-group weights for border correction ----
__global__ void tw1_kernel(const float* __restrict__ w1) {
    size_t idx = (size_t)blockIdx.x * blockDim.x + threadIdx.x;
    if (idx >= (size_t)8*9*CC*CC) return;
    int o   = idx % CC;
    int c   = (idx / CC) % CC;
    int tap = (idx / ((size_t)CC*CC)) % 9;
    int g   = idx / ((size_t)CC*CC*9);
    float s = (g < 4) ? 1.f : INV_SQRT2;
    g_wt[(((size_t)(g*9 + tap))*CC + c)*CC + o] =
        s * w1[(((size_t)o*2304 + (g+1)*CC + c))*9 + tap];
}

// ---- Gather border-band x into compact [band][c][n] buffer ----
__global__ void gather_kernel(const float* __restrict__ x) {
    size_t idx = (size_t)blockIdx.x * blockDim.x + threadIdx.x;
    if (idx >= (size_t)NBAND*CC*NN) return;
    int n   = idx % NN;
    int c   = (idx / NN) % CC;
    int rid = idx / (NN*CC);
    int i, j; band_pos(rid, i, j);
    g_xb[idx] = x[((size_t)n*CC + c)*HW + i*WW + j];
}

// ---- 5x5 conv (folded), zero-pad 2 -> g_h ----
__global__ void __launch_bounds__(224) conv5_kernel(const float* __restrict__ x,
                                                    const float* __restrict__ b1) {
    __shared__ __align__(16) float ws[4][25][64];
    __shared__ __align__(16) float xs[4][8][68];
    int tid = threadIdx.x;
    int og  = tid / 28;
    int pg  = tid % 28;
    int r   = pg / 7;
    int j0  = (pg % 7) * 8;
    int obase = blockIdx.x * 64;
    int i0    = blockIdx.y * 4;
    int n     = blockIdx.z;
    const float* xn = x + (size_t)n * CC * HW;

    float acc[8][8];
    #pragma unroll
    for (int a = 0; a < 8; a++)
        #pragma unroll
        for (int b = 0; b < 8; b++) acc[a][b] = 0.f;

    for (int cb = 0; cb < CC; cb += 4) {
        for (int e = tid; e < 4*25*64; e += 224) {
            int c = e / (25*64), tap = (e/64) % 25, o = e % 64;
            ws[c][tap][o] = g_weff[((size_t)(cb + c)*25 + tap)*CC + obase + o];
        }
        for (int e = tid; e < 4*8*68; e += 224) {
            int c = e / (8*68), rr = (e/68) % 8, cc = e % 68;
            int gi = i0 - 2 + rr, gj = cc - 2;
            float v = 0.f;
            if (gi >= 0 && gi < HH && gj >= 0 && gj < WW)
                v = xn[(size_t)(cb + c)*HW + gi*WW + gj];
            xs[c][rr][cc] = v;
        }
        __syncthreads();

        #pragma unroll 1
        for (int c = 0; c < 4; c++) {
            #pragma unroll 1
            for (int du = 0; du < 5; du++) {
                const float* xr = &xs[c][r + du][j0];
                const float* wr = &ws[c][du*5][og*8];
                #pragma unroll 1
                for (int dv = 0; dv < 5; dv++) {
                    float wv[8], xv[8];
                    #pragma unroll
                    for (int oo = 0; oo < 8; oo++) wv[oo] = wr[dv*64 + oo];
                    #pragma unroll
                    for (int jj = 0; jj < 8; jj++) xv[jj] = xr[dv + jj];
                    #pragma unroll
                    for (int oo = 0; oo < 8; oo++)
                        #pragma unroll
                        for (int jj = 0; jj < 8; jj++)
                            acc[oo][jj] += wv[oo] * xv[jj];
                }
            }
        }
        __syncthreads();
    }

    #pragma unroll
    for (int oo = 0; oo < 8; oo++) {
        int o = obase + og*8 + oo;
        float bb = b1[o];
        float* hp = g_h + ((size_t)n*CC + o)*HW + (i0 + r)*WW + j0;
        #pragma unroll
        for (int jj = 0; jj < 8; jj++) hp[jj] = acc[oo][jj] + bb;
    }
}

// ---- Exact border correction: block = border pixel, thread = out channel ----
__global__ void __launch_bounds__(256) corr_kernel() {
    __shared__ __align__(16) float xs[32][32];
    int o = threadIdx.x;
    int pi, pj; band_pos(blockIdx.x, pi, pj);
    float acc[NN];
    #pragma unroll
    for (int n = 0; n < NN; n++) acc[n] = 0.f;

    for (int g = 0; g < 8; g++) {
        int di = c_di[g], dj = c_dj[g];
        for (int a = 0; a < 3; a++) {
            for (int b = 0; b < 3; b++) {
                int qi = pi + a - 1, qj = pj + b - 1;
                int ui = qi - di,     uj = qj - dj;
                bool qin = ((unsigned)qi < HH) && ((unsigned)qj < WW);
                bool uin = ((unsigned)ui < HH) && ((unsigned)uj < WW);
                float sgn; int ri, rj;
                if (qin && !uin)      { sgn = -1.f; ri = qi; rj = qj; }
                else if (!qin && uin) { sgn =  1.f; ri = ui; rj = uj; }
                else continue;
                int rid = band_id(ri, rj);
                const float* xbp = g_xb + (size_t)rid * CC * NN;
                const float* wp  = g_wt + (size_t)(g*9 + a*3 + b) * CC * CC + o;
                for (int cb = 0; cb < CC; cb += 32) {
                    __syncthreads();
                    for (int e = o; e < 32*NN; e += 256)
                        xs[e / NN][e % NN] = xbp[(size_t)cb*NN + e];
                    __syncthreads();
                    #pragma unroll 1
                    for (int c = 0; c < 32; c++) {
                        float w = sgn * wp[(size_t)(cb + c) * CC];
                        #pragma unroll
                        for (int n4 = 0; n4 < 8; n4++) {
                            float4 v = *(const float4*)&xs[c][n4*4];
                            acc[n4*4+0] += w * v.x;
                            acc[n4*4+1] += w * v.y;
                            acc[n4*4+2] += w * v.z;
                            acc[n4*4+3] += w * v.w;
                        }
                    }
                }
            }
        }
    }
    size_t base = (size_t)o*HW + pi*WW + pj;
    #pragma unroll
    for (int n = 0; n < NN; n++)
        g_h[(size_t)n*CC*HW + base] += acc[n];
}

// ---- 1x1 conv: out[n,80,p] ----
__global__ void __launch_bounds__(256) conv1x1_kernel(const float* __restrict__ w2,
                                                      const float* __restrict__ b2,
                                                      float* __restrict__ out) {
    __shared__ __align__(16) float hs[32][128];
    __shared__ __align__(16) float ws2[32][80];
    int tid = threadIdx.x;
    int n = blockIdx.y;
    int pbase = blockIdx.x * 128;
    int pxg = tid % 32, ocg = tid / 32;
    int px0 = pxg * 4, oc0 = ocg * 10;

    float acc[10][4];
    #pragma unroll
    for (int k = 0; k < 10; k++)
        #pragma unroll
        for (int j = 0; j < 4; j++) acc[k][j] = 0.f;

    for (int cb = 0; cb < CC; cb += 32) {
        for (int e = tid; e < 32*128; e += 256) {
            int c = e / 128, p = e % 128;
            int gp = pbase + p;
            hs[c][p] = (gp < HW) ? g_h[((size_t)n*CC + cb + c)*HW + gp] : 0.f;
        }
        for (int e = tid; e < 32*80; e += 256) {
            int c = e / 80, oc = e % 80;
            ws2[c][oc] = w2[(size_t)oc*CC + cb + c];
        }
        __syncthreads();
        #pragma unroll 1
        for (int c = 0; c < 32; c++) {
            float4 hv = *(const float4*)&hs[c][px0];
            #pragma unroll
            for (int k = 0; k < 10; k++) {
                float wv = ws2[c][oc0 + k];
                acc[k][0] += wv * hv.x;
                acc[k][1] += wv * hv.y;
                acc[k][2] += wv * hv.z;
                acc[k][3] += wv * hv.w;
            }
        }
        __syncthreads();
    }

    #pragma unroll
    for (int k = 0; k < 10; k++) {
        int oc = oc0 + k;
        float bb = b2[oc];
        #pragma unroll
        for (int j = 0; j < 4; j++) {
            int gp = pbase + px0 + j;
            if (gp < HW)
                out[((size_t)n*OC2 + oc)*HW + gp] = acc[k][j] + bb;
        }
    }
}

extern "C" void kernel_launch(void* const* d_in, const int* in_sizes, int n_in,
                              void* d_out, int out_size) {
    const float *x = nullptr, *w1 = nullptr, *b1 = nullptr, *w2 = nullptr, *b2 = nullptr;
    for (int i = 0; i < n_in; i++) {
        long s = in_sizes[i];
        const float* p = (const float*)d_in[i];
        if      (s == (long)NN*CC*HW)   x  = p;
        else if (s == (long)CC*9*CC*9)  w1 = p;
        else if (s == CC)               b1 = p;
        else if (s == (long)OC2*CC)     w2 = p;
        else if (s == OC2)              b2 = p;
    }
    float* out = (float*)d_out;

    fold_kernel<<<(CC*25*CC + 255)/256, 256>>>(w1);
    tw1_kernel<<<(int)(((size_t)8*9*CC*CC + 255)/256), 256>>>(w1);
    gather_kernel<<<(NBAND*CC*NN + 255)/256, 256>>>(x);
    conv5_kernel<<<dim3(4, 14, NN), 224>>>(x, b1);
    corr_kernel<<<NBAND, 256>>>();
    conv1x1_kernel<<<dim3(25, NN), 256>>>(w2, b2, out);
}

// round 5
// speedup vs baseline: 2.3979x; 2.3979x over previous
#include <cuda_runtime.h>
#include <cuda_fp16.h>
#include <cstdint>
#include <cstddef>

#define NN 32
#define CC 256
#define HH 56
#define WW 56
#define HW (HH*WW)
#define OC2 80
#define NBAND 432
#define INV_SQRT2 0.7071067811865476f

__constant__ int c_di[8] = {1,-1,0,0,1,1,-1,-1};
__constant__ int c_dj[8] = {0,0,1,-1,1,-1,1,-1};

// Scratch (static device globals)
__device__ float g_weff[(size_t)CC*25*CC];        // [c][tap5x5][o]
__device__ float g_wt  [(size_t)8*9*CC*CC];       // [g*9+tap3x3][c][o]
__device__ float g_xb  [(size_t)NBAND*CC*NN];     // [band][c][n]
__device__ float g_h   [(size_t)NN*CC*HW];        // hidden activations
__device__ __half g_wAh[(size_t)1600*2048];       // A tiles: [((ot*25+tap)*16+cc)*2+split][o*16+c]

// ---------------- band helpers ----------------
__device__ __forceinline__ int band_id(int i, int j) {
    if (i < 2)   return i*WW + j;
    if (i >= 54) return 112 + (i-54)*WW + j;
    int k = (j < 2) ? j : (j - 52);
    return 224 + (i-2)*4 + k;
}
__device__ __forceinline__ void band_pos(int id, int& i, int& j) {
    if (id < 112)      { i = id/WW;           j = id%WW; }
    else if (id < 224) { int t = id-112; i = 54 + t/WW; j = t%WW; }
    else               { int t = id-224; i = 2 + t/4; int k = t%4; j = (k<2)?k:(52+k); }
}

// ---------------- fold 9-group 3x3 -> effective 5x5 ----------------
__global__ void fold_kernel(const float* __restrict__ w1) {
    int idx = blockIdx.x * blockDim.x + threadIdx.x;
    if (idx >= CC*25*CC) return;
    int o   = idx % CC;
    int tap = (idx / CC) % 25;
    int c   = idx / (CC*25);
    int du = tap/5 - 2, dv = tap%5 - 2;
    float t = 0.f;
    if (du >= -1 && du <= 1 && dv >= -1 && dv <= 1) {
        int a = du + 1, b = dv + 1;
        t += w1[(((size_t)o*2304 + c)*3 + a)*3 + b];
        #pragma unroll
        for (int g = 0; g < 8; g++) {
            float s = (g < 4) ? 1.f : INV_SQRT2;
            t += s * w1[(((size_t)o*2304 + (g+1)*CC + c)*3 + a)*3 + b];
        }
    }
    #pragma unroll
    for (int g = 0; g < 8; g++) {
        int a = du + c_di[g] + 1, b = dv + c_dj[g] + 1;
        if (a >= 0 && a < 3 && b >= 0 && b < 3) {
            float s = (g < 4) ? 1.f : INV_SQRT2;
            t -= s * w1[(((size_t)o*2304 + (g+1)*CC + c)*3 + a)*3 + b];
        }
    }
    g_weff[((size_t)c*25 + tap)*CC + o] = t;
}

// ---------------- transpose diff-group weights for correction ----------------
__global__ void tw1_kernel(const float* __restrict__ w1) {
    size_t idx = (size_t)blockIdx.x * blockDim.x + threadIdx.x;
    if (idx >= (size_t)8*9*CC*CC) return;
    int o   = idx % CC;
    int c   = (idx / CC) % CC;
    int tap = (idx / ((size_t)CC*CC)) % 9;
    int g   = idx / ((size_t)CC*CC*9);
    float s = (g < 4) ? 1.f : INV_SQRT2;
    g_wt[(((size_t)(g*9 + tap))*CC + c)*CC + o] =
        s * w1[(((size_t)o*2304 + (g+1)*CC + c))*9 + tap];
}

// ---------------- gather band x ----------------
__global__ void gather_kernel(const float* __restrict__ x) {
    size_t idx = (size_t)blockIdx.x * blockDim.x + threadIdx.x;
    if (idx >= (size_t)NBAND*CC*NN) return;
    int n   = idx % NN;
    int c   = (idx / NN) % CC;
    int rid = idx / (NN*CC);
    int i, j; band_pos(rid, i, j);
    g_xb[idx] = x[((size_t)n*CC + c)*HW + i*WW + j];
}

// ---------------- weight prep: Weff -> fp16 hi/lo A tiles ----------------
// tile = ((ot*25+tap)*16+cc)*2+split ; element idx = o*16 + c (row-major [128 o][16 c])
__global__ void wprep_kernel() {
    int idx = blockIdx.x * blockDim.x + threadIdx.x;
    if (idx >= 1600*2048) return;
    int e    = idx & 2047;
    int tile = idx >> 11;
    int o = e >> 4, c = e & 15;
    int split = tile & 1;
    int t2 = tile >> 1;
    int ccv = t2 & 15;
    int t3 = t2 >> 4;
    int tap = t3 % 25, ot = t3 / 25;
    float v = g_weff[(((size_t)(ccv*16 + c))*25 + tap)*CC + ot*128 + o];
    __half h = __float2half_rn(v);
    __half out = split ? __float2half_rn(v - __half2float(h)) : h;
    g_wAh[idx] = out;
}

// ---------------- conv5 via mma.sync m16n8k16 (fp16-split implicit GEMM) ----
#define MMA16816(cacc, a, b0, b1) \
    asm volatile("mma.sync.aligned.m16n8k16.row.col.f32.f16.f16.f32 " \
        "{%0,%1,%2,%3}, {%4,%5,%6,%7}, {%8,%9}, {%0,%1,%2,%3};" \
        : "+f"((cacc)[0]),"+f"((cacc)[1]),"+f"((cacc)[2]),"+f"((cacc)[3]) \
        : "r"((a)[0]),"r"((a)[1]),"r"((a)[2]),"r"((a)[3]), "r"(b0),"r"(b1))

__global__ void __launch_bounds__(256) conv5_mma_kernel(const float* __restrict__ x,
                                                        const float* __restrict__ b1) {
    // stage: 8 rows x 60 cols x 24 halfs (16 used + 8 pad => 48B px-stride, conflict-free)
    __shared__ __half SH[8*60*24];
    __shared__ __half SL[8*60*24];

    int tid  = threadIdx.x;
    int lane = tid & 31, wid = tid >> 5;
    int wm = wid & 3, wn = wid >> 2;          // warp grid 4m x 2n
    int ot = blockIdx.x;                       // 0..1 (128 outch each)
    int i0 = blockIdx.y * 4;                   // output row tile (4 rows)
    int n  = blockIdx.z;
    const float* xn = x + (size_t)n * CC * HW;

    float acc[2][14][4];
    #pragma unroll
    for (int mf = 0; mf < 2; mf++)
        #pragma unroll
        for (int nf = 0; nf < 14; nf++)
            #pragma unroll
            for (int q = 0; q < 4; q++) acc[mf][nf][q] = 0.f;

    // per-thread fragment offsets
    int boff[14];
    #pragma unroll
    for (int nf = 0; nf < 14; nf++) {
        int px = wn*112 + nf*8 + (lane >> 2);
        int r = px / 56, j = px % 56;
        boff[nf] = (r*60 + j)*24 + 2*(lane & 3);
    }
    int aoff = (wm*32 + (lane >> 2))*16 + 2*(lane & 3);

    #pragma unroll 1
    for (int cc = 0; cc < 16; cc++) {
        __syncthreads();
        // stage x window: rows i0-2..i0+5, cols -2..57, 16 channels, hi/lo split
        #pragma unroll 1
        for (int e = tid; e < 7680; e += 256) {
            int col = e % 60;
            int row = (e / 60) & 7;
            int c   = e / 480;
            int gi = i0 - 2 + row, gj = col - 2;
            float v = 0.f;
            if ((unsigned)gi < HH && (unsigned)gj < WW)
                v = xn[(size_t)(cc*16 + c)*HW + gi*WW + gj];
            __half h = __float2half_rn(v);
            __half l = __float2half_rn(v - __half2float(h));
            int sa = (row*60 + col)*24 + c;
            SH[sa] = h;
            SL[sa] = l;
        }
        __syncthreads();

        #pragma unroll 1
        for (int tap = 0; tap < 25; tap++) {
            int du = tap / 5, dv = tap % 5;
            const __half* tH = g_wAh + (size_t)(((ot*25 + tap)*16 + cc)*2)*2048;
            const __half* tL = tH + 2048;

            uint32_t ah[2][4], al[2][4];
            #pragma unroll
            for (int mf = 0; mf < 2; mf++) {
                const __half* pH = tH + mf*256 + aoff;
                const __half* pL = tL + mf*256 + aoff;
                ah[mf][0] = *(const uint32_t*)(pH);
                ah[mf][1] = *(const uint32_t*)(pH + 128);
                ah[mf][2] = *(const uint32_t*)(pH + 8);
                ah[mf][3] = *(const uint32_t*)(pH + 136);
                al[mf][0] = *(const uint32_t*)(pL);
                al[mf][1] = *(const uint32_t*)(pL + 128);
                al[mf][2] = *(const uint32_t*)(pL + 8);
                al[mf][3] = *(const uint32_t*)(pL + 136);
            }

            int toff = (du*60 + dv)*24;
            #pragma unroll
            for (int nf = 0; nf < 14; nf++) {
                const __half* bh = SH + boff[nf] + toff;
                const __half* bl = SL + boff[nf] + toff;
                uint32_t b0h = *(const uint32_t*)(bh);
                uint32_t b1h = *(const uint32_t*)(bh + 8);
                uint32_t b0l = *(const uint32_t*)(bl);
                uint32_t b1l = *(const uint32_t*)(bl + 8);
                #pragma unroll
                for (int mf = 0; mf < 2; mf++) {
                    MMA16816(acc[mf][nf], ah[mf], b0h, b1h);
                    MMA16816(acc[mf][nf], ah[mf], b0l, b1l);
                    MMA16816(acc[mf][nf], al[mf], b0h, b1h);
                }
            }
        }
    }

    // epilogue: +bias, write 224 contiguous px per o-row
    int r = lane >> 2, q = 2*(lane & 3);
    #pragma unroll
    for (int mf = 0; mf < 2; mf++) {
        int o0 = ot*128 + wm*32 + mf*16 + r;
        float bb0 = b1[o0], bb1 = b1[o0 + 8];
        float* h0 = g_h + ((size_t)n*CC + o0)*HW + i0*WW;
        float* h1 = h0 + (size_t)8*HW;
        #pragma unroll
        for (int nf = 0; nf < 14; nf++) {
            int px = wn*112 + nf*8 + q;
            float2 v0 = make_float2(acc[mf][nf][0] + bb0, acc[mf][nf][1] + bb0);
            float2 v1 = make_float2(acc[mf][nf][2] + bb1, acc[mf][nf][3] + bb1);
            *(float2*)(h0 + px) = v0;
            *(float2*)(h1 + px) = v1;
        }
    }
}

// ---------------- exact border correction ----------------
__global__ void __launch_bounds__(256) corr_kernel() {
    __shared__ __align__(16) float xs[32][32];
    int o = threadIdx.x;
    int pi, pj; band_pos(blockIdx.x, pi, pj);
    float acc[NN];
    #pragma unroll
    for (int n = 0; n < NN; n++) acc[n] = 0.f;

    for (int g = 0; g < 8; g++) {
        int di = c_di[g], dj = c_dj[g];
        for (int a = 0; a < 3; a++) {
            for (int b = 0; b < 3; b++) {
                int qi = pi + a - 1, qj = pj + b - 1;
                int ui = qi - di,     uj = qj - dj;
                bool qin = ((unsigned)qi < HH) && ((unsigned)qj < WW);
                bool uin = ((unsigned)ui < HH) && ((unsigned)uj < WW);
                float sgn; int ri, rj;
                if (qin && !uin)      { sgn = -1.f; ri = qi; rj = qj; }
                else if (!qin && uin) { sgn =  1.f; ri = ui; rj = uj; }
                else continue;
                int rid = band_id(ri, rj);
                const float* xbp = g_xb + (size_t)rid * CC * NN;
                const float* wp  = g_wt + (size_t)(g*9 + a*3 + b) * CC * CC + o;
                for (int cb = 0; cb < CC; cb += 32) {
                    __syncthreads();
                    for (int e = o; e < 32*NN; e += 256)
                        xs[e / NN][e % NN] = xbp[(size_t)cb*NN + e];
                    __syncthreads();
                    #pragma unroll 1
                    for (int c = 0; c < 32; c++) {
                        float w = sgn * wp[(size_t)(cb + c) * CC];
                        #pragma unroll
                        for (int n4 = 0; n4 < 8; n4++) {
                            float4 v = *(const float4*)&xs[c][n4*4];
                            acc[n4*4+0] += w * v.x;
                            acc[n4*4+1] += w * v.y;
                            acc[n4*4+2] += w * v.z;
                            acc[n4*4+3] += w * v.w;
                        }
                    }
                }
            }
        }
    }
    size_t base = (size_t)o*HW + pi*WW + pj;
    #pragma unroll
    for (int n = 0; n < NN; n++)
        g_h[(size_t)n*CC*HW + base] += acc[n];
}

// ---------------- 1x1 conv ----------------
__global__ void __launch_bounds__(256) conv1x1_kernel(const float* __restrict__ w2,
                                                      const float* __restrict__ b2,
                                                      float* __restrict__ out) {
    __shared__ __align__(16) float hs[32][128];
    __shared__ __align__(16) float ws2[32][80];
    int tid = threadIdx.x;
    int n = blockIdx.y;
    int pbase = blockIdx.x * 128;
    int pxg = tid % 32, ocg = tid / 32;
    int px0 = pxg * 4, oc0 = ocg * 10;

    float acc[10][4];
    #pragma unroll
    for (int k = 0; k < 10; k++)
        #pragma unroll
        for (int j = 0; j < 4; j++) acc[k][j] = 0.f;

    for (int cb = 0; cb < CC; cb += 32) {
        for (int e = tid; e < 32*128; e += 256) {
            int c = e / 128, p = e % 128;
            int gp = pbase + p;
            hs[c][p] = (gp < HW) ? g_h[((size_t)n*CC + cb + c)*HW + gp] : 0.f;
        }
        for (int e = tid; e < 32*80; e += 256) {
            int c = e / 80, oc = e % 80;
            ws2[c][oc] = w2[(size_t)oc*CC + cb + c];
        }
        __syncthreads();
        #pragma unroll 1
        for (int c = 0; c < 32; c++) {
            float4 hv = *(const float4*)&hs[c][px0];
            #pragma unroll
            for (int k = 0; k < 10; k++) {
                float wv = ws2[c][oc0 + k];
                acc[k][0] += wv * hv.x;
                acc[k][1] += wv * hv.y;
                acc[k][2] += wv * hv.z;
                acc[k][3] += wv * hv.w;
            }
        }
        __syncthreads();
    }

    #pragma unroll
    for (int k = 0; k < 10; k++) {
        int oc = oc0 + k;
        float bb = b2[oc];
        #pragma unroll
        for (int j = 0; j < 4; j++) {
            int gp = pbase + px0 + j;
            if (gp < HW)
                out[((size_t)n*OC2 + oc)*HW + gp] = acc[k][j] + bb;
        }
    }
}

extern "C" void kernel_launch(void* const* d_in, const int* in_sizes, int n_in,
                              void* d_out, int out_size) {
    const float *x = nullptr, *w1 = nullptr, *b1 = nullptr, *w2 = nullptr, *b2 = nullptr;
    for (int i = 0; i < n_in; i++) {
        long s = in_sizes[i];
        const float* p = (const float*)d_in[i];
        if      (s == (long)NN*CC*HW)   x  = p;
        else if (s == (long)CC*9*CC*9)  w1 = p;
        else if (s == CC)               b1 = p;
        else if (s == (long)OC2*CC)     w2 = p;
        else if (s == OC2)              b2 = p;
    }
    float* out = (float*)d_out;

    fold_kernel<<<(CC*25*CC + 255)/256, 256>>>(w1);
    wprep_kernel<<<(1600*2048 + 255)/256, 256>>>();
    tw1_kernel<<<(int)(((size_t)8*9*CC*CC + 255)/256), 256>>>(w1);
    gather_kernel<<<(NBAND*CC*NN + 255)/256, 256>>>(x);
    conv5_mma_kernel<<<dim3(2, 14, NN), 256>>>(x, b1);
    corr_kernel<<<NBAND, 256>>>();
    conv1x1_kernel<<<dim3(25, NN), 256>>>(w2, b2, out);
}

// round 6
// speedup vs baseline: 2.7858x; 1.1618x over previous
#include <cuda_runtime.h>
#include <cuda_fp16.h>
#include <cstdint>
#include <cstddef>

#define NN 32
#define CC 256
#define HH 56
#define WW 56
#define HW (HH*WW)
#define OC2 80
#define NBAND 432
#define INV_SQRT2 0.7071067811865476f

__constant__ int c_di[8] = {1,-1,0,0,1,1,-1,-1};
__constant__ int c_dj[8] = {0,0,1,-1,1,-1,1,-1};

// Scratch (static device globals)
__device__ float g_weff[(size_t)CC*25*CC];        // [c][tap5x5][o]
__device__ float g_wt  [(size_t)8*9*CC*CC];       // [g*9+tap3x3][c][o]
__device__ float g_xb  [(size_t)NBAND*CC*NN];     // [band][c][n]
__device__ float g_h   [(size_t)NN*CC*HW];        // hidden activations
__device__ __half g_wAh[(size_t)1600*2048];       // A tiles: [((ot*25+tap)*16+cc)*2+split][o*16+c]

// ---------------- band helpers ----------------
__device__ __forceinline__ int band_id(int i, int j) {
    if (i < 2)   return i*WW + j;
    if (i >= 54) return 112 + (i-54)*WW + j;
    int k = (j < 2) ? j : (j - 52);
    return 224 + (i-2)*4 + k;
}
__device__ __forceinline__ void band_pos(int id, int& i, int& j) {
    if (id < 112)      { i = id/WW;           j = id%WW; }
    else if (id < 224) { int t = id-112; i = 54 + t/WW; j = t%WW; }
    else               { int t = id-224; i = 2 + t/4; int k = t%4; j = (k<2)?k:(52+k); }
}

// ---------------- fold 9-group 3x3 -> effective 5x5 ----------------
__global__ void fold_kernel(const float* __restrict__ w1) {
    int idx = blockIdx.x * blockDim.x + threadIdx.x;
    if (idx >= CC*25*CC) return;
    int o   = idx % CC;
    int tap = (idx / CC) % 25;
    int c   = idx / (CC*25);
    int du = tap/5 - 2, dv = tap%5 - 2;
    float t = 0.f;
    if (du >= -1 && du <= 1 && dv >= -1 && dv <= 1) {
        int a = du + 1, b = dv + 1;
        t += w1[(((size_t)o*2304 + c)*3 + a)*3 + b];
        #pragma unroll
        for (int g = 0; g < 8; g++) {
            float s = (g < 4) ? 1.f : INV_SQRT2;
            t += s * w1[(((size_t)o*2304 + (g+1)*CC + c)*3 + a)*3 + b];
        }
    }
    #pragma unroll
    for (int g = 0; g < 8; g++) {
        int a = du + c_di[g] + 1, b = dv + c_dj[g] + 1;
        if (a >= 0 && a < 3 && b >= 0 && b < 3) {
            float s = (g < 4) ? 1.f : INV_SQRT2;
            t -= s * w1[(((size_t)o*2304 + (g+1)*CC + c)*3 + a)*3 + b];
        }
    }
    g_weff[((size_t)c*25 + tap)*CC + o] = t;
}

// ---------------- transpose diff-group weights for correction ----------------
__global__ void tw1_kernel(const float* __restrict__ w1) {
    size_t idx = (size_t)blockIdx.x * blockDim.x + threadIdx.x;
    if (idx >= (size_t)8*9*CC*CC) return;
    int o   = idx % CC;
    int c   = (idx / CC) % CC;
    int tap = (idx / ((size_t)CC*CC)) % 9;
    int g   = idx / ((size_t)CC*CC*9);
    float s = (g < 4) ? 1.f : INV_SQRT2;
    g_wt[(((size_t)(g*9 + tap))*CC + c)*CC + o] =
        s * w1[(((size_t)o*2304 + (g+1)*CC + c))*9 + tap];
}

// ---------------- gather band x ----------------
__global__ void gather_kernel(const float* __restrict__ x) {
    size_t idx = (size_t)blockIdx.x * blockDim.x + threadIdx.x;
    if (idx >= (size_t)NBAND*CC*NN) return;
    int n   = idx % NN;
    int c   = (idx / NN) % CC;
    int rid = idx / (NN*CC);
    int i, j; band_pos(rid, i, j);
    g_xb[idx] = x[((size_t)n*CC + c)*HW + i*WW + j];
}

// ---------------- weight prep: Weff -> fp16 hi/lo A tiles ----------------
__global__ void wprep_kernel() {
    int idx = blockIdx.x * blockDim.x + threadIdx.x;
    if (idx >= 1600*2048) return;
    int e    = idx & 2047;
    int tile = idx >> 11;
    int o = e >> 4, c = e & 15;
    int split = tile & 1;
    int t2 = tile >> 1;
    int ccv = t2 & 15;
    int t3 = t2 >> 4;
    int tap = t3 % 25, ot = t3 / 25;
    float v = g_weff[(((size_t)(ccv*16 + c))*25 + tap)*CC + ot*128 + o];
    __half h = __float2half_rn(v);
    __half out = split ? __float2half_rn(v - __half2float(h)) : h;
    g_wAh[idx] = out;
}

// ---------------- conv5 via mma.sync m16n8k16 (2-split: A_hi x (B_hi+B_lo)) ----
#define MMA16816(cacc, a, b0, b1) \
    asm volatile("mma.sync.aligned.m16n8k16.row.col.f32.f16.f16.f32 " \
        "{%0,%1,%2,%3}, {%4,%5,%6,%7}, {%8,%9}, {%0,%1,%2,%3};" \
        : "+f"((cacc)[0]),"+f"((cacc)[1]),"+f"((cacc)[2]),"+f"((cacc)[3]) \
        : "r"((a)[0]),"r"((a)[1]),"r"((a)[2]),"r"((a)[3]), "r"(b0),"r"(b1))

__global__ void __launch_bounds__(256) conv5_mma_kernel(const float* __restrict__ x,
                                                        const float* __restrict__ b1) {
    // stage: 8 rows x 60 cols x 24 halfs (16 used + 8 pad => 48B px-stride, conflict-free)
    __shared__ __half SH[8*60*24];
    __shared__ __half SL[8*60*24];

    int tid  = threadIdx.x;
    int lane = tid & 31, wid = tid >> 5;
    int wm = wid & 3, wn = wid >> 2;          // warp grid 4m x 2n
    int ot = blockIdx.x;                       // 0..1 (128 outch each)
    int i0 = blockIdx.y * 4;                   // output row tile (4 rows)
    int n  = blockIdx.z;
    const float* xn = x + (size_t)n * CC * HW;

    float acc[2][14][4];
    #pragma unroll
    for (int mf = 0; mf < 2; mf++)
        #pragma unroll
        for (int nf = 0; nf < 14; nf++)
            #pragma unroll
            for (int q = 0; q < 4; q++) acc[mf][nf][q] = 0.f;

    // per-thread fragment offsets
    int boff[14];
    #pragma unroll
    for (int nf = 0; nf < 14; nf++) {
        int px = wn*112 + nf*8 + (lane >> 2);
        int r = px / 56, j = px % 56;
        boff[nf] = (r*60 + j)*24 + 2*(lane & 3);
    }
    int aoff = (wm*32 + (lane >> 2))*16 + 2*(lane & 3);

    #pragma unroll 1
    for (int cc = 0; cc < 16; cc++) {
        __syncthreads();
        // stage x window: rows i0-2..i0+5, cols -2..57, 16 channels, hi/lo split
        #pragma unroll 1
        for (int e = tid; e < 7680; e += 256) {
            int col = e % 60;
            int row = (e / 60) & 7;
            int c   = e / 480;
            int gi = i0 - 2 + row, gj = col - 2;
            float v = 0.f;
            if ((unsigned)gi < HH && (unsigned)gj < WW)
                v = xn[(size_t)(cc*16 + c)*HW + gi*WW + gj];
            __half h = __float2half_rn(v);
            __half l = __float2half_rn(v - __half2float(h));
            int sa = (row*60 + col)*24 + c;
            SH[sa] = h;
            SL[sa] = l;
        }
        __syncthreads();

        #pragma unroll 1
        for (int tap = 0; tap < 25; tap++) {
            int du = tap / 5, dv = tap % 5;
            const __half* tH = g_wAh + (size_t)(((ot*25 + tap)*16 + cc)*2)*2048;

            uint32_t ah[2][4];
            #pragma unroll
            for (int mf = 0; mf < 2; mf++) {
                const __half* pH = tH + mf*256 + aoff;
                ah[mf][0] = *(const uint32_t*)(pH);
                ah[mf][1] = *(const uint32_t*)(pH + 128);
                ah[mf][2] = *(const uint32_t*)(pH + 8);
                ah[mf][3] = *(const uint32_t*)(pH + 136);
            }

            int toff = (du*60 + dv)*24;
            #pragma unroll
            for (int nf = 0; nf < 14; nf++) {
                const __half* bh = SH + boff[nf] + toff;
                const __half* bl = SL + boff[nf] + toff;
                uint32_t b0h = *(const uint32_t*)(bh);
                uint32_t b1h = *(const uint32_t*)(bh + 8);
                uint32_t b0l = *(const uint32_t*)(bl);
                uint32_t b1l = *(const uint32_t*)(bl + 8);
                #pragma unroll
                for (int mf = 0; mf < 2; mf++) {
                    MMA16816(acc[mf][nf], ah[mf], b0h, b1h);
                    MMA16816(acc[mf][nf], ah[mf], b0l, b1l);
                }
            }
        }
    }

    // epilogue: +bias, write 224 contiguous px per o-row
    int r = lane >> 2, q = 2*(lane & 3);
    #pragma unroll
    for (int mf = 0; mf < 2; mf++) {
        int o0 = ot*128 + wm*32 + mf*16 + r;
        float bb0 = b1[o0], bb1 = b1[o0 + 8];
        float* h0 = g_h + ((size_t)n*CC + o0)*HW + i0*WW;
        float* h1 = h0 + (size_t)8*HW;
        #pragma unroll
        for (int nf = 0; nf < 14; nf++) {
            int px = wn*112 + nf*8 + q;
            float2 v0 = make_float2(acc[mf][nf][0] + bb0, acc[mf][nf][1] + bb0);
            float2 v1 = make_float2(acc[mf][nf][2] + bb1, acc[mf][nf][3] + bb1);
            *(float2*)(h0 + px) = v0;
            *(float2*)(h1 + px) = v1;
        }
    }
}

// ---------------- exact border correction ----------------
__global__ void __launch_bounds__(256) corr_kernel() {
    __shared__ __align__(16) float xs[32][32];
    int o = threadIdx.x;
    int pi, pj; band_pos(blockIdx.x, pi, pj);
    float acc[NN];
    #pragma unroll
    for (int n = 0; n < NN; n++) acc[n] = 0.f;

    for (int g = 0; g < 8; g++) {
        int di = c_di[g], dj = c_dj[g];
        for (int a = 0; a < 3; a++) {
            for (int b = 0; b < 3; b++) {
                int qi = pi + a - 1, qj = pj + b - 1;
                int ui = qi - di,     uj = qj - dj;
                bool qin = ((unsigned)qi < HH) && ((unsigned)qj < WW);
                bool uin = ((unsigned)ui < HH) && ((unsigned)uj < WW);
                float sgn; int ri, rj;
                if (qin && !uin)      { sgn = -1.f; ri = qi; rj = qj; }
                else if (!qin && uin) { sgn =  1.f; ri = ui; rj = uj; }
                else continue;
                int rid = band_id(ri, rj);
                const float* xbp = g_xb + (size_t)rid * CC * NN;
                const float* wp  = g_wt + (size_t)(g*9 + a*3 + b) * CC * CC + o;
                for (int cb = 0; cb < CC; cb += 32) {
                    __syncthreads();
                    for (int e = o; e < 32*NN; e += 256)
                        xs[e / NN][e % NN] = xbp[(size_t)cb*NN + e];
                    __syncthreads();
                    #pragma unroll 1
                    for (int c = 0; c < 32; c++) {
                        float w = sgn * wp[(size_t)(cb + c) * CC];
                        #pragma unroll
                        for (int n4 = 0; n4 < 8; n4++) {
                            float4 v = *(const float4*)&xs[c][n4*4];
                            acc[n4*4+0] += w * v.x;
                            acc[n4*4+1] += w * v.y;
                            acc[n4*4+2] += w * v.z;
                            acc[n4*4+3] += w * v.w;
                        }
                    }
                }
            }
        }
    }
    size_t base = (size_t)o*HW + pi*WW + pj;
    #pragma unroll
    for (int n = 0; n < NN; n++)
        g_h[(size_t)n*CC*HW + base] += acc[n];
}

// ---------------- 1x1 conv ----------------
__global__ void __launch_bounds__(256) conv1x1_kernel(const float* __restrict__ w2,
                                                      const float* __restrict__ b2,
                                                      float* __restrict__ out) {
    __shared__ __align__(16) float hs[32][128];
    __shared__ __align__(16) float ws2[32][80];
    int tid = threadIdx.x;
    int n = blockIdx.y;
    int pbase = blockIdx.x * 128;
    int pxg = tid % 32, ocg = tid / 32;
    int px0 = pxg * 4, oc0 = ocg * 10;

    float acc[10][4];
    #pragma unroll
    for (int k = 0; k < 10; k++)
        #pragma unroll
        for (int j = 0; j < 4; j++) acc[k][j] = 0.f;

    for (int cb = 0; cb < CC; cb += 32) {
        for (int e = tid; e < 32*128; e += 256) {
            int c = e / 128, p = e % 128;
            int gp = pbase + p;
            hs[c][p] = (gp < HW) ? g_h[((size_t)n*CC + cb + c)*HW + gp] : 0.f;
        }
        for (int e = tid; e < 32*80; e += 256) {
            int c = e / 80, oc = e % 80;
            ws2[c][oc] = w2[(size_t)oc*CC + cb + c];
        }
        __syncthreads();
        #pragma unroll 1
        for (int c = 0; c < 32; c++) {
            float4 hv = *(const float4*)&hs[c][px0];
            #pragma unroll
            for (int k = 0; k < 10; k++) {
                float wv = ws2[c][oc0 + k];
                acc[k][0] += wv * hv.x;
                acc[k][1] += wv * hv.y;
                acc[k][2] += wv * hv.z;
                acc[k][3] += wv * hv.w;
            }
        }
        __syncthreads();
    }

    #pragma unroll
    for (int k = 0; k < 10; k++) {
        int oc = oc0 + k;
        float bb = b2[oc];
        #pragma unroll
        for (int j = 0; j < 4; j++) {
            int gp = pbase + px0 + j;
            if (gp < HW)
                out[((size_t)n*OC2 + oc)*HW + gp] = acc[k][j] + bb;
        }
    }
}

extern "C" void kernel_launch(void* const* d_in, const int* in_sizes, int n_in,
                              void* d_out, int out_size) {
    const float *x = nullptr, *w1 = nullptr, *b1 = nullptr, *w2 = nullptr, *b2 = nullptr;
    for (int i = 0; i < n_in; i++) {
        long s = in_sizes[i];
        const float* p = (const float*)d_in[i];
        if      (s == (long)NN*CC*HW)   x  = p;
        else if (s == (long)CC*9*CC*9)  w1 = p;
        else if (s == CC)               b1 = p;
        else if (s == (long)OC2*CC)     w2 = p;
        else if (s == OC2)              b2 = p;
    }
    float* out = (float*)d_out;

    fold_kernel<<<(CC*25*CC + 255)/256, 256>>>(w1);
    wprep_kernel<<<(1600*2048 + 255)/256, 256>>>();
    tw1_kernel<<<(int)(((size_t)8*9*CC*CC + 255)/256), 256>>>(w1);
    gather_kernel<<<(NBAND*CC*NN + 255)/256, 256>>>(x);
    conv5_mma_kernel<<<dim3(2, 14, NN), 256>>>(x, b1);
    corr_kernel<<<NBAND, 256>>>();
    conv1x1_kernel<<<dim3(25, NN), 256>>>(w2, b2, out);
}

// round 7
// speedup vs baseline: 3.1715x; 1.1385x over previous
#include <cuda_runtime.h>
#include <cuda_fp16.h>
#include <cstdint>
#include <cstddef>

#define NN 32
#define CC 256
#define HH 56
#define WW 56
#define HW (HH*WW)
#define OC2 80
#define NBAND 432
#define INV_SQRT2 0.7071067811865476f

__constant__ int c_di[8] = {1,-1,0,0,1,1,-1,-1};
__constant__ int c_dj[8] = {0,0,1,-1,1,-1,1,-1};

// Scratch (static device globals)
__device__ float g_weff[(size_t)CC*25*CC];        // [c][tap5x5][o]
__device__ float g_wt  [(size_t)8*9*CC*CC];       // [g*9+tap3x3][c][o]
__device__ float g_xb  [(size_t)NBAND*CC*NN];     // [band][c][n]
__device__ float g_h   [(size_t)NN*CC*HW];        // hidden activations
__device__ __half g_wAh[(size_t)800*2048];        // A tiles (hi only): [(ot*25+tap)*16+cc][o*16+c]

// ---------------- band helpers ----------------
__device__ __forceinline__ int band_id(int i, int j) {
    if (i < 2)   return i*WW + j;
    if (i >= 54) return 112 + (i-54)*WW + j;
    int k = (j < 2) ? j : (j - 52);
    return 224 + (i-2)*4 + k;
}
__device__ __forceinline__ void band_pos(int id, int& i, int& j) {
    if (id < 112)      { i = id/WW;           j = id%WW; }
    else if (id < 224) { int t = id-112; i = 54 + t/WW; j = t%WW; }
    else               { int t = id-224; i = 2 + t/4; int k = t%4; j = (k<2)?k:(52+k); }
}

// ---------------- fold 9-group 3x3 -> effective 5x5 ----------------
__global__ void fold_kernel(const float* __restrict__ w1) {
    int idx = blockIdx.x * blockDim.x + threadIdx.x;
    if (idx >= CC*25*CC) return;
    int o   = idx % CC;
    int tap = (idx / CC) % 25;
    int c   = idx / (CC*25);
    int du = tap/5 - 2, dv = tap%5 - 2;
    float t = 0.f;
    if (du >= -1 && du <= 1 && dv >= -1 && dv <= 1) {
        int a = du + 1, b = dv + 1;
        t += w1[(((size_t)o*2304 + c)*3 + a)*3 + b];
        #pragma unroll
        for (int g = 0; g < 8; g++) {
            float s = (g < 4) ? 1.f : INV_SQRT2;
            t += s * w1[(((size_t)o*2304 + (g+1)*CC + c)*3 + a)*3 + b];
        }
    }
    #pragma unroll
    for (int g = 0; g < 8; g++) {
        int a = du + c_di[g] + 1, b = dv + c_dj[g] + 1;
        if (a >= 0 && a < 3 && b >= 0 && b < 3) {
            float s = (g < 4) ? 1.f : INV_SQRT2;
            t -= s * w1[(((size_t)o*2304 + (g+1)*CC + c)*3 + a)*3 + b];
        }
    }
    g_weff[((size_t)c*25 + tap)*CC + o] = t;
}

// ---------------- transpose diff-group weights for correction ----------------
__global__ void tw1_kernel(const float* __restrict__ w1) {
    size_t idx = (size_t)blockIdx.x * blockDim.x + threadIdx.x;
    if (idx >= (size_t)8*9*CC*CC) return;
    int o   = idx % CC;
    int c   = (idx / CC) % CC;
    int tap = (idx / ((size_t)CC*CC)) % 9;
    int g   = idx / ((size_t)CC*CC*9);
    float s = (g < 4) ? 1.f : INV_SQRT2;
    g_wt[(((size_t)(g*9 + tap))*CC + c)*CC + o] =
        s * w1[(((size_t)o*2304 + (g+1)*CC + c))*9 + tap];
}

// ---------------- gather band x ----------------
__global__ void gather_kernel(const float* __restrict__ x) {
    size_t idx = (size_t)blockIdx.x * blockDim.x + threadIdx.x;
    if (idx >= (size_t)NBAND*CC*NN) return;
    int n   = idx % NN;
    int c   = (idx / NN) % CC;
    int rid = idx / (NN*CC);
    int i, j; band_pos(rid, i, j);
    g_xb[idx] = x[((size_t)n*CC + c)*HW + i*WW + j];
}

// ---------------- weight prep: Weff -> fp16 hi A tiles ----------------
// tile = (ot*25+tap)*16+cc ; element idx = o*16 + c (row-major [128 o][16 c])
__global__ void wprep_kernel() {
    int idx = blockIdx.x * blockDim.x + threadIdx.x;
    if (idx >= 800*2048) return;
    int e    = idx & 2047;
    int tile = idx >> 11;
    int o = e >> 4, c = e & 15;
    int ccv = tile & 15;
    int t3 = tile >> 4;
    int tap = t3 % 25, ot = t3 / 25;
    float v = g_weff[(((size_t)(ccv*16 + c))*25 + tap)*CC + ot*128 + o];
    g_wAh[idx] = __float2half_rn(v);
}

// ---------------- conv5 via mma.sync m16n8k16 (single A_hi x B_hi) --------
#define MMA16816(cacc, a, b0, b1) \
    asm volatile("mma.sync.aligned.m16n8k16.row.col.f32.f16.f16.f32 " \
        "{%0,%1,%2,%3}, {%4,%5,%6,%7}, {%8,%9}, {%0,%1,%2,%3};" \
        : "+f"((cacc)[0]),"+f"((cacc)[1]),"+f"((cacc)[2]),"+f"((cacc)[3]) \
        : "r"((a)[0]),"r"((a)[1]),"r"((a)[2]),"r"((a)[3]), "r"(b0),"r"(b1))

__global__ void __launch_bounds__(256) conv5_mma_kernel(const float* __restrict__ x,
                                                        const float* __restrict__ b1) {
    // stage: 8 rows x 60 cols x 24 halfs (16 used + 8 pad => 48B px-stride, conflict-free)
    __shared__ __half SH[8*60*24];

    int tid  = threadIdx.x;
    int lane = tid & 31, wid = tid >> 5;
    int wm = wid & 3, wn = wid >> 2;          // warp grid 4m x 2n
    int ot = blockIdx.x;                       // 0..1 (128 outch each)
    int i0 = blockIdx.y * 4;                   // output row tile (4 rows)
    int n  = blockIdx.z;
    const float* xn = x + (size_t)n * CC * HW;

    float acc[2][14][4];
    #pragma unroll
    for (int mf = 0; mf < 2; mf++)
        #pragma unroll
        for (int nf = 0; nf < 14; nf++)
            #pragma unroll
            for (int q = 0; q < 4; q++) acc[mf][nf][q] = 0.f;

    // per-thread fragment offsets
    int boff[14];
    #pragma unroll
    for (int nf = 0; nf < 14; nf++) {
        int px = wn*112 + nf*8 + (lane >> 2);
        int r = px / 56, j = px % 56;
        boff[nf] = (r*60 + j)*24 + 2*(lane & 3);
    }
    int aoff = (wm*32 + (lane >> 2))*16 + 2*(lane & 3);

    #pragma unroll 1
    for (int cc = 0; cc < 16; cc++) {
        __syncthreads();
        // stage x window: rows i0-2..i0+5, cols -2..57, 16 channels (fp16 hi)
        #pragma unroll 1
        for (int e = tid; e < 7680; e += 256) {
            int col = e % 60;
            int row = (e / 60) & 7;
            int c   = e / 480;
            int gi = i0 - 2 + row, gj = col - 2;
            float v = 0.f;
            if ((unsigned)gi < HH && (unsigned)gj < WW)
                v = xn[(size_t)(cc*16 + c)*HW + gi*WW + gj];
            SH[(row*60 + col)*24 + c] = __float2half_rn(v);
        }
        __syncthreads();

        #pragma unroll 1
        for (int tap = 0; tap < 25; tap++) {
            int du = tap / 5, dv = tap % 5;
            const __half* tH = g_wAh + (size_t)((ot*25 + tap)*16 + cc)*2048;

            uint32_t ah[2][4];
            #pragma unroll
            for (int mf = 0; mf < 2; mf++) {
                const __half* pH = tH + mf*256 + aoff;
                ah[mf][0] = *(const uint32_t*)(pH);
                ah[mf][1] = *(const uint32_t*)(pH + 128);
                ah[mf][2] = *(const uint32_t*)(pH + 8);
                ah[mf][3] = *(const uint32_t*)(pH + 136);
            }

            int toff = (du*60 + dv)*24;
            #pragma unroll
            for (int nf = 0; nf < 14; nf++) {
                const __half* bh = SH + boff[nf] + toff;
                uint32_t b0h = *(const uint32_t*)(bh);
                uint32_t b1h = *(const uint32_t*)(bh + 8);
                #pragma unroll
                for (int mf = 0; mf < 2; mf++)
                    MMA16816(acc[mf][nf], ah[mf], b0h, b1h);
            }
        }
    }

    // epilogue: +bias, write 224 contiguous px per o-row
    int r = lane >> 2, q = 2*(lane & 3);
    #pragma unroll
    for (int mf = 0; mf < 2; mf++) {
        int o0 = ot*128 + wm*32 + mf*16 + r;
        float bb0 = b1[o0], bb1 = b1[o0 + 8];
        float* h0 = g_h + ((size_t)n*CC + o0)*HW + i0*WW;
        float* h1 = h0 + (size_t)8*HW;
        #pragma unroll
        for (int nf = 0; nf < 14; nf++) {
            int px = wn*112 + nf*8 + q;
            float2 v0 = make_float2(acc[mf][nf][0] + bb0, acc[mf][nf][1] + bb0);
            float2 v1 = make_float2(acc[mf][nf][2] + bb1, acc[mf][nf][3] + bb1);
            *(float2*)(h0 + px) = v0;
            *(float2*)(h1 + px) = v1;
        }
    }
}

// ---------------- exact border correction ----------------
__global__ void __launch_bounds__(256) corr_kernel() {
    __shared__ __align__(16) float xs[32][32];
    int o = threadIdx.x;
    int pi, pj; band_pos(blockIdx.x, pi, pj);
    float acc[NN];
    #pragma unroll
    for (int n = 0; n < NN; n++) acc[n] = 0.f;

    for (int g = 0; g < 8; g++) {
        int di = c_di[g], dj = c_dj[g];
        for (int a = 0; a < 3; a++) {
            for (int b = 0; b < 3; b++) {
                int qi = pi + a - 1, qj = pj + b - 1;
                int ui = qi - di,     uj = qj - dj;
                bool qin = ((unsigned)qi < HH) && ((unsigned)qj < WW);
                bool uin = ((unsigned)ui < HH) && ((unsigned)uj < WW);
                float sgn; int ri, rj;
                if (qin && !uin)      { sgn = -1.f; ri = qi; rj = qj; }
                else if (!qin && uin) { sgn =  1.f; ri = ui; rj = uj; }
                else continue;
                int rid = band_id(ri, rj);
                const float* xbp = g_xb + (size_t)rid * CC * NN;
                const float* wp  = g_wt + (size_t)(g*9 + a*3 + b) * CC * CC + o;
                for (int cb = 0; cb < CC; cb += 32) {
                    __syncthreads();
                    for (int e = o; e < 32*NN; e += 256)
                        xs[e / NN][e % NN] = xbp[(size_t)cb*NN + e];
                    __syncthreads();
                    #pragma unroll 1
                    for (int c = 0; c < 32; c++) {
                        float w = sgn * wp[(size_t)(cb + c) * CC];
                        #pragma unroll
                        for (int n4 = 0; n4 < 8; n4++) {
                            float4 v = *(const float4*)&xs[c][n4*4];
                            acc[n4*4+0] += w * v.x;
                            acc[n4*4+1] += w * v.y;
                            acc[n4*4+2] += w * v.z;
                            acc[n4*4+3] += w * v.w;
                        }
                    }
                }
            }
        }
    }
    size_t base = (size_t)o*HW + pi*WW + pj;
    #pragma unroll
    for (int n = 0; n < NN; n++)
        g_h[(size_t)n*CC*HW + base] += acc[n];
}

// ---------------- 1x1 conv ----------------
__global__ void __launch_bounds__(256) conv1x1_kernel(const float* __restrict__ w2,
                                                      const float* __restrict__ b2,
                                                      float* __restrict__ out) {
    __shared__ __align__(16) float hs[32][128];
    __shared__ __align__(16) float ws2[32][80];
    int tid = threadIdx.x;
    int n = blockIdx.y;
    int pbase = blockIdx.x * 128;
    int pxg = tid % 32, ocg = tid / 32;
    int px0 = pxg * 4, oc0 = ocg * 10;

    float acc[10][4];
    #pragma unroll
    for (int k = 0; k < 10; k++)
        #pragma unroll
        for (int j = 0; j < 4; j++) acc[k][j] = 0.f;

    for (int cb = 0; cb < CC; cb += 32) {
        for (int e = tid; e < 32*128; e += 256) {
            int c = e / 128, p = e % 128;
            int gp = pbase + p;
            hs[c][p] = (gp < HW) ? g_h[((size_t)n*CC + cb + c)*HW + gp] : 0.f;
        }
        for (int e = tid; e < 32*80; e += 256) {
            int c = e / 80, oc = e % 80;
            ws2[c][oc] = w2[(size_t)oc*CC + cb + c];
        }
        __syncthreads();
        #pragma unroll 1
        for (int c = 0; c < 32; c++) {
            float4 hv = *(const float4*)&hs[c][px0];
            #pragma unroll
            for (int k = 0; k < 10; k++) {
                float wv = ws2[c][oc0 + k];
                acc[k][0] += wv * hv.x;
                acc[k][1] += wv * hv.y;
                acc[k][2] += wv * hv.z;
                acc[k][3] += wv * hv.w;
            }
        }
        __syncthreads();
    }

    #pragma unroll
    for (int k = 0; k < 10; k++) {
        int oc = oc0 + k;
        float bb = b2[oc];
        #pragma unroll
        for (int j = 0; j < 4; j++) {
            int gp = pbase + px0 + j;
            if (gp < HW)
                out[((size_t)n*OC2 + oc)*HW + gp] = acc[k][j] + bb;
        }
    }
}

extern "C" void kernel_launch(void* const* d_in, const int* in_sizes, int n_in,
                              void* d_out, int out_size) {
    const float *x = nullptr, *w1 = nullptr, *b1 = nullptr, *w2 = nullptr, *b2 = nullptr;
    for (int i = 0; i < n_in; i++) {
        long s = in_sizes[i];
        const float* p = (const float*)d_in[i];
        if      (s == (long)NN*CC*HW)   x  = p;
        else if (s == (long)CC*9*CC*9)  w1 = p;
        else if (s == CC)               b1 = p;
        else if (s == (long)OC2*CC)     w2 = p;
        else if (s == OC2)              b2 = p;
    }
    float* out = (float*)d_out;

    fold_kernel<<<(CC*25*CC + 255)/256, 256>>>(w1);
    wprep_kernel<<<(800*2048 + 255)/256, 256>>>();
    tw1_kernel<<<(int)(((size_t)8*9*CC*CC + 255)/256), 256>>>(w1);
    gather_kernel<<<(NBAND*CC*NN + 255)/256, 256>>>(x);
    conv5_mma_kernel<<<dim3(2, 14, NN), 256>>>(x, b1);
    corr_kernel<<<NBAND, 256>>>();
    conv1x1_kernel<<<dim3(25, NN), 256>>>(w2, b2, out);
}

// round 8
// speedup vs baseline: 3.2781x; 1.0336x over previous
#include <cuda_runtime.h>
#include <cuda_fp16.h>
#include <cstdint>
#include <cstddef>

#define NN 32
#define CC 256
#define HH 56
#define WW 56
#define HW (HH*WW)
#define OC2 80
#define NBAND 432
#define INV_SQRT2 0.7071067811865476f

__constant__ int c_di[8] = {1,-1,0,0,1,1,-1,-1};
__constant__ int c_dj[8] = {0,0,1,-1,1,-1,1,-1};

// Scratch (static device globals)
__device__ float g_weff[(size_t)CC*25*CC];        // [c][tap5x5][o]
__device__ float g_wt  [(size_t)8*9*CC*CC];       // [g*9+tap3x3][c][o]
__device__ float g_xb  [(size_t)NBAND*CC*NN];     // [band][c][n]
__device__ float g_h   [(size_t)NN*CC*HW];        // hidden activations
// A tiles, per-thread 16B-packed fragments: [tile][wm*2+mf][lane][8 halfs]
__device__ __align__(16) __half g_wAh[(size_t)800*2048];

// ---------------- band helpers ----------------
__device__ __forceinline__ int band_id(int i, int j) {
    if (i < 2)   return i*WW + j;
    if (i >= 54) return 112 + (i-54)*WW + j;
    int k = (j < 2) ? j : (j - 52);
    return 224 + (i-2)*4 + k;
}
__device__ __forceinline__ void band_pos(int id, int& i, int& j) {
    if (id < 112)      { i = id/WW;           j = id%WW; }
    else if (id < 224) { int t = id-112; i = 54 + t/WW; j = t%WW; }
    else               { int t = id-224; i = 2 + t/4; int k = t%4; j = (k<2)?k:(52+k); }
}

__device__ __forceinline__ uint32_t smem_u32(const void* p) {
    uint32_t a;
    asm("{ .reg .u64 t; cvta.to.shared.u64 t, %1; cvt.u32.u64 %0, t; }" : "=r"(a) : "l"(p));
    return a;
}

// ---------------- fold 9-group 3x3 -> effective 5x5 ----------------
__global__ void fold_kernel(const float* __restrict__ w1) {
    int idx = blockIdx.x * blockDim.x + threadIdx.x;
    if (idx >= CC*25*CC) return;
    int o   = idx % CC;
    int tap = (idx / CC) % 25;
    int c   = idx / (CC*25);
    int du = tap/5 - 2, dv = tap%5 - 2;
    float t = 0.f;
    if (du >= -1 && du <= 1 && dv >= -1 && dv <= 1) {
        int a = du + 1, b = dv + 1;
        t += w1[(((size_t)o*2304 + c)*3 + a)*3 + b];
        #pragma unroll
        for (int g = 0; g < 8; g++) {
            float s = (g < 4) ? 1.f : INV_SQRT2;
            t += s * w1[(((size_t)o*2304 + (g+1)*CC + c)*3 + a)*3 + b];
        }
    }
    #pragma unroll
    for (int g = 0; g < 8; g++) {
        int a = du + c_di[g] + 1, b = dv + c_dj[g] + 1;
        if (a >= 0 && a < 3 && b >= 0 && b < 3) {
            float s = (g < 4) ? 1.f : INV_SQRT2;
            t -= s * w1[(((size_t)o*2304 + (g+1)*CC + c)*3 + a)*3 + b];
        }
    }
    g_weff[((size_t)c*25 + tap)*CC + o] = t;
}

// ---------------- transpose diff-group weights for correction ----------------
__global__ void tw1_kernel(const float* __restrict__ w1) {
    size_t idx = (size_t)blockIdx.x * blockDim.x + threadIdx.x;
    if (idx >= (size_t)8*9*CC*CC) return;
    int o   = idx % CC;
    int c   = (idx / CC) % CC;
    int tap = (idx / ((size_t)CC*CC)) % 9;
    int g   = idx / ((size_t)CC*CC*9);
    float s = (g < 4) ? 1.f : INV_SQRT2;
    g_wt[(((size_t)(g*9 + tap))*CC + c)*CC + o] =
        s * w1[(((size_t)o*2304 + (g+1)*CC + c))*9 + tap];
}

// ---------------- gather band x ----------------
__global__ void gather_kernel(const float* __restrict__ x) {
    size_t idx = (size_t)blockIdx.x * blockDim.x + threadIdx.x;
    if (idx >= (size_t)NBAND*CC*NN) return;
    int n   = idx % NN;
    int c   = (idx / NN) % CC;
    int rid = idx / (NN*CC);
    int i, j; band_pos(rid, i, j);
    g_xb[idx] = x[((size_t)n*CC + c)*HW + i*WW + j];
}

// ---------------- weight prep: Weff -> fp16 A fragments, LDG.128-packed ----
// tile = (ot*25+tap)*16+cc ; e = ((wm*2+mf)*32 + lane)*8 + h
// h: apair=h>>1 (a0..a3), half=h&1
//   o = wm*32 + mf*16 + (lane>>2) + (apair&1)*8
//   c = 2*(lane&3) + (apair>>1)*8 + half
__global__ void wprep_kernel() {
    int idx = blockIdx.x * blockDim.x + threadIdx.x;
    if (idx >= 800*2048) return;
    int e    = idx & 2047;
    int tile = idx >> 11;
    int h     = e & 7;
    int lane  = (e >> 3) & 31;
    int wmmf  = e >> 8;
    int wm = wmmf >> 1, mf = wmmf & 1;
    int apair = h >> 1, half = h & 1;
    int o = wm*32 + mf*16 + (lane >> 2) + (apair & 1)*8;
    int c = 2*(lane & 3) + (apair >> 1)*8 + half;
    int ccv = tile & 15;
    int t3 = tile >> 4;
    int tap = t3 % 25, ot = t3 / 25;
    float v = g_weff[(((size_t)(ccv*16 + c))*25 + tap)*CC + ot*128 + o];
    g_wAh[idx] = __float2half_rn(v);
}

// ---------------- conv5 via mma.sync m16n8k16 (ldmatrix B, LDG.128 A) -----
#define MMA16816(cacc, a, b0, b1) \
    asm volatile("mma.sync.aligned.m16n8k16.row.col.f32.f16.f16.f32 " \
        "{%0,%1,%2,%3}, {%4,%5,%6,%7}, {%8,%9}, {%0,%1,%2,%3};" \
        : "+f"((cacc)[0]),"+f"((cacc)[1]),"+f"((cacc)[2]),"+f"((cacc)[3]) \
        : "r"((a)[0]),"r"((a)[1]),"r"((a)[2]),"r"((a)[3]), "r"(b0),"r"(b1))

#define LDSM_X4(r0, r1, r2, r3, addr) \
    asm volatile("ldmatrix.sync.aligned.m8n8.x4.shared.b16 {%0,%1,%2,%3}, [%4];" \
        : "=r"(r0), "=r"(r1), "=r"(r2), "=r"(r3) : "r"(addr))

__global__ void __launch_bounds__(256) conv5_mma_kernel(const float* __restrict__ x,
                                                        const float* __restrict__ b1) {
    // stage: 8 rows x 60 cols x 24 halfs (16 used + 8 pad => 48B px-stride, conflict-free)
    __shared__ __align__(16) __half SH[8*60*24];

    int tid  = threadIdx.x;
    int lane = tid & 31, wid = tid >> 5;
    int wm = wid & 3, wn = wid >> 2;          // warp grid 4m x 2n
    int ot = blockIdx.x;                       // 0..1 (128 outch each)
    int i0 = blockIdx.y * 4;                   // output row tile (4 rows)
    int n  = blockIdx.z;
    const float* xn = x + (size_t)n * CC * HW;

    float acc[2][14][4];
    #pragma unroll
    for (int mf = 0; mf < 2; mf++)
        #pragma unroll
        for (int nf = 0; nf < 14; nf++)
            #pragma unroll
            for (int q = 0; q < 4; q++) acc[mf][nf][q] = 0.f;

    // per-lane ldmatrix row addresses for the 7 nf-pairs
    uint32_t sh0 = smem_u32(SH);
    int qsel = lane >> 3;            // 0..3: (nf-within-pair, k-half)
    int rrow = lane & 7;
    uint32_t lbase[7];
    #pragma unroll
    for (int np = 0; np < 7; np++) {
        int px = wn*112 + np*16 + (qsel >> 1)*8 + rrow;
        int pr = px / 56, pj = px % 56;
        lbase[np] = sh0 + ((pr*60 + pj)*24 + (qsel & 1)*8)*2;
    }

    #pragma unroll 1
    for (int cc = 0; cc < 16; cc++) {
        __syncthreads();
        // stage x window: rows i0-2..i0+5, cols -2..57, 16 channels (fp16 hi)
        #pragma unroll 1
        for (int e = tid; e < 7680; e += 256) {
            int col = e % 60;
            int row = (e / 60) & 7;
            int c   = e / 480;
            int gi = i0 - 2 + row, gj = col - 2;
            float v = 0.f;
            if ((unsigned)gi < HH && (unsigned)gj < WW)
                v = xn[(size_t)(cc*16 + c)*HW + gi*WW + gj];
            SH[(row*60 + col)*24 + c] = __float2half_rn(v);
        }
        __syncthreads();

        #pragma unroll 1
        for (int tap = 0; tap < 25; tap++) {
            int du = tap / 5, dv = tap % 5;
            const __half* tH = g_wAh + (size_t)((ot*25 + tap)*16 + cc)*2048;

            uint32_t ah[2][4];
            #pragma unroll
            for (int mf = 0; mf < 2; mf++) {
                uint4 av = *(const uint4*)(tH + (wm*2 + mf)*256 + lane*8);
                ah[mf][0] = av.x; ah[mf][1] = av.y;
                ah[mf][2] = av.z; ah[mf][3] = av.w;
            }

            uint32_t taddr = (uint32_t)((du*60 + dv)*48);
            #pragma unroll
            for (int np = 0; np < 7; np++) {
                uint32_t m0, m1, m2, m3;
                LDSM_X4(m0, m1, m2, m3, lbase[np] + taddr);
                #pragma unroll
                for (int mf = 0; mf < 2; mf++) {
                    MMA16816(acc[mf][2*np    ], ah[mf], m0, m1);
                    MMA16816(acc[mf][2*np + 1], ah[mf], m2, m3);
                }
            }
        }
    }

    // epilogue: +bias, write 224 contiguous px per o-row
    int r = lane >> 2, q = 2*(lane & 3);
    #pragma unroll
    for (int mf = 0; mf < 2; mf++) {
        int o0 = ot*128 + wm*32 + mf*16 + r;
        float bb0 = b1[o0], bb1 = b1[o0 + 8];
        float* h0 = g_h + ((size_t)n*CC + o0)*HW + i0*WW;
        float* h1 = h0 + (size_t)8*HW;
        #pragma unroll
        for (int nf = 0; nf < 14; nf++) {
            int px = wn*112 + nf*8 + q;
            float2 v0 = make_float2(acc[mf][nf][0] + bb0, acc[mf][nf][1] + bb0);
            float2 v1 = make_float2(acc[mf][nf][2] + bb1, acc[mf][nf][3] + bb1);
            *(float2*)(h0 + px) = v0;
            *(float2*)(h1 + px) = v1;
        }
    }
}

// ---------------- exact border correction ----------------
__global__ void __launch_bounds__(256) corr_kernel() {
    __shared__ __align__(16) float xs[32][32];
    int o = threadIdx.x;
    int pi, pj; band_pos(blockIdx.x, pi, pj);
    float acc[NN];
    #pragma unroll
    for (int n = 0; n < NN; n++) acc[n] = 0.f;

    for (int g = 0; g < 8; g++) {
        int di = c_di[g], dj = c_dj[g];
        for (int a = 0; a < 3; a++) {
            for (int b = 0; b < 3; b++) {
                int qi = pi + a - 1, qj = pj + b - 1;
                int ui = qi - di,     uj = qj - dj;
                bool qin = ((unsigned)qi < HH) && ((unsigned)qj < WW);
                bool uin = ((unsigned)ui < HH) && ((unsigned)uj < WW);
                float sgn; int ri, rj;
                if (qin && !uin)      { sgn = -1.f; ri = qi; rj = qj; }
                else if (!qin && uin) { sgn =  1.f; ri = ui; rj = uj; }
                else continue;
                int rid = band_id(ri, rj);
                const float* xbp = g_xb + (size_t)rid * CC * NN;
                const float* wp  = g_wt + (size_t)(g*9 + a*3 + b) * CC * CC + o;
                for (int cb = 0; cb < CC; cb += 32) {
                    __syncthreads();
                    for (int e = o; e < 32*NN; e += 256)
                        xs[e / NN][e % NN] = xbp[(size_t)cb*NN + e];
                    __syncthreads();
                    #pragma unroll 1
                    for (int c = 0; c < 32; c++) {
                        float w = sgn * wp[(size_t)(cb + c) * CC];
                        #pragma unroll
                        for (int n4 = 0; n4 < 8; n4++) {
                            float4 v = *(const float4*)&xs[c][n4*4];
                            acc[n4*4+0] += w * v.x;
                            acc[n4*4+1] += w * v.y;
                            acc[n4*4+2] += w * v.z;
                            acc[n4*4+3] += w * v.w;
                        }
                    }
                }
            }
        }
    }
    size_t base = (size_t)o*HW + pi*WW + pj;
    #pragma unroll
    for (int n = 0; n < NN; n++)
        g_h[(size_t)n*CC*HW + base] += acc[n];
}

// ---------------- 1x1 conv ----------------
__global__ void __launch_bounds__(256) conv1x1_kernel(const float* __restrict__ w2,
                                                      const float* __restrict__ b2,
                                                      float* __restrict__ out) {
    __shared__ __align__(16) float hs[32][128];
    __shared__ __align__(16) float ws2[32][80];
    int tid = threadIdx.x;
    int n = blockIdx.y;
    int pbase = blockIdx.x * 128;
    int pxg = tid % 32, ocg = tid / 32;
    int px0 = pxg * 4, oc0 = ocg * 10;

    float acc[10][4];
    #pragma unroll
    for (int k = 0; k < 10; k++)
        #pragma unroll
        for (int j = 0; j < 4; j++) acc[k][j] = 0.f;

    for (int cb = 0; cb < CC; cb += 32) {
        for (int e = tid; e < 32*128; e += 256) {
            int c = e / 128, p = e % 128;
            int gp = pbase + p;
            hs[c][p] = (gp < HW) ? g_h[((size_t)n*CC + cb + c)*HW + gp] : 0.f;
        }
        for (int e = tid; e < 32*80; e += 256) {
            int c = e / 80, oc = e % 80;
            ws2[c][oc] = w2[(size_t)oc*CC + cb + c];
        }
        __syncthreads();
        #pragma unroll 1
        for (int c = 0; c < 32; c++) {
            float4 hv = *(const float4*)&hs[c][px0];
            #pragma unroll
            for (int k = 0; k < 10; k++) {
                float wv = ws2[c][oc0 + k];
                acc[k][0] += wv * hv.x;
                acc[k][1] += wv * hv.y;
                acc[k][2] += wv * hv.z;
                acc[k][3] += wv * hv.w;
            }
        }
        __syncthreads();
    }

    #pragma unroll
    for (int k = 0; k < 10; k++) {
        int oc = oc0 + k;
        float bb = b2[oc];
        #pragma unroll
        for (int j = 0; j < 4; j++) {
            int gp = pbase + px0 + j;
            if (gp < HW)
                out[((size_t)n*OC2 + oc)*HW + gp] = acc[k][j] + bb;
        }
    }
}

extern "C" void kernel_launch(void* const* d_in, const int* in_sizes, int n_in,
                              void* d_out, int out_size) {
    const float *x = nullptr, *w1 = nullptr, *b1 = nullptr, *w2 = nullptr, *b2 = nullptr;
    for (int i = 0; i < n_in; i++) {
        long s = in_sizes[i];
        const float* p = (const float*)d_in[i];
        if      (s == (long)NN*CC*HW)   x  = p;
        else if (s == (long)CC*9*CC*9)  w1 = p;
        else if (s == CC)               b1 = p;
        else if (s == (long)OC2*CC)     w2 = p;
        else if (s == OC2)              b2 = p;
    }
    float* out = (float*)d_out;

    fold_kernel<<<(CC*25*CC + 255)/256, 256>>>(w1);
    wprep_kernel<<<(800*2048 + 255)/256, 256>>>();
    tw1_kernel<<<(int)(((size_t)8*9*CC*CC + 255)/256), 256>>>(w1);
    gather_kernel<<<(NBAND*CC*NN + 255)/256, 256>>>(x);
    conv5_mma_kernel<<<dim3(2, 14, NN), 256>>>(x, b1);
    corr_kernel<<<NBAND, 256>>>();
    conv1x1_kernel<<<dim3(25, NN), 256>>>(w2, b2, out);
}

// round 9
// speedup vs baseline: 3.4376x; 1.0486x over previous
#include <cuda_runtime.h>
#include <cuda_fp16.h>
#include <cstdint>
#include <cstddef>

#define NN 32
#define CC 256
#define HH 56
#define WW 56
#define HW (HH*WW)
#define OC2 80
#define NBAND 432
#define INV_SQRT2 0.7071067811865476f

__constant__ int c_di[8] = {1,-1,0,0,1,1,-1,-1};
__constant__ int c_dj[8] = {0,0,1,-1,1,-1,1,-1};

// Scratch (static device globals)
__device__ float g_weff[(size_t)CC*25*CC];        // [c][tap5x5][o]
__device__ float g_wt  [(size_t)8*9*CC*CC];       // [g*9+tap3x3][c][o]
__device__ float g_xb  [(size_t)NBAND*CC*NN];     // [band][c][n]
__device__ float g_h   [(size_t)NN*CC*HW];        // hidden activations
// A tiles, per-thread 16B-packed fragments: [tile][wm*2+mf][lane][8 halfs]
__device__ __align__(16) __half g_wAh[(size_t)800*2048];

// ---------------- band helpers ----------------
__device__ __forceinline__ int band_id(int i, int j) {
    if (i < 2)   return i*WW + j;
    if (i >= 54) return 112 + (i-54)*WW + j;
    int k = (j < 2) ? j : (j - 52);
    return 224 + (i-2)*4 + k;
}
__device__ __forceinline__ void band_pos(int id, int& i, int& j) {
    if (id < 112)      { i = id/WW;           j = id%WW; }
    else if (id < 224) { int t = id-112; i = 54 + t/WW; j = t%WW; }
    else               { int t = id-224; i = 2 + t/4; int k = t%4; j = (k<2)?k:(52+k); }
}

__device__ __forceinline__ uint32_t smem_u32(const void* p) {
    uint32_t a;
    asm("{ .reg .u64 t; cvta.to.shared.u64 t, %1; cvt.u32.u64 %0, t; }" : "=r"(a) : "l"(p));
    return a;
}

// ---------------- fold 9-group 3x3 -> effective 5x5 ----------------
__global__ void fold_kernel(const float* __restrict__ w1) {
    int idx = blockIdx.x * blockDim.x + threadIdx.x;
    if (idx >= CC*25*CC) return;
    int o   = idx % CC;
    int tap = (idx / CC) % 25;
    int c   = idx / (CC*25);
    int du = tap/5 - 2, dv = tap%5 - 2;
    float t = 0.f;
    if (du >= -1 && du <= 1 && dv >= -1 && dv <= 1) {
        int a = du + 1, b = dv + 1;
        t += w1[(((size_t)o*2304 + c)*3 + a)*3 + b];
        #pragma unroll
        for (int g = 0; g < 8; g++) {
            float s = (g < 4) ? 1.f : INV_SQRT2;
            t += s * w1[(((size_t)o*2304 + (g+1)*CC + c)*3 + a)*3 + b];
        }
    }
    #pragma unroll
    for (int g = 0; g < 8; g++) {
        int a = du + c_di[g] + 1, b = dv + c_dj[g] + 1;
        if (a >= 0 && a < 3 && b >= 0 && b < 3) {
            float s = (g < 4) ? 1.f : INV_SQRT2;
            t -= s * w1[(((size_t)o*2304 + (g+1)*CC + c)*3 + a)*3 + b];
        }
    }
    g_weff[((size_t)c*25 + tap)*CC + o] = t;
}

// ---------------- transpose diff-group weights for correction ----------------
__global__ void tw1_kernel(const float* __restrict__ w1) {
    size_t idx = (size_t)blockIdx.x * blockDim.x + threadIdx.x;
    if (idx >= (size_t)8*9*CC*CC) return;
    int o   = idx % CC;
    int c   = (idx / CC) % CC;
    int tap = (idx / ((size_t)CC*CC)) % 9;
    int g   = idx / ((size_t)CC*CC*9);
    float s = (g < 4) ? 1.f : INV_SQRT2;
    g_wt[(((size_t)(g*9 + tap))*CC + c)*CC + o] =
        s * w1[(((size_t)o*2304 + (g+1)*CC + c))*9 + tap];
}

// ---------------- gather band x ----------------
__global__ void gather_kernel(const float* __restrict__ x) {
    size_t idx = (size_t)blockIdx.x * blockDim.x + threadIdx.x;
    if (idx >= (size_t)NBAND*CC*NN) return;
    int n   = idx % NN;
    int c   = (idx / NN) % CC;
    int rid = idx / (NN*CC);
    int i, j; band_pos(rid, i, j);
    g_xb[idx] = x[((size_t)n*CC + c)*HW + i*WW + j];
}

// ---------------- weight prep: Weff -> fp16 A fragments, LDG.128-packed ----
__global__ void wprep_kernel() {
    int idx = blockIdx.x * blockDim.x + threadIdx.x;
    if (idx >= 800*2048) return;
    int e    = idx & 2047;
    int tile = idx >> 11;
    int h     = e & 7;
    int lane  = (e >> 3) & 31;
    int wmmf  = e >> 8;
    int wm = wmmf >> 1, mf = wmmf & 1;
    int apair = h >> 1, half = h & 1;
    int o = wm*32 + mf*16 + (lane >> 2) + (apair & 1)*8;
    int c = 2*(lane & 3) + (apair >> 1)*8 + half;
    int ccv = tile & 15;
    int t3 = tile >> 4;
    int tap = t3 % 25, ot = t3 / 25;
    float v = g_weff[(((size_t)(ccv*16 + c))*25 + tap)*CC + ot*128 + o];
    g_wAh[idx] = __float2half_rn(v);
}

// ---------------- conv5 via mma.sync m16n8k16, register-double-buffered ----
#define MMA16816(cacc, a, b0, b1) \
    asm volatile("mma.sync.aligned.m16n8k16.row.col.f32.f16.f16.f32 " \
        "{%0,%1,%2,%3}, {%4,%5,%6,%7}, {%8,%9}, {%0,%1,%2,%3};" \
        : "+f"((cacc)[0]),"+f"((cacc)[1]),"+f"((cacc)[2]),"+f"((cacc)[3]) \
        : "r"((a)[0]),"r"((a)[1]),"r"((a)[2]),"r"((a)[3]), "r"(b0),"r"(b1))

#define LDSM_X4(r0, r1, r2, r3, addr) \
    asm volatile("ldmatrix.sync.aligned.m8n8.x4.shared.b16 {%0,%1,%2,%3}, [%4];" \
        : "=r"(r0), "=r"(r1), "=r"(r2), "=r"(r3) : "r"(addr))

__global__ void __launch_bounds__(256) conv5_mma_kernel(const float* __restrict__ x,
                                                        const float* __restrict__ b1) {
    // stage: 8 rows x 60 cols x 24 halfs (16 used + 8 pad => 48B px-stride, conflict-free)
    __shared__ __align__(16) __half SH[8*60*24];

    int tid  = threadIdx.x;
    int lane = tid & 31, wid = tid >> 5;
    int wm = wid & 3, wn = wid >> 2;          // warp grid 4m x 2n
    int ot = blockIdx.x;                       // 0..1 (128 outch each)
    int i0 = blockIdx.y * 4;                   // output row tile (4 rows)
    int n  = blockIdx.z;
    const float* xn = x + (size_t)n * CC * HW;

    float acc[2][14][4];
    #pragma unroll
    for (int mf = 0; mf < 2; mf++)
        #pragma unroll
        for (int nf = 0; nf < 14; nf++)
            #pragma unroll
            for (int q = 0; q < 4; q++) acc[mf][nf][q] = 0.f;

    // per-lane ldmatrix row addresses for the 7 nf-pairs
    uint32_t sh0 = smem_u32(SH);
    int qsel = lane >> 3;            // 0..3: (nf-within-pair, k-half)
    int rrow = lane & 7;
    uint32_t lbase[7];
    #pragma unroll
    for (int np = 0; np < 7; np++) {
        int px = wn*112 + np*16 + (qsel >> 1)*8 + rrow;
        int pr = px / 56, pj = px % 56;
        lbase[np] = sh0 + ((pr*60 + pj)*24 + (qsel & 1)*8)*2;
    }

    const __half* aBase = g_wAh + (size_t)(ot*25)*16*2048 + (wm*2)*256 + lane*8;

    #pragma unroll 1
    for (int cc = 0; cc < 16; cc++) {
        __syncthreads();
        // stage x window: rows i0-2..i0+5, cols -2..57, 16 channels (fp16 hi)
        #pragma unroll 1
        for (int e = tid; e < 7680; e += 256) {
            int col = e % 60;
            int row = (e / 60) & 7;
            int c   = e / 480;
            int gi = i0 - 2 + row, gj = col - 2;
            float v = 0.f;
            if ((unsigned)gi < HH && (unsigned)gj < WW)
                v = xn[(size_t)(cc*16 + c)*HW + gi*WW + gj];
            SH[(row*60 + col)*24 + c] = __float2half_rn(v);
        }
        __syncthreads();

        // register double buffers
        uint32_t ahb[2][2][4];
        uint32_t bmb[2][7][4];

        // prologue: load tap 0 into buffer 0
        {
            const __half* tH = aBase + (size_t)cc*2048;
            #pragma unroll
            for (int mf = 0; mf < 2; mf++) {
                uint4 av = *(const uint4*)(tH + mf*256);
                ahb[0][mf][0] = av.x; ahb[0][mf][1] = av.y;
                ahb[0][mf][2] = av.z; ahb[0][mf][3] = av.w;
            }
            #pragma unroll
            for (int np = 0; np < 7; np++)
                LDSM_X4(bmb[0][np][0], bmb[0][np][1], bmb[0][np][2], bmb[0][np][3],
                        lbase[np]);
        }

        #pragma unroll
        for (int tap = 0; tap < 25; tap++) {
            int cur = tap & 1, nxt = cur ^ 1;
            if (tap < 24) {
                int t1 = tap + 1;
                int du = t1 / 5, dv = t1 % 5;
                const __half* tH = aBase + (size_t)(t1*16 + cc)*2048;
                #pragma unroll
                for (int mf = 0; mf < 2; mf++) {
                    uint4 av = *(const uint4*)(tH + mf*256);
                    ahb[nxt][mf][0] = av.x; ahb[nxt][mf][1] = av.y;
                    ahb[nxt][mf][2] = av.z; ahb[nxt][mf][3] = av.w;
                }
                uint32_t taddr = (uint32_t)((du*60 + dv)*48);
                #pragma unroll
                for (int np = 0; np < 7; np++)
                    LDSM_X4(bmb[nxt][np][0], bmb[nxt][np][1],
                            bmb[nxt][np][2], bmb[nxt][np][3],
                            lbase[np] + taddr);
            }
            #pragma unroll
            for (int np = 0; np < 7; np++) {
                #pragma unroll
                for (int mf = 0; mf < 2; mf++) {
                    MMA16816(acc[mf][2*np    ], ahb[cur][mf],
                             bmb[cur][np][0], bmb[cur][np][1]);
                    MMA16816(acc[mf][2*np + 1], ahb[cur][mf],
                             bmb[cur][np][2], bmb[cur][np][3]);
                }
            }
        }
    }

    // epilogue: +bias, write 224 contiguous px per o-row
    int r = lane >> 2, q = 2*(lane & 3);
    #pragma unroll
    for (int mf = 0; mf < 2; mf++) {
        int o0 = ot*128 + wm*32 + mf*16 + r;
        float bb0 = b1[o0], bb1 = b1[o0 + 8];
        float* h0 = g_h + ((size_t)n*CC + o0)*HW + i0*WW;
        float* h1 = h0 + (size_t)8*HW;
        #pragma unroll
        for (int nf = 0; nf < 14; nf++) {
            int px = wn*112 + nf*8 + q;
            float2 v0 = make_float2(acc[mf][nf][0] + bb0, acc[mf][nf][1] + bb0);
            float2 v1 = make_float2(acc[mf][nf][2] + bb1, acc[mf][nf][3] + bb1);
            *(float2*)(h0 + px) = v0;
            *(float2*)(h1 + px) = v1;
        }
    }
}

// ---------------- exact border correction ----------------
__global__ void __launch_bounds__(256) corr_kernel() {
    __shared__ __align__(16) float xs[32][32];
    int o = threadIdx.x;
    int pi, pj; band_pos(blockIdx.x, pi, pj);
    float acc[NN];
    #pragma unroll
    for (int n = 0; n < NN; n++) acc[n] = 0.f;

    for (int g = 0; g < 8; g++) {
        int di = c_di[g], dj = c_dj[g];
        for (int a = 0; a < 3; a++) {
            for (int b = 0; b < 3; b++) {
                int qi = pi + a - 1, qj = pj + b - 1;
                int ui = qi - di,     uj = qj - dj;
                bool qin = ((unsigned)qi < HH) && ((unsigned)qj < WW);
                bool uin = ((unsigned)ui < HH) && ((unsigned)uj < WW);
                float sgn; int ri, rj;
                if (qin && !uin)      { sgn = -1.f; ri = qi; rj = qj; }
                else if (!qin && uin) { sgn =  1.f; ri = ui; rj = uj; }
                else continue;
                int rid = band_id(ri, rj);
                const float* xbp = g_xb + (size_t)rid * CC * NN;
                const float* wp  = g_wt + (size_t)(g*9 + a*3 + b) * CC * CC + o;
                for (int cb = 0; cb < CC; cb += 32) {
                    __syncthreads();
                    for (int e = o; e < 32*NN; e += 256)
                        xs[e / NN][e % NN] = xbp[(size_t)cb*NN + e];
                    __syncthreads();
                    #pragma unroll 1
                    for (int c = 0; c < 32; c++) {
                        float w = sgn * wp[(size_t)(cb + c) * CC];
                        #pragma unroll
                        for (int n4 = 0; n4 < 8; n4++) {
                            float4 v = *(const float4*)&xs[c][n4*4];
                            acc[n4*4+0] += w * v.x;
                            acc[n4*4+1] += w * v.y;
                            acc[n4*4+2] += w * v.z;
                            acc[n4*4+3] += w * v.w;
                        }
                    }
                }
            }
        }
    }
    size_t base = (size_t)o*HW + pi*WW + pj;
    #pragma unroll
    for (int n = 0; n < NN; n++)
        g_h[(size_t)n*CC*HW + base] += acc[n];
}

// ---------------- 1x1 conv ----------------
__global__ void __launch_bounds__(256) conv1x1_kernel(const float* __restrict__ w2,
                                                      const float* __restrict__ b2,
                                                      float* __restrict__ out) {
    __shared__ __align__(16) float hs[32][128];
    __shared__ __align__(16) float ws2[32][80];
    int tid = threadIdx.x;
    int n = blockIdx.y;
    int pbase = blockIdx.x * 128;
    int pxg = tid % 32, ocg = tid / 32;
    int px0 = pxg * 4, oc0 = ocg * 10;

    float acc[10][4];
    #pragma unroll
    for (int k = 0; k < 10; k++)
        #pragma unroll
        for (int j = 0; j < 4; j++) acc[k][j] = 0.f;

    for (int cb = 0; cb < CC; cb += 32) {
        for (int e = tid; e < 32*128; e += 256) {
            int c = e / 128, p = e % 128;
            int gp = pbase + p;
            hs[c][p] = (gp < HW) ? g_h[((size_t)n*CC + cb + c)*HW + gp] : 0.f;
        }
        for (int e = tid; e < 32*80; e += 256) {
            int c = e / 80, oc = e % 80;
            ws2[c][oc] = w2[(size_t)oc*CC + cb + c];
        }
        __syncthreads();
        #pragma unroll 1
        for (int c = 0; c < 32; c++) {
            float4 hv = *(const float4*)&hs[c][px0];
            #pragma unroll
            for (int k = 0; k < 10; k++) {
                float wv = ws2[c][oc0 + k];
                acc[k][0] += wv * hv.x;
                acc[k][1] += wv * hv.y;
                acc[k][2] += wv * hv.z;
                acc[k][3] += wv * hv.w;
            }
        }
        __syncthreads();
    }

    #pragma unroll
    for (int k = 0; k < 10; k++) {
        int oc = oc0 + k;
        float bb = b2[oc];
        #pragma unroll
        for (int j = 0; j < 4; j++) {
            int gp = pbase + px0 + j;
            if (gp < HW)
                out[((size_t)n*OC2 + oc)*HW + gp] = acc[k][j] + bb;
        }
    }
}

extern "C" void kernel_launch(void* const* d_in, const int* in_sizes, int n_in,
                              void* d_out, int out_size) {
    const float *x = nullptr, *w1 = nullptr, *b1 = nullptr, *w2 = nullptr, *b2 = nullptr;
    for (int i = 0; i < n_in; i++) {
        long s = in_sizes[i];
        const float* p = (const float*)d_in[i];
        if      (s == (long)NN*CC*HW)   x  = p;
        else if (s == (long)CC*9*CC*9)  w1 = p;
        else if (s == CC)               b1 = p;
        else if (s == (long)OC2*CC)     w2 = p;
        else if (s == OC2)              b2 = p;
    }
    float* out = (float*)d_out;

    fold_kernel<<<(CC*25*CC + 255)/256, 256>>>(w1);
    wprep_kernel<<<(800*2048 + 255)/256, 256>>>();
    tw1_kernel<<<(int)(((size_t)8*9*CC*CC + 255)/256), 256>>>(w1);
    gather_kernel<<<(NBAND*CC*NN + 255)/256, 256>>>(x);
    conv5_mma_kernel<<<dim3(2, 14, NN), 256>>>(x, b1);
    corr_kernel<<<NBAND, 256>>>();
    conv1x1_kernel<<<dim3(25, NN), 256>>>(w2, b2, out);
}

// round 10
// speedup vs baseline: 4.5105x; 1.3121x over previous
#include <cuda_runtime.h>
#include <cuda_fp16.h>
#include <cstdint>
#include <cstddef>

#define NN 32
#define CC 256
#define HH 56
#define WW 56
#define HW (HH*WW)
#define OC2 80
#define NBAND 432
#define INV_SQRT2 0.7071067811865476f

__constant__ int c_di[8] = {1,-1,0,0,1,1,-1,-1};
__constant__ int c_dj[8] = {0,0,1,-1,1,-1,1,-1};

// Scratch (static device globals)
__device__ float g_weff[(size_t)CC*25*CC];        // [c][tap5x5][o]
__device__ float g_wt  [(size_t)8*9*CC*CC];       // [g*9+tap3x3][c][o]
__device__ float g_xb  [(size_t)NBAND*CC*NN];     // [band][c][n]
__device__ float g_h   [(size_t)NN*CC*HW];        // hidden activations
__device__ __half g_xh [(size_t)NN*HW*CC];        // x transposed: [n][px][c] fp16
// A tiles, per-thread 16B-packed fragments: [tile][wm*2+mf][lane][8 halfs]
__device__ __align__(16) __half g_wAh[(size_t)800*2048];

// ---------------- band helpers ----------------
__device__ __forceinline__ int band_id(int i, int j) {
    if (i < 2)   return i*WW + j;
    if (i >= 54) return 112 + (i-54)*WW + j;
    int k = (j < 2) ? j : (j - 52);
    return 224 + (i-2)*4 + k;
}
__device__ __forceinline__ void band_pos(int id, int& i, int& j) {
    if (id < 112)      { i = id/WW;           j = id%WW; }
    else if (id < 224) { int t = id-112; i = 54 + t/WW; j = t%WW; }
    else               { int t = id-224; i = 2 + t/4; int k = t%4; j = (k<2)?k:(52+k); }
}

__device__ __forceinline__ uint32_t smem_u32(const void* p) {
    uint32_t a;
    asm("{ .reg .u64 t; cvta.to.shared.u64 t, %1; cvt.u32.u64 %0, t; }" : "=r"(a) : "l"(p));
    return a;
}

// ---------------- fold 9-group 3x3 -> effective 5x5 ----------------
__global__ void fold_kernel(const float* __restrict__ w1) {
    int idx = blockIdx.x * blockDim.x + threadIdx.x;
    if (idx >= CC*25*CC) return;
    int o   = idx % CC;
    int tap = (idx / CC) % 25;
    int c   = idx / (CC*25);
    int du = tap/5 - 2, dv = tap%5 - 2;
    float t = 0.f;
    if (du >= -1 && du <= 1 && dv >= -1 && dv <= 1) {
        int a = du + 1, b = dv + 1;
        t += w1[(((size_t)o*2304 + c)*3 + a)*3 + b];
        #pragma unroll
        for (int g = 0; g < 8; g++) {
            float s = (g < 4) ? 1.f : INV_SQRT2;
            t += s * w1[(((size_t)o*2304 + (g+1)*CC + c)*3 + a)*3 + b];
        }
    }
    #pragma unroll
    for (int g = 0; g < 8; g++) {
        int a = du + c_di[g] + 1, b = dv + c_dj[g] + 1;
        if (a >= 0 && a < 3 && b >= 0 && b < 3) {
            float s = (g < 4) ? 1.f : INV_SQRT2;
            t -= s * w1[(((size_t)o*2304 + (g+1)*CC + c)*3 + a)*3 + b];
        }
    }
    g_weff[((size_t)c*25 + tap)*CC + o] = t;
}

// ---------------- transpose diff-group weights for correction ----------------
__global__ void tw1_kernel(const float* __restrict__ w1) {
    size_t idx = (size_t)blockIdx.x * blockDim.x + threadIdx.x;
    if (idx >= (size_t)8*9*CC*CC) return;
    int o   = idx % CC;
    int c   = (idx / CC) % CC;
    int tap = (idx / ((size_t)CC*CC)) % 9;
    int g   = idx / ((size_t)CC*CC*9);
    float s = (g < 4) ? 1.f : INV_SQRT2;
    g_wt[(((size_t)(g*9 + tap))*CC + c)*CC + o] =
        s * w1[(((size_t)o*2304 + (g+1)*CC + c))*9 + tap];
}

// ---------------- gather band x ----------------
__global__ void gather_kernel(const float* __restrict__ x) {
    size_t idx = (size_t)blockIdx.x * blockDim.x + threadIdx.x;
    if (idx >= (size_t)NBAND*CC*NN) return;
    int n   = idx % NN;
    int c   = (idx / NN) % CC;
    int rid = idx / (NN*CC);
    int i, j; band_pos(rid, i, j);
    g_xb[idx] = x[((size_t)n*CC + c)*HW + i*WW + j];
}

// ---------------- x transpose: [n][c][px] fp32 -> [n][px][c] fp16 ----------
__global__ void xprep_kernel(const float* __restrict__ x) {
    __shared__ float t[32][33];
    int n  = blockIdx.z;
    int cb = blockIdx.y * 32;
    int pb = blockIdx.x * 32;
    int tx = threadIdx.x & 31, ty = threadIdx.x >> 5;   // 32 x 8
    #pragma unroll
    for (int r = ty; r < 32; r += 8)
        t[r][tx] = x[((size_t)n*CC + cb + r)*HW + pb + tx];
    __syncthreads();
    #pragma unroll
    for (int r = ty; r < 32; r += 8)
        g_xh[((size_t)n*HW + pb + r)*CC + cb + tx] = __float2half_rn(t[tx][r]);
}

// ---------------- weight prep: Weff -> fp16 A fragments, LDG.128-packed ----
__global__ void wprep_kernel() {
    int idx = blockIdx.x * blockDim.x + threadIdx.x;
    if (idx >= 800*2048) return;
    int e    = idx & 2047;
    int tile = idx >> 11;
    int h     = e & 7;
    int lane  = (e >> 3) & 31;
    int wmmf  = e >> 8;
    int wm = wmmf >> 1, mf = wmmf & 1;
    int apair = h >> 1, half = h & 1;
    int o = wm*32 + mf*16 + (lane >> 2) + (apair & 1)*8;
    int c = 2*(lane & 3) + (apair >> 1)*8 + half;
    int ccv = tile & 15;
    int t3 = tile >> 4;
    int tap = t3 % 25, ot = t3 / 25;
    float v = g_weff[(((size_t)(ccv*16 + c))*25 + tap)*CC + ot*128 + o];
    g_wAh[idx] = __float2half_rn(v);
}

// ---------------- conv5: mma.sync + cp.async double-buffered staging -------
#define MMA16816(cacc, a, b0, b1) \
    asm volatile("mma.sync.aligned.m16n8k16.row.col.f32.f16.f16.f32 " \
        "{%0,%1,%2,%3}, {%4,%5,%6,%7}, {%8,%9}, {%0,%1,%2,%3};" \
        : "+f"((cacc)[0]),"+f"((cacc)[1]),"+f"((cacc)[2]),"+f"((cacc)[3]) \
        : "r"((a)[0]),"r"((a)[1]),"r"((a)[2]),"r"((a)[3]), "r"(b0),"r"(b1))

#define LDSM_X4(r0, r1, r2, r3, addr) \
    asm volatile("ldmatrix.sync.aligned.m8n8.x4.shared.b16 {%0,%1,%2,%3}, [%4];" \
        : "=r"(r0), "=r"(r1), "=r"(r2), "=r"(r3) : "r"(addr))

#define CP_ASYNC16(dst, src, sz) \
    asm volatile("cp.async.cg.shared.global [%0], [%1], 16, %2;" \
        :: "r"(dst), "l"(src), "r"(sz))
#define CP_COMMIT() asm volatile("cp.async.commit_group;" ::: "memory")
#define CP_WAIT0()  asm volatile("cp.async.wait_group 0;" ::: "memory")

#define STAGE_BYTES 23040   // 8*60*24 halfs * 2B

__device__ __forceinline__ void stage_cc(uint32_t shdst, const __half* __restrict__ xnp,
                                         int i0, int cc, int tid) {
    #pragma unroll
    for (int it = 0; it < 4; it++) {
        int e = tid + it*256;
        if (e < 960) {
            int chunk = e & 1, px = e >> 1;
            int col = px % 60, row = px / 60;
            int gi = i0 - 2 + row, gj = col - 2;
            bool inb = ((unsigned)gi < HH) && ((unsigned)gj < WW);
            const __half* src = inb
                ? xnp + ((size_t)gi*WW + gj)*CC + cc*16 + chunk*8
                : xnp;
            CP_ASYNC16(shdst + px*48 + chunk*16, src, inb ? 16 : 0);
        }
    }
}

__global__ void __launch_bounds__(256) conv5_mma_kernel(const float* __restrict__ b1) {
    // two stage buffers: 8 rows x 60 cols x 24 halfs each (48B px-stride)
    __shared__ __align__(16) __half SH[2*8*60*24];

    int tid  = threadIdx.x;
    int lane = tid & 31, wid = tid >> 5;
    int wm = wid & 3, wn = wid >> 2;          // warp grid 4m x 2n
    int ot = blockIdx.x;                       // 0..1 (128 outch each)
    int i0 = blockIdx.y * 4;                   // output row tile (4 rows)
    int n  = blockIdx.z;
    const __half* xnp = g_xh + (size_t)n * HW * CC;

    float acc[2][14][4];
    #pragma unroll
    for (int mf = 0; mf < 2; mf++)
        #pragma unroll
        for (int nf = 0; nf < 14; nf++)
            #pragma unroll
            for (int q = 0; q < 4; q++) acc[mf][nf][q] = 0.f;

    // per-lane ldmatrix row addresses (buffer-relative)
    uint32_t sh0 = smem_u32(SH);
    int qsel = lane >> 3;
    int rrow = lane & 7;
    uint32_t lbase[7];
    #pragma unroll
    for (int np = 0; np < 7; np++) {
        int px = wn*112 + np*16 + (qsel >> 1)*8 + rrow;
        int pr = px / 56, pj = px % 56;
        lbase[np] = sh0 + ((pr*60 + pj)*24 + (qsel & 1)*8)*2;
    }

    const __half* aBase = g_wAh + (size_t)(ot*25)*16*2048 + (wm*2)*256 + lane*8;

    // prologue: stage cc=0 into buffer 0
    stage_cc(sh0, xnp, i0, 0, tid);
    CP_COMMIT();
    CP_WAIT0();
    __syncthreads();

    #pragma unroll 1
    for (int cc = 0; cc < 16; cc++) {
        int buf = cc & 1;
        uint32_t bo = (uint32_t)(buf * STAGE_BYTES);

        // async-prefetch next cc chunk into the other buffer
        if (cc < 15) {
            stage_cc(sh0 + (buf ^ 1)*STAGE_BYTES, xnp, i0, cc + 1, tid);
            CP_COMMIT();
        }

        // register double buffers over taps
        uint32_t ahb[2][2][4];
        uint32_t bmb[2][7][4];
        {
            const __half* tH = aBase + (size_t)cc*2048;
            #pragma unroll
            for (int mf = 0; mf < 2; mf++) {
                uint4 av = *(const uint4*)(tH + mf*256);
                ahb[0][mf][0] = av.x; ahb[0][mf][1] = av.y;
                ahb[0][mf][2] = av.z; ahb[0][mf][3] = av.w;
            }
            #pragma unroll
            for (int np = 0; np < 7; np++)
                LDSM_X4(bmb[0][np][0], bmb[0][np][1], bmb[0][np][2], bmb[0][np][3],
                        lbase[np] + bo);
        }

        #pragma unroll
        for (int tap = 0; tap < 25; tap++) {
            int cur = tap & 1, nxt = cur ^ 1;
            if (tap < 24) {
                int t1 = tap + 1;
                int du = t1 / 5, dv = t1 % 5;
                const __half* tH = aBase + (size_t)(t1*16 + cc)*2048;
                #pragma unroll
                for (int mf = 0; mf < 2; mf++) {
                    uint4 av = *(const uint4*)(tH + mf*256);
                    ahb[nxt][mf][0] = av.x; ahb[nxt][mf][1] = av.y;
                    ahb[nxt][mf][2] = av.z; ahb[nxt][mf][3] = av.w;
                }
                uint32_t taddr = bo + (uint32_t)((du*60 + dv)*48);
                #pragma unroll
                for (int np = 0; np < 7; np++)
                    LDSM_X4(bmb[nxt][np][0], bmb[nxt][np][1],
                            bmb[nxt][np][2], bmb[nxt][np][3],
                            lbase[np] + taddr);
            }
            #pragma unroll
            for (int np = 0; np < 7; np++) {
                #pragma unroll
                for (int mf = 0; mf < 2; mf++) {
                    MMA16816(acc[mf][2*np    ], ahb[cur][mf],
                             bmb[cur][np][0], bmb[cur][np][1]);
                    MMA16816(acc[mf][2*np + 1], ahb[cur][mf],
                             bmb[cur][np][2], bmb[cur][np][3]);
                }
            }
        }

        if (cc < 15) {
            CP_WAIT0();
            __syncthreads();
        }
    }

    // epilogue: +bias, write 224 contiguous px per o-row
    int r = lane >> 2, q = 2*(lane & 3);
    #pragma unroll
    for (int mf = 0; mf < 2; mf++) {
        int o0 = ot*128 + wm*32 + mf*16 + r;
        float bb0 = b1[o0], bb1 = b1[o0 + 8];
        float* h0 = g_h + ((size_t)n*CC + o0)*HW + i0*WW;
        float* h1 = h0 + (size_t)8*HW;
        #pragma unroll
        for (int nf = 0; nf < 14; nf++) {
            int px = wn*112 + nf*8 + q;
            float2 v0 = make_float2(acc[mf][nf][0] + bb0, acc[mf][nf][1] + bb0);
            float2 v1 = make_float2(acc[mf][nf][2] + bb1, acc[mf][nf][3] + bb1);
            *(float2*)(h0 + px) = v0;
            *(float2*)(h1 + px) = v1;
        }
    }
}

// ---------------- exact border correction ----------------
__global__ void __launch_bounds__(256) corr_kernel() {
    __shared__ __align__(16) float xs[32][32];
    int o = threadIdx.x;
    int pi, pj; band_pos(blockIdx.x, pi, pj);
    float acc[NN];
    #pragma unroll
    for (int n = 0; n < NN; n++) acc[n] = 0.f;

    for (int g = 0; g < 8; g++) {
        int di = c_di[g], dj = c_dj[g];
        for (int a = 0; a < 3; a++) {
            for (int b = 0; b < 3; b++) {
                int qi = pi + a - 1, qj = pj + b - 1;
                int ui = qi - di,     uj = qj - dj;
                bool qin = ((unsigned)qi < HH) && ((unsigned)qj < WW);
                bool uin = ((unsigned)ui < HH) && ((unsigned)uj < WW);
                float sgn; int ri, rj;
                if (qin && !uin)      { sgn = -1.f; ri = qi; rj = qj; }
                else if (!qin && uin) { sgn =  1.f; ri = ui; rj = uj; }
                else continue;
                int rid = band_id(ri, rj);
                const float* xbp = g_xb + (size_t)rid * CC * NN;
                const float* wp  = g_wt + (size_t)(g*9 + a*3 + b) * CC * CC + o;
                for (int cb = 0; cb < CC; cb += 32) {
                    __syncthreads();
                    for (int e = o; e < 32*NN; e += 256)
                        xs[e / NN][e % NN] = xbp[(size_t)cb*NN + e];
                    __syncthreads();
                    #pragma unroll 1
                    for (int c = 0; c < 32; c++) {
                        float w = sgn * wp[(size_t)(cb + c) * CC];
                        #pragma unroll
                        for (int n4 = 0; n4 < 8; n4++) {
                            float4 v = *(const float4*)&xs[c][n4*4];
                            acc[n4*4+0] += w * v.x;
                            acc[n4*4+1] += w * v.y;
                            acc[n4*4+2] += w * v.z;
                            acc[n4*4+3] += w * v.w;
                        }
                    }
                }
            }
        }
    }
    size_t base = (size_t)o*HW + pi*WW + pj;
    #pragma unroll
    for (int n = 0; n < NN; n++)
        g_h[(size_t)n*CC*HW + base] += acc[n];
}

// ---------------- 1x1 conv ----------------
__global__ void __launch_bounds__(256) conv1x1_kernel(const float* __restrict__ w2,
                                                      const float* __restrict__ b2,
                                                      float* __restrict__ out) {
    __shared__ __align__(16) float hs[32][128];
    __shared__ __align__(16) float ws2[32][80];
    int tid = threadIdx.x;
    int n = blockIdx.y;
    int pbase = blockIdx.x * 128;
    int pxg = tid % 32, ocg = tid / 32;
    int px0 = pxg * 4, oc0 = ocg * 10;

    float acc[10][4];
    #pragma unroll
    for (int k = 0; k < 10; k++)
        #pragma unroll
        for (int j = 0; j < 4; j++) acc[k][j] = 0.f;

    for (int cb = 0; cb < CC; cb += 32) {
        for (int e = tid; e < 32*128; e += 256) {
            int c = e / 128, p = e % 128;
            int gp = pbase + p;
            hs[c][p] = (gp < HW) ? g_h[((size_t)n*CC + cb + c)*HW + gp] : 0.f;
        }
        for (int e = tid; e < 32*80; e += 256) {
            int c = e / 80, oc = e % 80;
            ws2[c][oc] = w2[(size_t)oc*CC + cb + c];
        }
        __syncthreads();
        #pragma unroll 1
        for (int c = 0; c < 32; c++) {
            float4 hv = *(const float4*)&hs[c][px0];
            #pragma unroll
            for (int k = 0; k < 10; k++) {
                float wv = ws2[c][oc0 + k];
                acc[k][0] += wv * hv.x;
                acc[k][1] += wv * hv.y;
                acc[k][2] += wv * hv.z;
                acc[k][3] += wv * hv.w;
            }
        }
        __syncthreads();
    }

    #pragma unroll
    for (int k = 0; k < 10; k++) {
        int oc = oc0 + k;
        float bb = b2[oc];
        #pragma unroll
        for (int j = 0; j < 4; j++) {
            int gp = pbase + px0 + j;
            if (gp < HW)
                out[((size_t)n*OC2 + oc)*HW + gp] = acc[k][j] + bb;
        }
    }
}

extern "C" void kernel_launch(void* const* d_in, const int* in_sizes, int n_in,
                              void* d_out, int out_size) {
    const float *x = nullptr, *w1 = nullptr, *b1 = nullptr, *w2 = nullptr, *b2 = nullptr;
    for (int i = 0; i < n_in; i++) {
        long s = in_sizes[i];
        const float* p = (const float*)d_in[i];
        if      (s == (long)NN*CC*HW)   x  = p;
        else if (s == (long)CC*9*CC*9)  w1 = p;
        else if (s == CC)               b1 = p;
        else if (s == (long)OC2*CC)     w2 = p;
        else if (s == OC2)              b2 = p;
    }
    float* out = (float*)d_out;

    fold_kernel<<<(CC*25*CC + 255)/256, 256>>>(w1);
    wprep_kernel<<<(800*2048 + 255)/256, 256>>>();
    xprep_kernel<<<dim3(98, 8, NN), 256>>>(x);
    tw1_kernel<<<(int)(((size_t)8*9*CC*CC + 255)/256), 256>>>(w1);
    gather_kernel<<<(NBAND*CC*NN + 255)/256, 256>>>(x);
    conv5_mma_kernel<<<dim3(2, 14, NN), 256>>>(b1);
    corr_kernel<<<NBAND, 256>>>();
    conv1x1_kernel<<<dim3(25, NN), 256>>>(w2, b2, out);
}

// round 11
// speedup vs baseline: 6.6322x; 1.4704x over previous
#include <cuda_runtime.h>
#include <cuda_fp16.h>
#include <cstdint>
#include <cstddef>

#define NN 32
#define CC 256
#define HH 56
#define WW 56
#define HW (HH*WW)
#define OC2 80
#define NBAND 432
#define INV_SQRT2 0.7071067811865476f

__constant__ int c_di[8] = {1,-1,0,0,1,1,-1,-1};
__constant__ int c_dj[8] = {0,0,1,-1,1,-1,1,-1};

// Scratch (static device globals)
__device__ float g_weff[(size_t)CC*25*CC];        // [c][tap5x5][o]
__device__ float g_xb  [(size_t)NBAND*CC*NN];     // [band][c][n]
__device__ float g_h   [(size_t)NN*CC*HW];        // hidden activations
__device__ __half g_xh [(size_t)NN*HW*CC];        // x transposed: [n][px][c] fp16
__device__ __align__(16) __half g_wAh[(size_t)800*2048]; // A tiles packed
// Aggregated border-correction weights: [cls*25+slot][c][o]
__device__ float g_wagg[(size_t)625*CC*CC];
__device__ int   g_aggcnt[625];
__device__ int   g_aggcombo[625*20];
__device__ float g_aggcoef[625*20];

// ---------------- band helpers ----------------
__device__ __forceinline__ int band_id(int i, int j) {
    if (i < 2)   return i*WW + j;
    if (i >= 54) return 112 + (i-54)*WW + j;
    int k = (j < 2) ? j : (j - 52);
    return 224 + (i-2)*4 + k;
}
__device__ __forceinline__ void band_pos(int id, int& i, int& j) {
    if (id < 112)      { i = id/WW;           j = id%WW; }
    else if (id < 224) { int t = id-112; i = 54 + t/WW; j = t%WW; }
    else               { int t = id-224; i = 2 + t/4; int k = t%4; j = (k<2)?k:(52+k); }
}

__device__ __forceinline__ uint32_t smem_u32(const void* p) {
    uint32_t a;
    asm("{ .reg .u64 t; cvta.to.shared.u64 t, %1; cvt.u32.u64 %0, t; }" : "=r"(a) : "l"(p));
    return a;
}

// ---------------- fold 9-group 3x3 -> effective 5x5 ----------------
__global__ void fold_kernel(const float* __restrict__ w1) {
    int idx = blockIdx.x * blockDim.x + threadIdx.x;
    if (idx >= CC*25*CC) return;
    int o   = idx % CC;
    int tap = (idx / CC) % 25;
    int c   = idx / (CC*25);
    int du = tap/5 - 2, dv = tap%5 - 2;
    float t = 0.f;
    if (du >= -1 && du <= 1 && dv >= -1 && dv <= 1) {
        int a = du + 1, b = dv + 1;
        t += w1[(((size_t)o*2304 + c)*3 + a)*3 + b];
        #pragma unroll
        for (int g = 0; g < 8; g++) {
            float s = (g < 4) ? 1.f : INV_SQRT2;
            t += s * w1[(((size_t)o*2304 + (g+1)*CC + c)*3 + a)*3 + b];
        }
    }
    #pragma unroll
    for (int g = 0; g < 8; g++) {
        int a = du + c_di[g] + 1, b = dv + c_dj[g] + 1;
        if (a >= 0 && a < 3 && b >= 0 && b < 3) {
            float s = (g < 4) ? 1.f : INV_SQRT2;
            t -= s * w1[(((size_t)o*2304 + (g+1)*CC + c)*3 + a)*3 + b];
        }
    }
    g_weff[((size_t)c*25 + tap)*CC + o] = t;
}

// ---------------- border-correction aggregation table ----------------
// class ci/cj: 0,1 -> rows 0,1; 2 -> interior; 3,4 -> rows 54,55
__global__ void aggtab_kernel() {
    int sc = threadIdx.x;       // 0..624
    if (sc >= 625) return;
    int cls = sc / 25, slot = sc % 25;
    int ci = cls / 5, cj = cls % 5;
    int oi = slot/5 - 2, oj = slot%5 - 2;
    const int rep[5] = {0, 1, 28, 54, 55};
    int pi = rep[ci], pj = rep[cj];
    int cnt = 0;
    if (!(ci == 2 && cj == 2)) {
        for (int g = 0; g < 8; g++) {
            int di = c_di[g], dj = c_dj[g];
            for (int a = 0; a < 3; a++) {
                for (int b = 0; b < 3; b++) {
                    int qi = pi + a - 1, qj = pj + b - 1;
                    int ui = qi - di,    uj = qj - dj;
                    bool qin = ((unsigned)qi < HH) && ((unsigned)qj < WW);
                    bool uin = ((unsigned)ui < HH) && ((unsigned)uj < WW);
                    float sgn; int si, sj;
                    if (qin && !uin)      { sgn = -1.f; si = qi; sj = qj; }
                    else if (!qin && uin) { sgn =  1.f; si = ui; sj = uj; }
                    else continue;
                    if (si - pi == oi && sj - pj == oj && cnt < 20) {
                        g_aggcombo[sc*20 + cnt] = g*9 + a*3 + b;
                        g_aggcoef [sc*20 + cnt] = sgn * ((g < 4) ? 1.f : INV_SQRT2);
                        cnt++;
                    }
                }
            }
        }
    }
    g_aggcnt[sc] = cnt;
}

// ---------------- materialize aggregated weights ----------------
__global__ void wagg_kernel(const float* __restrict__ w1) {
    int sc = blockIdx.x;        // 0..624
    int c  = blockIdx.y;        // 0..255
    int o  = threadIdx.x;       // 0..255
    int cnt = g_aggcnt[sc];
    float t = 0.f;
    for (int k = 0; k < cnt; k++) {
        int combo = g_aggcombo[sc*20 + k];
        float cf  = g_aggcoef [sc*20 + k];
        int g = combo / 9, tap = combo % 9;
        t += cf * w1[((size_t)o*2304 + (g+1)*CC + c)*9 + tap];
    }
    g_wagg[((size_t)sc*CC + c)*CC + o] = t;
}

// ---------------- gather band x ----------------
__global__ void gather_kernel(const float* __restrict__ x) {
    size_t idx = (size_t)blockIdx.x * blockDim.x + threadIdx.x;
    if (idx >= (size_t)NBAND*CC*NN) return;
    int n   = idx % NN;
    int c   = (idx / NN) % CC;
    int rid = idx / (NN*CC);
    int i, j; band_pos(rid, i, j);
    g_xb[idx] = x[((size_t)n*CC + c)*HW + i*WW + j];
}

// ---------------- x transpose: [n][c][px] fp32 -> [n][px][c] fp16 ----------
__global__ void xprep_kernel(const float* __restrict__ x) {
    __shared__ float t[32][33];
    int n  = blockIdx.z;
    int cb = blockIdx.y * 32;
    int pb = blockIdx.x * 32;
    int tx = threadIdx.x & 31, ty = threadIdx.x >> 5;
    #pragma unroll
    for (int r = ty; r < 32; r += 8)
        t[r][tx] = x[((size_t)n*CC + cb + r)*HW + pb + tx];
    __syncthreads();
    #pragma unroll
    for (int r = ty; r < 32; r += 8)
        g_xh[((size_t)n*HW + pb + r)*CC + cb + tx] = __float2half_rn(t[tx][r]);
}

// ---------------- weight prep: Weff -> fp16 A fragments, LDG.128-packed ----
__global__ void wprep_kernel() {
    int idx = blockIdx.x * blockDim.x + threadIdx.x;
    if (idx >= 800*2048) return;
    int e    = idx & 2047;
    int tile = idx >> 11;
    int h     = e & 7;
    int lane  = (e >> 3) & 31;
    int wmmf  = e >> 8;
    int wm = wmmf >> 1, mf = wmmf & 1;
    int apair = h >> 1, half = h & 1;
    int o = wm*32 + mf*16 + (lane >> 2) + (apair & 1)*8;
    int c = 2*(lane & 3) + (apair >> 1)*8 + half;
    int ccv = tile & 15;
    int t3 = tile >> 4;
    int tap = t3 % 25, ot = t3 / 25;
    float v = g_weff[(((size_t)(ccv*16 + c))*25 + tap)*CC + ot*128 + o];
    g_wAh[idx] = __float2half_rn(v);
}

// ---------------- conv5: mma.sync + cp.async double-buffered staging -------
#define MMA16816(cacc, a, b0, b1) \
    asm volatile("mma.sync.aligned.m16n8k16.row.col.f32.f16.f16.f32 " \
        "{%0,%1,%2,%3}, {%4,%5,%6,%7}, {%8,%9}, {%0,%1,%2,%3};" \
        : "+f"((cacc)[0]),"+f"((cacc)[1]),"+f"((cacc)[2]),"+f"((cacc)[3]) \
        : "r"((a)[0]),"r"((a)[1]),"r"((a)[2]),"r"((a)[3]), "r"(b0),"r"(b1))

#define LDSM_X4(r0, r1, r2, r3, addr) \
    asm volatile("ldmatrix.sync.aligned.m8n8.x4.shared.b16 {%0,%1,%2,%3}, [%4];" \
        : "=r"(r0), "=r"(r1), "=r"(r2), "=r"(r3) : "r"(addr))

#define CP_ASYNC16(dst, src, sz) \
    asm volatile("cp.async.cg.shared.global [%0], [%1], 16, %2;" \
        :: "r"(dst), "l"(src), "r"(sz))
#define CP_COMMIT() asm volatile("cp.async.commit_group;" ::: "memory")
#define CP_WAIT0()  asm volatile("cp.async.wait_group 0;" ::: "memory")

#define STAGE_BYTES 23040   // 8*60*24 halfs * 2B

__device__ __forceinline__ void stage_cc(uint32_t shdst, const __half* __restrict__ xnp,
                                         int i0, int cc, int tid) {
    #pragma unroll
    for (int it = 0; it < 4; it++) {
        int e = tid + it*256;
        if (e < 960) {
            int chunk = e & 1, px = e >> 1;
            int col = px % 60, row = px / 60;
            int gi = i0 - 2 + row, gj = col - 2;
            bool inb = ((unsigned)gi < HH) && ((unsigned)gj < WW);
            const __half* src = inb
                ? xnp + ((size_t)gi*WW + gj)*CC + cc*16 + chunk*8
                : xnp;
            CP_ASYNC16(shdst + px*48 + chunk*16, src, inb ? 16 : 0);
        }
    }
}

__global__ void __launch_bounds__(256) conv5_mma_kernel(const float* __restrict__ b1) {
    __shared__ __align__(16) __half SH[2*8*60*24];

    int tid  = threadIdx.x;
    int lane = tid & 31, wid = tid >> 5;
    int wm = wid & 3, wn = wid >> 2;
    int ot = blockIdx.x;
    int i0 = blockIdx.y * 4;
    int n  = blockIdx.z;
    const __half* xnp = g_xh + (size_t)n * HW * CC;

    float acc[2][14][4];
    #pragma unroll
    for (int mf = 0; mf < 2; mf++)
        #pragma unroll
        for (int nf = 0; nf < 14; nf++)
            #pragma unroll
            for (int q = 0; q < 4; q++) acc[mf][nf][q] = 0.f;

    uint32_t sh0 = smem_u32(SH);
    int qsel = lane >> 3;
    int rrow = lane & 7;
    uint32_t lbase[7];
    #pragma unroll
    for (int np = 0; np < 7; np++) {
        int px = wn*112 + np*16 + (qsel >> 1)*8 + rrow;
        int pr = px / 56, pj = px % 56;
        lbase[np] = sh0 + ((pr*60 + pj)*24 + (qsel & 1)*8)*2;
    }

    const __half* aBase = g_wAh + (size_t)(ot*25)*16*2048 + (wm*2)*256 + lane*8;

    stage_cc(sh0, xnp, i0, 0, tid);
    CP_COMMIT();
    CP_WAIT0();
    __syncthreads();

    #pragma unroll 1
    for (int cc = 0; cc < 16; cc++) {
        int buf = cc & 1;
        uint32_t bo = (uint32_t)(buf * STAGE_BYTES);

        if (cc < 15) {
            stage_cc(sh0 + (buf ^ 1)*STAGE_BYTES, xnp, i0, cc + 1, tid);
            CP_COMMIT();
        }

        uint32_t ahb[2][2][4];
        uint32_t bmb[2][7][4];
        {
            const __half* tH = aBase + (size_t)cc*2048;
            #pragma unroll
            for (int mf = 0; mf < 2; mf++) {
                uint4 av = *(const uint4*)(tH + mf*256);
                ahb[0][mf][0] = av.x; ahb[0][mf][1] = av.y;
                ahb[0][mf][2] = av.z; ahb[0][mf][3] = av.w;
            }
            #pragma unroll
            for (int np = 0; np < 7; np++)
                LDSM_X4(bmb[0][np][0], bmb[0][np][1], bmb[0][np][2], bmb[0][np][3],
                        lbase[np] + bo);
        }

        #pragma unroll
        for (int tap = 0; tap < 25; tap++) {
            int cur = tap & 1, nxt = cur ^ 1;
            if (tap < 24) {
                int t1 = tap + 1;
                int du = t1 / 5, dv = t1 % 5;
                const __half* tH = aBase + (size_t)(t1*16 + cc)*2048;
                #pragma unroll
                for (int mf = 0; mf < 2; mf++) {
                    uint4 av = *(const uint4*)(tH + mf*256);
                    ahb[nxt][mf][0] = av.x; ahb[nxt][mf][1] = av.y;
                    ahb[nxt][mf][2] = av.z; ahb[nxt][mf][3] = av.w;
                }
                uint32_t taddr = bo + (uint32_t)((du*60 + dv)*48);
                #pragma unroll
                for (int np = 0; np < 7; np++)
                    LDSM_X4(bmb[nxt][np][0], bmb[nxt][np][1],
                            bmb[nxt][np][2], bmb[nxt][np][3],
                            lbase[np] + taddr);
            }
            #pragma unroll
            for (int np = 0; np < 7; np++) {
                #pragma unroll
                for (int mf = 0; mf < 2; mf++) {
                    MMA16816(acc[mf][2*np    ], ahb[cur][mf],
                             bmb[cur][np][0], bmb[cur][np][1]);
                    MMA16816(acc[mf][2*np + 1], ahb[cur][mf],
                             bmb[cur][np][2], bmb[cur][np][3]);
                }
            }
        }

        if (cc < 15) {
            CP_WAIT0();
            __syncthreads();
        }
    }

    int r = lane >> 2, q = 2*(lane & 3);
    #pragma unroll
    for (int mf = 0; mf < 2; mf++) {
        int o0 = ot*128 + wm*32 + mf*16 + r;
        float bb0 = b1[o0], bb1 = b1[o0 + 8];
        float* h0 = g_h + ((size_t)n*CC + o0)*HW + i0*WW;
        float* h1 = h0 + (size_t)8*HW;
        #pragma unroll
        for (int nf = 0; nf < 14; nf++) {
            int px = wn*112 + nf*8 + q;
            float2 v0 = make_float2(acc[mf][nf][0] + bb0, acc[mf][nf][1] + bb0);
            float2 v1 = make_float2(acc[mf][nf][2] + bb1, acc[mf][nf][3] + bb1);
            *(float2*)(h0 + px) = v0;
            *(float2*)(h1 + px) = v1;
        }
    }
}

// ---------------- border correction via aggregated source weights ---------
__global__ void __launch_bounds__(256) corr_kernel() {
    __shared__ __align__(16) float xs[32][32];
    int o = threadIdx.x;
    int pi, pj; band_pos(blockIdx.x, pi, pj);
    int ci = pi < 2 ? pi : (pi > 53 ? pi - 51 : 2);
    int cj = pj < 2 ? pj : (pj > 53 ? pj - 51 : 2);
    int cls = ci*5 + cj;
    float acc[NN];
    #pragma unroll
    for (int n = 0; n < NN; n++) acc[n] = 0.f;

    for (int slot = 0; slot < 25; slot++) {
        int sc = cls*25 + slot;
        if (g_aggcnt[sc] == 0) continue;
        int si = pi + slot/5 - 2, sj = pj + slot%5 - 2;
        int rid = band_id(si, sj);
        const float* xbp = g_xb + (size_t)rid * CC * NN;
        const float* wp  = g_wagg + (size_t)sc * CC * CC + o;
        for (int cb = 0; cb < CC; cb += 32) {
            __syncthreads();
            for (int e = o; e < 32*NN; e += 256)
                xs[e / NN][e % NN] = xbp[(size_t)cb*NN + e];
            __syncthreads();
            #pragma unroll 1
            for (int c = 0; c < 32; c++) {
                float w = wp[(size_t)(cb + c) * CC];
                #pragma unroll
                for (int n4 = 0; n4 < 8; n4++) {
                    float4 v = *(const float4*)&xs[c][n4*4];
                    acc[n4*4+0] += w * v.x;
                    acc[n4*4+1] += w * v.y;
                    acc[n4*4+2] += w * v.z;
                    acc[n4*4+3] += w * v.w;
                }
            }
        }
    }
    size_t base = (size_t)o*HW + pi*WW + pj;
    #pragma unroll
    for (int n = 0; n < NN; n++)
        g_h[(size_t)n*CC*HW + base] += acc[n];
}

// ---------------- 1x1 conv ----------------
__global__ void __launch_bounds__(256) conv1x1_kernel(const float* __restrict__ w2,
                                                      const float* __restrict__ b2,
                                                      float* __restrict__ out) {
    __shared__ __align__(16) float hs[32][128];
    __shared__ __align__(16) float ws2[32][80];
    int tid = threadIdx.x;
    int n = blockIdx.y;
    int pbase = blockIdx.x * 128;
    int pxg = tid % 32, ocg = tid / 32;
    int px0 = pxg * 4, oc0 = ocg * 10;

    float acc[10][4];
    #pragma unroll
    for (int k = 0; k < 10; k++)
        #pragma unroll
        for (int j = 0; j < 4; j++) acc[k][j] = 0.f;

    for (int cb = 0; cb < CC; cb += 32) {
        for (int e = tid; e < 32*128; e += 256) {
            int c = e / 128, p = e % 128;
            int gp = pbase + p;
            hs[c][p] = (gp < HW) ? g_h[((size_t)n*CC + cb + c)*HW + gp] : 0.f;
        }
        for (int e = tid; e < 32*80; e += 256) {
            int c = e / 80, oc = e % 80;
            ws2[c][oc] = w2[(size_t)oc*CC + cb + c];
        }
        __syncthreads();
        #pragma unroll 1
        for (int c = 0; c < 32; c++) {
            float4 hv = *(const float4*)&hs[c][px0];
            #pragma unroll
            for (int k = 0; k < 10; k++) {
                float wv = ws2[c][oc0 + k];
                acc[k][0] += wv * hv.x;
                acc[k][1] += wv * hv.y;
                acc[k][2] += wv * hv.z;
                acc[k][3] += wv * hv.w;
            }
        }
        __syncthreads();
    }

    #pragma unroll
    for (int k = 0; k < 10; k++) {
        int oc = oc0 + k;
        float bb = b2[oc];
        #pragma unroll
        for (int j = 0; j < 4; j++) {
            int gp = pbase + px0 + j;
            if (gp < HW)
                out[((size_t)n*OC2 + oc)*HW + gp] = acc[k][j] + bb;
        }
    }
}

extern "C" void kernel_launch(void* const* d_in, const int* in_sizes, int n_in,
                              void* d_out, int out_size) {
    const float *x = nullptr, *w1 = nullptr, *b1 = nullptr, *w2 = nullptr, *b2 = nullptr;
    for (int i = 0; i < n_in; i++) {
        long s = in_sizes[i];
        const float* p = (const float*)d_in[i];
        if      (s == (long)NN*CC*HW)   x  = p;
        else if (s == (long)CC*9*CC*9)  w1 = p;
        else if (s == CC)               b1 = p;
        else if (s == (long)OC2*CC)     w2 = p;
        else if (s == OC2)              b2 = p;
    }
    float* out = (float*)d_out;

    fold_kernel<<<(CC*25*CC + 255)/256, 256>>>(w1);
    wprep_kernel<<<(800*2048 + 255)/256, 256>>>();
    xprep_kernel<<<dim3(98, 8, NN), 256>>>(x);
    aggtab_kernel<<<1, 640>>>();
    wagg_kernel<<<dim3(625, 256), 256>>>(w1);
    gather_kernel<<<(NBAND*CC*NN + 255)/256, 256>>>(x);
    conv5_mma_kernel<<<dim3(2, 14, NN), 256>>>(b1);
    corr_kernel<<<NBAND, 256>>>();
    conv1x1_kernel<<<dim3(25, NN), 256>>>(w2, b2, out);
}

// round 12
// speedup vs baseline: 6.7286x; 1.0145x over previous
#include <cuda_runtime.h>
#include <cuda_fp16.h>
#include <cstdint>
#include <cstddef>

#define NN 32
#define CC 256
#define HH 56
#define WW 56
#define HW (HH*WW)
#define OC2 80
#define NBAND 432
#define INV_SQRT2 0.7071067811865476f

__constant__ int c_di[8] = {1,-1,0,0,1,1,-1,-1};
__constant__ int c_dj[8] = {0,0,1,-1,1,-1,1,-1};

// Scratch (static device globals)
__device__ float g_weff[(size_t)CC*25*CC];        // [c][tap5x5][o]
__device__ float g_xb  [(size_t)NBAND*CC*NN];     // [band][c][n]
__device__ float g_h   [(size_t)NN*CC*HW];        // hidden activations
__device__ __half g_xh [(size_t)NN*HW*CC];        // x transposed: [n][px][c] fp16
__device__ __align__(16) __half g_wAh[(size_t)800*2048]; // A tiles packed
// Aggregated border-correction weights: [cls*25+slot][c][o]
__device__ float g_wagg[(size_t)625*CC*CC];
__device__ int   g_aggcnt[625];
__device__ int   g_aggcombo[625*20];
__device__ float g_aggcoef[625*20];

// ---------------- band helpers ----------------
__device__ __forceinline__ int band_id(int i, int j) {
    if (i < 2)   return i*WW + j;
    if (i >= 54) return 112 + (i-54)*WW + j;
    int k = (j < 2) ? j : (j - 52);
    return 224 + (i-2)*4 + k;
}
__device__ __forceinline__ void band_pos(int id, int& i, int& j) {
    if (id < 112)      { i = id/WW;           j = id%WW; }
    else if (id < 224) { int t = id-112; i = 54 + t/WW; j = t%WW; }
    else               { int t = id-224; i = 2 + t/4; int k = t%4; j = (k<2)?k:(52+k); }
}

__device__ __forceinline__ uint32_t smem_u32(const void* p) {
    uint32_t a;
    asm("{ .reg .u64 t; cvta.to.shared.u64 t, %1; cvt.u32.u64 %0, t; }" : "=r"(a) : "l"(p));
    return a;
}

// ---------------- fold 9-group 3x3 -> effective 5x5 ----------------
__global__ void fold_kernel(const float* __restrict__ w1) {
    int idx = blockIdx.x * blockDim.x + threadIdx.x;
    if (idx >= CC*25*CC) return;
    int o   = idx % CC;
    int tap = (idx / CC) % 25;
    int c   = idx / (CC*25);
    int du = tap/5 - 2, dv = tap%5 - 2;
    float t = 0.f;
    if (du >= -1 && du <= 1 && dv >= -1 && dv <= 1) {
        int a = du + 1, b = dv + 1;
        t += w1[(((size_t)o*2304 + c)*3 + a)*3 + b];
        #pragma unroll
        for (int g = 0; g < 8; g++) {
            float s = (g < 4) ? 1.f : INV_SQRT2;
            t += s * w1[(((size_t)o*2304 + (g+1)*CC + c)*3 + a)*3 + b];
        }
    }
    #pragma unroll
    for (int g = 0; g < 8; g++) {
        int a = du + c_di[g] + 1, b = dv + c_dj[g] + 1;
        if (a >= 0 && a < 3 && b >= 0 && b < 3) {
            float s = (g < 4) ? 1.f : INV_SQRT2;
            t -= s * w1[(((size_t)o*2304 + (g+1)*CC + c)*3 + a)*3 + b];
        }
    }
    g_weff[((size_t)c*25 + tap)*CC + o] = t;
}

// ---------------- border-correction aggregation table ----------------
__global__ void aggtab_kernel() {
    int sc = threadIdx.x;       // 0..624
    if (sc >= 625) return;
    int cls = sc / 25, slot = sc % 25;
    int ci = cls / 5, cj = cls % 5;
    int oi = slot/5 - 2, oj = slot%5 - 2;
    const int rep[5] = {0, 1, 28, 54, 55};
    int pi = rep[ci], pj = rep[cj];
    int cnt = 0;
    if (!(ci == 2 && cj == 2)) {
        for (int g = 0; g < 8; g++) {
            int di = c_di[g], dj = c_dj[g];
            for (int a = 0; a < 3; a++) {
                for (int b = 0; b < 3; b++) {
                    int qi = pi + a - 1, qj = pj + b - 1;
                    int ui = qi - di,    uj = qj - dj;
                    bool qin = ((unsigned)qi < HH) && ((unsigned)qj < WW);
                    bool uin = ((unsigned)ui < HH) && ((unsigned)uj < WW);
                    float sgn; int si, sj;
                    if (qin && !uin)      { sgn = -1.f; si = qi; sj = qj; }
                    else if (!qin && uin) { sgn =  1.f; si = ui; sj = uj; }
                    else continue;
                    if (si - pi == oi && sj - pj == oj && cnt < 20) {
                        g_aggcombo[sc*20 + cnt] = g*9 + a*3 + b;
                        g_aggcoef [sc*20 + cnt] = sgn * ((g < 4) ? 1.f : INV_SQRT2);
                        cnt++;
                    }
                }
            }
        }
    }
    g_aggcnt[sc] = cnt;
}

// ---------------- materialize aggregated weights ----------------
__global__ void wagg_kernel(const float* __restrict__ w1) {
    int sc = blockIdx.x;        // 0..624
    int c  = blockIdx.y;        // 0..255
    int o  = threadIdx.x;       // 0..255
    int cnt = g_aggcnt[sc];
    float t = 0.f;
    for (int k = 0; k < cnt; k++) {
        int combo = g_aggcombo[sc*20 + k];
        float cf  = g_aggcoef [sc*20 + k];
        int g = combo / 9, tap = combo % 9;
        t += cf * w1[((size_t)o*2304 + (g+1)*CC + c)*9 + tap];
    }
    g_wagg[((size_t)sc*CC + c)*CC + o] = t;
}

// ---------------- gather band x ----------------
__global__ void gather_kernel(const float* __restrict__ x) {
    size_t idx = (size_t)blockIdx.x * blockDim.x + threadIdx.x;
    if (idx >= (size_t)NBAND*CC*NN) return;
    int n   = idx % NN;
    int c   = (idx / NN) % CC;
    int rid = idx / (NN*CC);
    int i, j; band_pos(rid, i, j);
    g_xb[idx] = x[((size_t)n*CC + c)*HW + i*WW + j];
}

// ---------------- x transpose: [n][c][px] fp32 -> [n][px][c] fp16 ----------
__global__ void xprep_kernel(const float* __restrict__ x) {
    __shared__ float t[32][33];
    int n  = blockIdx.z;
    int cb = blockIdx.y * 32;
    int pb = blockIdx.x * 32;
    int tx = threadIdx.x & 31, ty = threadIdx.x >> 5;
    #pragma unroll
    for (int r = ty; r < 32; r += 8)
        t[r][tx] = x[((size_t)n*CC + cb + r)*HW + pb + tx];
    __syncthreads();
    #pragma unroll
    for (int r = ty; r < 32; r += 8)
        g_xh[((size_t)n*HW + pb + r)*CC + cb + tx] = __float2half_rn(t[tx][r]);
}

// ---------------- weight prep: Weff -> fp16 A fragments (layout unchanged) --
__global__ void wprep_kernel() {
    int idx = blockIdx.x * blockDim.x + threadIdx.x;
    if (idx >= 800*2048) return;
    int e    = idx & 2047;
    int tile = idx >> 11;
    int h     = e & 7;
    int lane  = (e >> 3) & 31;
    int wmmf  = e >> 8;                  // now warp index 0..7 (16 o each)
    int apair = h >> 1, half = h & 1;
    int o = wmmf*16 + (lane >> 2) + (apair & 1)*8;
    int c = 2*(lane & 3) + (apair >> 1)*8 + half;
    int ccv = tile & 15;
    int t3 = tile >> 4;
    int tap = t3 % 25, ot = t3 / 25;
    float v = g_weff[(((size_t)(ccv*16 + c))*25 + tap)*CC + ot*128 + o];
    g_wAh[idx] = __float2half_rn(v);
}

// ---------------- conv5: occupancy-2 mma.sync + cp.async staging -----------
#define MMA16816(cacc, a, b0, b1) \
    asm volatile("mma.sync.aligned.m16n8k16.row.col.f32.f16.f16.f32 " \
        "{%0,%1,%2,%3}, {%4,%5,%6,%7}, {%8,%9}, {%0,%1,%2,%3};" \
        : "+f"((cacc)[0]),"+f"((cacc)[1]),"+f"((cacc)[2]),"+f"((cacc)[3]) \
        : "r"((a)[0]),"r"((a)[1]),"r"((a)[2]),"r"((a)[3]), "r"(b0),"r"(b1))

#define LDSM_X4(r0, r1, r2, r3, addr) \
    asm volatile("ldmatrix.sync.aligned.m8n8.x4.shared.b16 {%0,%1,%2,%3}, [%4];" \
        : "=r"(r0), "=r"(r1), "=r"(r2), "=r"(r3) : "r"(addr))

#define CP_ASYNC16(dst, src, sz) \
    asm volatile("cp.async.cg.shared.global [%0], [%1], 16, %2;" \
        :: "r"(dst), "l"(src), "r"(sz))
#define CP_COMMIT() asm volatile("cp.async.commit_group;" ::: "memory")
#define CP_WAIT0()  asm volatile("cp.async.wait_group 0;" ::: "memory")

#define STAGE_BYTES 17280   // 6*60*24 halfs * 2B

// stage 6 rows x 60 cols x 16 channels of one cc chunk
__device__ __forceinline__ void stage_cc(uint32_t shdst, const __half* __restrict__ xnp,
                                         int i0, int cc, int tid) {
    #pragma unroll
    for (int it = 0; it < 3; it++) {
        int e = tid + it*256;
        if (e < 720) {
            int chunk = e & 1, px = e >> 1;
            int col = px % 60, row = px / 60;
            int gi = i0 - 2 + row, gj = col - 2;
            bool inb = ((unsigned)gi < HH) && ((unsigned)gj < WW);
            const __half* src = inb
                ? xnp + ((size_t)gi*WW + gj)*CC + cc*16 + chunk*8
                : xnp;
            CP_ASYNC16(shdst + px*48 + chunk*16, src, inb ? 16 : 0);
        }
    }
}

__global__ void __launch_bounds__(256, 2) conv5_mma_kernel(const float* __restrict__ b1) {
    __shared__ __align__(16) __half SH[2*6*60*24];

    int tid  = threadIdx.x;
    int lane = tid & 31, wm = tid >> 5;   // 8 warps, 16 o each
    int ot = blockIdx.x;                   // 0..1
    int i0 = blockIdx.y * 2;               // 2 output rows
    int n  = blockIdx.z;
    const __half* xnp = g_xh + (size_t)n * HW * CC;

    float acc[14][4];
    #pragma unroll
    for (int nf = 0; nf < 14; nf++)
        #pragma unroll
        for (int q = 0; q < 4; q++) acc[nf][q] = 0.f;

    // per-lane ldmatrix row addresses (buffer-relative)
    uint32_t sh0 = smem_u32(SH);
    int qsel = lane >> 3;
    int rrow = lane & 7;
    uint32_t lbase[7];
    #pragma unroll
    for (int np = 0; np < 7; np++) {
        int px = np*16 + (qsel >> 1)*8 + rrow;
        int pr = px / 56, pj = px % 56;
        lbase[np] = sh0 + ((pr*60 + pj)*24 + (qsel & 1)*8)*2;
    }

    const __half* aBase = g_wAh + (size_t)(ot*25)*16*2048 + wm*256 + lane*8;

    stage_cc(sh0, xnp, i0, 0, tid);
    CP_COMMIT();
    CP_WAIT0();
    __syncthreads();

    #pragma unroll 1
    for (int cc = 0; cc < 16; cc++) {
        int buf = cc & 1;
        uint32_t bo = (uint32_t)(buf * STAGE_BYTES);

        if (cc < 15) {
            stage_cc(sh0 + (buf ^ 1)*STAGE_BYTES, xnp, i0, cc + 1, tid);
            CP_COMMIT();
        }

        // A double-buffer over taps; B loaded fresh per tap
        uint32_t ahb[2][4];
        {
            uint4 av = *(const uint4*)(aBase + (size_t)cc*2048);
            ahb[0][0] = av.x; ahb[0][1] = av.y; ahb[0][2] = av.z; ahb[0][3] = av.w;
        }

        #pragma unroll
        for (int tap = 0; tap < 25; tap++) {
            int cur = tap & 1, nxt = cur ^ 1;
            if (tap < 24) {
                uint4 av = *(const uint4*)(aBase + (size_t)((tap + 1)*16 + cc)*2048);
                ahb[nxt][0] = av.x; ahb[nxt][1] = av.y;
                ahb[nxt][2] = av.z; ahb[nxt][3] = av.w;
            }
            int du = tap / 5, dv = tap % 5;
            uint32_t taddr = bo + (uint32_t)((du*60 + dv)*48);
            uint32_t bm[7][4];
            #pragma unroll
            for (int np = 0; np < 7; np++)
                LDSM_X4(bm[np][0], bm[np][1], bm[np][2], bm[np][3],
                        lbase[np] + taddr);
            #pragma unroll
            for (int np = 0; np < 7; np++) {
                MMA16816(acc[2*np    ], ahb[cur], bm[np][0], bm[np][1]);
                MMA16816(acc[2*np + 1], ahb[cur], bm[np][2], bm[np][3]);
            }
        }

        if (cc < 15) {
            CP_WAIT0();
            __syncthreads();
        }
    }

    // epilogue: +bias, write 2 rows x 56 px per o-row
    int r = lane >> 2, q = 2*(lane & 3);
    int o0 = ot*128 + wm*16 + r;
    float bb0 = b1[o0], bb1 = b1[o0 + 8];
    float* h0 = g_h + ((size_t)n*CC + o0)*HW;
    float* h1 = h0 + (size_t)8*HW;
    #pragma unroll
    for (int nf = 0; nf < 14; nf++) {
        int px = nf*8 + q;
        int pr = px / 56, col = px % 56;
        size_t off = (size_t)(i0 + pr)*WW + col;
        float2 v0 = make_float2(acc[nf][0] + bb0, acc[nf][1] + bb0);
        float2 v1 = make_float2(acc[nf][2] + bb1, acc[nf][3] + bb1);
        *(float2*)(h0 + off) = v0;
        *(float2*)(h1 + off) = v1;
    }
}

// ---------------- border correction via aggregated source weights ---------
__global__ void __launch_bounds__(256) corr_kernel() {
    __shared__ __align__(16) float xs[32][32];
    int o = threadIdx.x;
    int pi, pj; band_pos(blockIdx.x, pi, pj);
    int ci = pi < 2 ? pi : (pi > 53 ? pi - 51 : 2);
    int cj = pj < 2 ? pj : (pj > 53 ? pj - 51 : 2);
    int cls = ci*5 + cj;
    float acc[NN];
    #pragma unroll
    for (int n = 0; n < NN; n++) acc[n] = 0.f;

    for (int slot = 0; slot < 25; slot++) {
        int sc = cls*25 + slot;
        if (g_aggcnt[sc] == 0) continue;
        int si = pi + slot/5 - 2, sj = pj + slot%5 - 2;
        int rid = band_id(si, sj);
        const float* xbp = g_xb + (size_t)rid * CC * NN;
        const float* wp  = g_wagg + (size_t)sc * CC * CC + o;
        for (int cb = 0; cb < CC; cb += 32) {
            __syncthreads();
            for (int e = o; e < 32*NN; e += 256)
                xs[e / NN][e % NN] = xbp[(size_t)cb*NN + e];
            __syncthreads();
            #pragma unroll 1
            for (int c = 0; c < 32; c++) {
                float w = wp[(size_t)(cb + c) * CC];
                #pragma unroll
                for (int n4 = 0; n4 < 8; n4++) {
                    float4 v = *(const float4*)&xs[c][n4*4];
                    acc[n4*4+0] += w * v.x;
                    acc[n4*4+1] += w * v.y;
                    acc[n4*4+2] += w * v.z;
                    acc[n4*4+3] += w * v.w;
                }
            }
        }
    }
    size_t base = (size_t)o*HW + pi*WW + pj;
    #pragma unroll
    for (int n = 0; n < NN; n++)
        g_h[(size_t)n*CC*HW + base] += acc[n];
}

// ---------------- 1x1 conv ----------------
__global__ void __launch_bounds__(256) conv1x1_kernel(const float* __restrict__ w2,
                                                      const float* __restrict__ b2,
                                                      float* __restrict__ out) {
    __shared__ __align__(16) float hs[32][128];
    __shared__ __align__(16) float ws2[32][80];
    int tid = threadIdx.x;
    int n = blockIdx.y;
    int pbase = blockIdx.x * 128;
    int pxg = tid % 32, ocg = tid / 32;
    int px0 = pxg * 4, oc0 = ocg * 10;

    float acc[10][4];
    #pragma unroll
    for (int k = 0; k < 10; k++)
        #pragma unroll
        for (int j = 0; j < 4; j++) acc[k][j] = 0.f;

    for (int cb = 0; cb < CC; cb += 32) {
        for (int e = tid; e < 32*128; e += 256) {
            int c = e / 128, p = e % 128;
            int gp = pbase + p;
            hs[c][p] = (gp < HW) ? g_h[((size_t)n*CC + cb + c)*HW + gp] : 0.f;
        }
        for (int e = tid; e < 32*80; e += 256) {
            int c = e / 80, oc = e % 80;
            ws2[c][oc] = w2[(size_t)oc*CC + cb + c];
        }
        __syncthreads();
        #pragma unroll 1
        for (int c = 0; c < 32; c++) {
            float4 hv = *(const float4*)&hs[c][px0];
            #pragma unroll
            for (int k = 0; k < 10; k++) {
                float wv = ws2[c][oc0 + k];
                acc[k][0] += wv * hv.x;
                acc[k][1] += wv * hv.y;
                acc[k][2] += wv * hv.z;
                acc[k][3] += wv * hv.w;
            }
        }
        __syncthreads();
    }

    #pragma unroll
    for (int k = 0; k < 10; k++) {
        int oc = oc0 + k;
        float bb = b2[oc];
        #pragma unroll
        for (int j = 0; j < 4; j++) {
            int gp = pbase + px0 + j;
            if (gp < HW)
                out[((size_t)n*OC2 + oc)*HW + gp] = acc[k][j] + bb;
        }
    }
}

extern "C" void kernel_launch(void* const* d_in, const int* in_sizes, int n_in,
                              void* d_out, int out_size) {
    const float *x = nullptr, *w1 = nullptr, *b1 = nullptr, *w2 = nullptr, *b2 = nullptr;
    for (int i = 0; i < n_in; i++) {
        long s = in_sizes[i];
        const float* p = (const float*)d_in[i];
        if      (s == (long)NN*CC*HW)   x  = p;
        else if (s == (long)CC*9*CC*9)  w1 = p;
        else if (s == CC)               b1 = p;
        else if (s == (long)OC2*CC)     w2 = p;
        else if (s == OC2)              b2 = p;
    }
    float* out = (float*)d_out;

    fold_kernel<<<(CC*25*CC + 255)/256, 256>>>(w1);
    wprep_kernel<<<(800*2048 + 255)/256, 256>>>();
    xprep_kernel<<<dim3(98, 8, NN), 256>>>(x);
    aggtab_kernel<<<1, 640>>>();
    wagg_kernel<<<dim3(625, 256), 256>>>(w1);
    gather_kernel<<<(NBAND*CC*NN + 255)/256, 256>>>(x);
    conv5_mma_kernel<<<dim3(2, 28, NN), 256>>>(b1);
    corr_kernel<<<NBAND, 256>>>();
    conv1x1_kernel<<<dim3(25, NN), 256>>>(w2, b2, out);
}

// round 13
// speedup vs baseline: 6.8602x; 1.0196x over previous
#include <cuda_runtime.h>
#include <cuda_fp16.h>
#include <cstdint>
#include <cstddef>

#define NN 32
#define CC 256
#define HH 56
#define WW 56
#define HW (HH*WW)
#define OC2 80
#define NBAND 432
#define INV_SQRT2 0.7071067811865476f

__constant__ int c_di[8] = {1,-1,0,0,1,1,-1,-1};
__constant__ int c_dj[8] = {0,0,1,-1,1,-1,1,-1};

// Scratch (static device globals)
__device__ float g_weff[(size_t)CC*25*CC];        // [c][tap5x5][o]
__device__ float g_xb  [(size_t)NBAND*CC*NN];     // [band][c][n]
__device__ float g_h   [(size_t)NN*CC*HW];        // hidden activations
__device__ __half g_xh [(size_t)NN*HW*CC];        // x transposed: [n][px][c] fp16
__device__ __align__(16) __half g_wAh[(size_t)400*4096]; // A fragments packed
// Aggregated border-correction weights: [cls*25+slot][c][o]
__device__ float g_wagg[(size_t)625*CC*CC];
__device__ int   g_aggcnt[625];
__device__ int   g_aggcombo[625*20];
__device__ float g_aggcoef[625*20];

// ---------------- band helpers ----------------
__device__ __forceinline__ int band_id(int i, int j) {
    if (i < 2)   return i*WW + j;
    if (i >= 54) return 112 + (i-54)*WW + j;
    int k = (j < 2) ? j : (j - 52);
    return 224 + (i-2)*4 + k;
}
__device__ __forceinline__ void band_pos(int id, int& i, int& j) {
    if (id < 112)      { i = id/WW;           j = id%WW; }
    else if (id < 224) { int t = id-112; i = 54 + t/WW; j = t%WW; }
    else               { int t = id-224; i = 2 + t/4; int k = t%4; j = (k<2)?k:(52+k); }
}

__device__ __forceinline__ uint32_t smem_u32(const void* p) {
    uint32_t a;
    asm("{ .reg .u64 t; cvta.to.shared.u64 t, %1; cvt.u32.u64 %0, t; }" : "=r"(a) : "l"(p));
    return a;
}

// ---------------- fold 9-group 3x3 -> effective 5x5 ----------------
__global__ void fold_kernel(const float* __restrict__ w1) {
    int idx = blockIdx.x * blockDim.x + threadIdx.x;
    if (idx >= CC*25*CC) return;
    int o   = idx % CC;
    int tap = (idx / CC) % 25;
    int c   = idx / (CC*25);
    int du = tap/5 - 2, dv = tap%5 - 2;
    float t = 0.f;
    if (du >= -1 && du <= 1 && dv >= -1 && dv <= 1) {
        int a = du + 1, b = dv + 1;
        t += w1[(((size_t)o*2304 + c)*3 + a)*3 + b];
        #pragma unroll
        for (int g = 0; g < 8; g++) {
            float s = (g < 4) ? 1.f : INV_SQRT2;
            t += s * w1[(((size_t)o*2304 + (g+1)*CC + c)*3 + a)*3 + b];
        }
    }
    #pragma unroll
    for (int g = 0; g < 8; g++) {
        int a = du + c_di[g] + 1, b = dv + c_dj[g] + 1;
        if (a >= 0 && a < 3 && b >= 0 && b < 3) {
            float s = (g < 4) ? 1.f : INV_SQRT2;
            t -= s * w1[(((size_t)o*2304 + (g+1)*CC + c)*3 + a)*3 + b];
        }
    }
    g_weff[((size_t)c*25 + tap)*CC + o] = t;
}

// ---------------- border-correction aggregation table ----------------
__global__ void aggtab_kernel() {
    int sc = threadIdx.x;       // 0..624
    if (sc >= 625) return;
    int cls = sc / 25, slot = sc % 25;
    int ci = cls / 5, cj = cls % 5;
    int oi = slot/5 - 2, oj = slot%5 - 2;
    const int rep[5] = {0, 1, 28, 54, 55};
    int pi = rep[ci], pj = rep[cj];
    int cnt = 0;
    if (!(ci == 2 && cj == 2)) {
        for (int g = 0; g < 8; g++) {
            int di = c_di[g], dj = c_dj[g];
            for (int a = 0; a < 3; a++) {
                for (int b = 0; b < 3; b++) {
                    int qi = pi + a - 1, qj = pj + b - 1;
                    int ui = qi - di,    uj = qj - dj;
                    bool qin = ((unsigned)qi < HH) && ((unsigned)qj < WW);
                    bool uin = ((unsigned)ui < HH) && ((unsigned)uj < WW);
                    float sgn; int si, sj;
                    if (qin && !uin)      { sgn = -1.f; si = qi; sj = qj; }
                    else if (!qin && uin) { sgn =  1.f; si = ui; sj = uj; }
                    else continue;
                    if (si - pi == oi && sj - pj == oj && cnt < 20) {
                        g_aggcombo[sc*20 + cnt] = g*9 + a*3 + b;
                        g_aggcoef [sc*20 + cnt] = sgn * ((g < 4) ? 1.f : INV_SQRT2);
                        cnt++;
                    }
                }
            }
        }
    }
    g_aggcnt[sc] = cnt;
}

// ---------------- materialize aggregated weights ----------------
__global__ void wagg_kernel(const float* __restrict__ w1) {
    int sc = blockIdx.x;        // 0..624
    int c  = blockIdx.y;        // 0..255
    int o  = threadIdx.x;       // 0..255
    int cnt = g_aggcnt[sc];
    float t = 0.f;
    for (int k = 0; k < cnt; k++) {
        int combo = g_aggcombo[sc*20 + k];
        float cf  = g_aggcoef [sc*20 + k];
        int g = combo / 9, tap = combo % 9;
        t += cf * w1[((size_t)o*2304 + (g+1)*CC + c)*9 + tap];
    }
    g_wagg[((size_t)sc*CC + c)*CC + o] = t;
}

// ---------------- gather band x ----------------
__global__ void gather_kernel(const float* __restrict__ x) {
    size_t idx = (size_t)blockIdx.x * blockDim.x + threadIdx.x;
    if (idx >= (size_t)NBAND*CC*NN) return;
    int n   = idx % NN;
    int c   = (idx / NN) % CC;
    int rid = idx / (NN*CC);
    int i, j; band_pos(rid, i, j);
    g_xb[idx] = x[((size_t)n*CC + c)*HW + i*WW + j];
}

// ---------------- x transpose: [n][c][px] fp32 -> [n][px][c] fp16 ----------
__global__ void xprep_kernel(const float* __restrict__ x) {
    __shared__ float t[32][33];
    int n  = blockIdx.z;
    int cb = blockIdx.y * 32;
    int pb = blockIdx.x * 32;
    int tx = threadIdx.x & 31, ty = threadIdx.x >> 5;
    #pragma unroll
    for (int r = ty; r < 32; r += 8)
        t[r][tx] = x[((size_t)n*CC + cb + r)*HW + pb + tx];
    __syncthreads();
    #pragma unroll
    for (int r = ty; r < 32; r += 8)
        g_xh[((size_t)n*HW + pb + r)*CC + cb + tx] = __float2half_rn(t[tx][r]);
}

// ---------------- weight prep: Weff -> fp16 A fragments (4-mf warp tile) ---
// tile = tap*16+cc ; e = ((wm*4+mf)*32 + lane)*8 + h
//   o = wm*64 + mf*16 + (lane>>2) + (apair&1)*8
//   c = 2*(lane&3) + (apair>>1)*8 + half
__global__ void wprep_kernel() {
    int idx = blockIdx.x * blockDim.x + threadIdx.x;
    if (idx >= 400*4096) return;
    int e    = idx & 4095;
    int tile = idx >> 12;
    int h     = e & 7;
    int lane  = (e >> 3) & 31;
    int wmmf  = e >> 8;                  // 0..15 = wm*4+mf
    int wm = wmmf >> 2, mf = wmmf & 3;
    int apair = h >> 1, half = h & 1;
    int o = wm*64 + mf*16 + (lane >> 2) + (apair & 1)*8;
    int c = 2*(lane & 3) + (apair >> 1)*8 + half;
    int ccv = tile & 15;
    int tap = tile >> 4;                 // 0..24
    float v = g_weff[(((size_t)(ccv*16 + c))*25 + tap)*CC + o];
    g_wAh[idx] = __float2half_rn(v);
}

// ---------------- conv5: 4-mf warp tile mma.sync + cp.async staging --------
#define MMA16816(cacc, a, b0, b1) \
    asm volatile("mma.sync.aligned.m16n8k16.row.col.f32.f16.f16.f32 " \
        "{%0,%1,%2,%3}, {%4,%5,%6,%7}, {%8,%9}, {%0,%1,%2,%3};" \
        : "+f"((cacc)[0]),"+f"((cacc)[1]),"+f"((cacc)[2]),"+f"((cacc)[3]) \
        : "r"((a)[0]),"r"((a)[1]),"r"((a)[2]),"r"((a)[3]), "r"(b0),"r"(b1))

#define LDSM_X2(r0, r1, addr) \
    asm volatile("ldmatrix.sync.aligned.m8n8.x2.shared.b16 {%0,%1}, [%2];" \
        : "=r"(r0), "=r"(r1) : "r"(addr))

#define CP_ASYNC16(dst, src, sz) \
    asm volatile("cp.async.cg.shared.global [%0], [%1], 16, %2;" \
        :: "r"(dst), "l"(src), "r"(sz))
#define CP_COMMIT() asm volatile("cp.async.commit_group;" ::: "memory")
#define CP_WAIT0()  asm volatile("cp.async.wait_group 0;" ::: "memory")

#define STAGE_BYTES 17280   // 6*60*24 halfs * 2B

// stage 6 rows x 60 cols x 16 channels of one cc chunk
__device__ __forceinline__ void stage_cc(uint32_t shdst, const __half* __restrict__ xnp,
                                         int i0, int cc, int tid) {
    #pragma unroll
    for (int it = 0; it < 3; it++) {
        int e = tid + it*256;
        if (e < 720) {
            int chunk = e & 1, px = e >> 1;
            int col = px % 60, row = px / 60;
            int gi = i0 - 2 + row, gj = col - 2;
            bool inb = ((unsigned)gi < HH) && ((unsigned)gj < WW);
            const __half* src = inb
                ? xnp + ((size_t)gi*WW + gj)*CC + cc*16 + chunk*8
                : xnp;
            CP_ASYNC16(shdst + px*48 + chunk*16, src, inb ? 16 : 0);
        }
    }
}

__global__ void __launch_bounds__(256, 1) conv5_mma_kernel(const float* __restrict__ b1) {
    __shared__ __align__(16) __half SH[2*6*60*24];

    int tid  = threadIdx.x;
    int lane = tid & 31, wid = tid >> 5;
    int wm = wid & 3, wn = wid >> 2;      // 4m x 2n; warp tile 64 o x 56 px
    int i0 = blockIdx.x * 2;               // 2 output rows
    int n  = blockIdx.y;
    const __half* xnp = g_xh + (size_t)n * HW * CC;

    float acc[4][7][4];
    #pragma unroll
    for (int mf = 0; mf < 4; mf++)
        #pragma unroll
        for (int nf = 0; nf < 7; nf++)
            #pragma unroll
            for (int q = 0; q < 4; q++) acc[mf][nf][q] = 0.f;

    // per-lane ldmatrix row addresses (x2: lanes 0-7 -> k0 matrix, 8-15 -> k8)
    uint32_t sh0 = smem_u32(SH);
    int rrow = lane & 7;
    int khalf = (lane >> 3) & 1;
    uint32_t lbase[7];
    #pragma unroll
    for (int nf = 0; nf < 7; nf++)
        lbase[nf] = sh0 + ((wn*60 + nf*8 + rrow)*24 + khalf*8)*2;

    // per-thread A fragment base: + tile*4096 + mf*256
    const __half* aBase = g_wAh + wm*1024 + lane*8;

    stage_cc(sh0, xnp, i0, 0, tid);
    CP_COMMIT();
    CP_WAIT0();
    __syncthreads();

    #pragma unroll 1
    for (int cc = 0; cc < 16; cc++) {
        int buf = cc & 1;
        uint32_t bo = (uint32_t)(buf * STAGE_BYTES);

        if (cc < 15) {
            stage_cc(sh0 + (buf ^ 1)*STAGE_BYTES, xnp, i0, cc + 1, tid);
            CP_COMMIT();
        }

        // A register double-buffer over taps
        uint32_t ahb[2][4][4];
        {
            const __half* tH = aBase + (size_t)cc*4096;
            #pragma unroll
            for (int mf = 0; mf < 4; mf++) {
                uint4 av = *(const uint4*)(tH + mf*256);
                ahb[0][mf][0] = av.x; ahb[0][mf][1] = av.y;
                ahb[0][mf][2] = av.z; ahb[0][mf][3] = av.w;
            }
        }

        #pragma unroll
        for (int tap = 0; tap < 25; tap++) {
            int cur = tap & 1, nxt = cur ^ 1;
            if (tap < 24) {
                const __half* tH = aBase + (size_t)((tap + 1)*16 + cc)*4096;
                #pragma unroll
                for (int mf = 0; mf < 4; mf++) {
                    uint4 av = *(const uint4*)(tH + mf*256);
                    ahb[nxt][mf][0] = av.x; ahb[nxt][mf][1] = av.y;
                    ahb[nxt][mf][2] = av.z; ahb[nxt][mf][3] = av.w;
                }
            }
            int du = tap / 5, dv = tap % 5;
            uint32_t taddr = bo + (uint32_t)((du*60 + dv)*48);
            uint32_t bm[7][2];
            #pragma unroll
            for (int nf = 0; nf < 7; nf++)
                LDSM_X2(bm[nf][0], bm[nf][1], lbase[nf] + taddr);
            #pragma unroll
            for (int nf = 0; nf < 7; nf++) {
                #pragma unroll
                for (int mf = 0; mf < 4; mf++)
                    MMA16816(acc[mf][nf], ahb[cur][mf], bm[nf][0], bm[nf][1]);
            }
        }

        if (cc < 15) {
            CP_WAIT0();
            __syncthreads();
        }
    }

    // epilogue: +bias, write rows i0+wn
    int r = lane >> 2, q = 2*(lane & 3);
    #pragma unroll
    for (int mf = 0; mf < 4; mf++) {
        int o0 = wm*64 + mf*16 + r;
        float bb0 = b1[o0], bb1 = b1[o0 + 8];
        float* h0 = g_h + ((size_t)n*CC + o0)*HW + (size_t)(i0 + wn)*WW;
        float* h1 = h0 + (size_t)8*HW;
        #pragma unroll
        for (int nf = 0; nf < 7; nf++) {
            int col = nf*8 + q;
            float2 v0 = make_float2(acc[mf][nf][0] + bb0, acc[mf][nf][1] + bb0);
            float2 v1 = make_float2(acc[mf][nf][2] + bb1, acc[mf][nf][3] + bb1);
            *(float2*)(h0 + col) = v0;
            *(float2*)(h1 + col) = v1;
        }
    }
}

// ---------------- border correction via aggregated source weights ---------
__global__ void __launch_bounds__(256) corr_kernel() {
    __shared__ __align__(16) float xs[32][32];
    int o = threadIdx.x;
    int pi, pj; band_pos(blockIdx.x, pi, pj);
    int ci = pi < 2 ? pi : (pi > 53 ? pi - 51 : 2);
    int cj = pj < 2 ? pj : (pj > 53 ? pj - 51 : 2);
    int cls = ci*5 + cj;
    float acc[NN];
    #pragma unroll
    for (int n = 0; n < NN; n++) acc[n] = 0.f;

    for (int slot = 0; slot < 25; slot++) {
        int sc = cls*25 + slot;
        if (g_aggcnt[sc] == 0) continue;
        int si = pi + slot/5 - 2, sj = pj + slot%5 - 2;
        int rid = band_id(si, sj);
        const float* xbp = g_xb + (size_t)rid * CC * NN;
        const float* wp  = g_wagg + (size_t)sc * CC * CC + o;
        for (int cb = 0; cb < CC; cb += 32) {
            __syncthreads();
            for (int e = o; e < 32*NN; e += 256)
                xs[e / NN][e % NN] = xbp[(size_t)cb*NN + e];
            __syncthreads();
            #pragma unroll 1
            for (int c = 0; c < 32; c++) {
                float w = wp[(size_t)(cb + c) * CC];
                #pragma unroll
                for (int n4 = 0; n4 < 8; n4++) {
                    float4 v = *(const float4*)&xs[c][n4*4];
                    acc[n4*4+0] += w * v.x;
                    acc[n4*4+1] += w * v.y;
                    acc[n4*4+2] += w * v.z;
                    acc[n4*4+3] += w * v.w;
                }
            }
        }
    }
    size_t base = (size_t)o*HW + pi*WW + pj;
    #pragma unroll
    for (int n = 0; n < NN; n++)
        g_h[(size_t)n*CC*HW + base] += acc[n];
}

// ---------------- 1x1 conv ----------------
__global__ void __launch_bounds__(256) conv1x1_kernel(const float* __restrict__ w2,
                                                      const float* __restrict__ b2,
                                                      float* __restrict__ out) {
    __shared__ __align__(16) float hs[32][128];
    __shared__ __align__(16) float ws2[32][80];
    int tid = threadIdx.x;
    int n = blockIdx.y;
    int pbase = blockIdx.x * 128;
    int pxg = tid % 32, ocg = tid / 32;
    int px0 = pxg * 4, oc0 = ocg * 10;

    float acc[10][4];
    #pragma unroll
    for (int k = 0; k < 10; k++)
        #pragma unroll
        for (int j = 0; j < 4; j++) acc[k][j] = 0.f;

    for (int cb = 0; cb < CC; cb += 32) {
        for (int e = tid; e < 32*128; e += 256) {
            int c = e / 128, p = e % 128;
            int gp = pbase + p;
            hs[c][p] = (gp < HW) ? g_h[((size_t)n*CC + cb + c)*HW + gp] : 0.f;
        }
        for (int e = tid; e < 32*80; e += 256) {
            int c = e / 80, oc = e % 80;
            ws2[c][oc] = w2[(size_t)oc*CC + cb + c];
        }
        __syncthreads();
        #pragma unroll 1
        for (int c = 0; c < 32; c++) {
            float4 hv = *(const float4*)&hs[c][px0];
            #pragma unroll
            for (int k = 0; k < 10; k++) {
                float wv = ws2[c][oc0 + k];
                acc[k][0] += wv * hv.x;
                acc[k][1] += wv * hv.y;
                acc[k][2] += wv * hv.z;
                acc[k][3] += wv * hv.w;
            }
        }
        __syncthreads();
    }

    #pragma unroll
    for (int k = 0; k < 10; k++) {
        int oc = oc0 + k;
        float bb = b2[oc];
        #pragma unroll
        for (int j = 0; j < 4; j++) {
            int gp = pbase + px0 + j;
            if (gp < HW)
                out[((size_t)n*OC2 + oc)*HW + gp] = acc[k][j] + bb;
        }
    }
}

extern "C" void kernel_launch(void* const* d_in, const int* in_sizes, int n_in,
                              void* d_out, int out_size) {
    const float *x = nullptr, *w1 = nullptr, *b1 = nullptr, *w2 = nullptr, *b2 = nullptr;
    for (int i = 0; i < n_in; i++) {
        long s = in_sizes[i];
        const float* p = (const float*)d_in[i];
        if      (s == (long)NN*CC*HW)   x  = p;
        else if (s == (long)CC*9*CC*9)  w1 = p;
        else if (s == CC)               b1 = p;
        else if (s == (long)OC2*CC)     w2 = p;
        else if (s == OC2)              b2 = p;
    }
    float* out = (float*)d_out;

    fold_kernel<<<(CC*25*CC + 255)/256, 256>>>(w1);
    wprep_kernel<<<(400*4096 + 255)/256, 256>>>();
    xprep_kernel<<<dim3(98, 8, NN), 256>>>(x);
    aggtab_kernel<<<1, 640>>>();
    wagg_kernel<<<dim3(625, 256), 256>>>(w1);
    gather_kernel<<<(NBAND*CC*NN + 255)/256, 256>>>(x);
    conv5_mma_kernel<<<dim3(28, NN), 256>>>(b1);
    corr_kernel<<<NBAND, 256>>>();
    conv1x1_kernel<<<dim3(25, NN), 256>>>(w2, b2, out);
}

// round 14
// speedup vs baseline: 10.0369x; 1.4631x over previous
#include <cuda_runtime.h>
#include <cuda_fp16.h>
#include <cstdint>
#include <cstddef>

#define NN 32
#define CC 256
#define HH 56
#define WW 56
#define HW (HH*WW)
#define OC2 80
#define NBAND 432
#define INV_SQRT2 0.7071067811865476f

__constant__ int c_di[8] = {1,-1,0,0,1,1,-1,-1};
__constant__ int c_dj[8] = {0,0,1,-1,1,-1,1,-1};

// Scratch (static device globals)
__device__ float g_weff[(size_t)CC*25*CC];        // [c][tap5x5][o]
__device__ float g_h   [(size_t)NN*CC*HW];        // hidden activations
__device__ __half g_xh [(size_t)NN*HW*CC];        // x transposed: [n][px][c] fp16
__device__ __align__(16) __half g_wAh[(size_t)400*4096];   // conv5 A fragments
__device__ __align__(16) __half g_waggh[(size_t)625*65536]; // corr A fragments fp16
__device__ int   g_aggcnt[625];
__device__ int   g_aggcombo[625*20];
__device__ float g_aggcoef[625*20];

// ---------------- band helpers ----------------
__device__ __forceinline__ void band_pos(int id, int& i, int& j) {
    if (id < 112)      { i = id/WW;           j = id%WW; }
    else if (id < 224) { int t = id-112; i = 54 + t/WW; j = t%WW; }
    else               { int t = id-224; i = 2 + t/4; int k = t%4; j = (k<2)?k:(52+k); }
}

__device__ __forceinline__ uint32_t smem_u32(const void* p) {
    uint32_t a;
    asm("{ .reg .u64 t; cvta.to.shared.u64 t, %1; cvt.u32.u64 %0, t; }" : "=r"(a) : "l"(p));
    return a;
}

// ---------------- fold 9-group 3x3 -> effective 5x5 ----------------
__global__ void fold_kernel(const float* __restrict__ w1) {
    int idx = blockIdx.x * blockDim.x + threadIdx.x;
    if (idx >= CC*25*CC) return;
    int o   = idx % CC;
    int tap = (idx / CC) % 25;
    int c   = idx / (CC*25);
    int du = tap/5 - 2, dv = tap%5 - 2;
    float t = 0.f;
    if (du >= -1 && du <= 1 && dv >= -1 && dv <= 1) {
        int a = du + 1, b = dv + 1;
        t += w1[(((size_t)o*2304 + c)*3 + a)*3 + b];
        #pragma unroll
        for (int g = 0; g < 8; g++) {
            float s = (g < 4) ? 1.f : INV_SQRT2;
            t += s * w1[(((size_t)o*2304 + (g+1)*CC + c)*3 + a)*3 + b];
        }
    }
    #pragma unroll
    for (int g = 0; g < 8; g++) {
        int a = du + c_di[g] + 1, b = dv + c_dj[g] + 1;
        if (a >= 0 && a < 3 && b >= 0 && b < 3) {
            float s = (g < 4) ? 1.f : INV_SQRT2;
            t -= s * w1[(((size_t)o*2304 + (g+1)*CC + c)*3 + a)*3 + b];
        }
    }
    g_weff[((size_t)c*25 + tap)*CC + o] = t;
}

// ---------------- border-correction aggregation table ----------------
__global__ void aggtab_kernel() {
    int sc = threadIdx.x;       // 0..624
    if (sc >= 625) return;
    int cls = sc / 25, slot = sc % 25;
    int ci = cls / 5, cj = cls % 5;
    int oi = slot/5 - 2, oj = slot%5 - 2;
    const int rep[5] = {0, 1, 28, 54, 55};
    int pi = rep[ci], pj = rep[cj];
    int cnt = 0;
    if (!(ci == 2 && cj == 2)) {
        for (int g = 0; g < 8; g++) {
            int di = c_di[g], dj = c_dj[g];
            for (int a = 0; a < 3; a++) {
                for (int b = 0; b < 3; b++) {
                    int qi = pi + a - 1, qj = pj + b - 1;
                    int ui = qi - di,    uj = qj - dj;
                    bool qin = ((unsigned)qi < HH) && ((unsigned)qj < WW);
                    bool uin = ((unsigned)ui < HH) && ((unsigned)uj < WW);
                    float sgn; int si, sj;
                    if (qin && !uin)      { sgn = -1.f; si = qi; sj = qj; }
                    else if (!qin && uin) { sgn =  1.f; si = ui; sj = uj; }
                    else continue;
                    if (si - pi == oi && sj - pj == oj && cnt < 20) {
                        g_aggcombo[sc*20 + cnt] = g*9 + a*3 + b;
                        g_aggcoef [sc*20 + cnt] = sgn * ((g < 4) ? 1.f : INV_SQRT2);
                        cnt++;
                    }
                }
            }
        }
    }
    g_aggcnt[sc] = cnt;
}

// ---------------- materialize aggregated weights as fp16 MMA fragments ----
// per sc, per kchunk: 4096 halfs, e = (mf*32 + lane)*8 + h
//   o = mf*16 + (lane>>2) + (apair&1)*8 ; c = kc*16 + 2*(lane&3) + (apair>>1)*8 + half
__global__ void wagg_kernel(const float* __restrict__ w1) {
    int sc = blockIdx.x;        // 0..624
    int kc = blockIdx.y;        // 0..15
    int cnt = g_aggcnt[sc];
    if (cnt == 0) return;
    int tid = threadIdx.x;      // 0..255, 16 halfs each
    #pragma unroll 1
    for (int h16 = 0; h16 < 16; h16++) {
        int e = tid*16 + h16;
        int h    = e & 7;
        int lane = (e >> 3) & 31;
        int mf   = e >> 8;
        int apair = h >> 1, half = h & 1;
        int o = mf*16 + (lane >> 2) + (apair & 1)*8;
        int c = kc*16 + 2*(lane & 3) + (apair >> 1)*8 + half;
        float t = 0.f;
        for (int k = 0; k < cnt; k++) {
            int combo = g_aggcombo[sc*20 + k];
            float cf  = g_aggcoef [sc*20 + k];
            int g = combo / 9, tap = combo % 9;
            t += cf * w1[((size_t)o*2304 + (g+1)*CC + c)*9 + tap];
        }
        g_waggh[(size_t)sc*65536 + kc*4096 + e] = __float2half_rn(t);
    }
}

// ---------------- x transpose: [n][c][px] fp32 -> [n][px][c] fp16 ----------
__global__ void xprep_kernel(const float* __restrict__ x) {
    __shared__ float t[32][33];
    int n  = blockIdx.z;
    int cb = blockIdx.y * 32;
    int pb = blockIdx.x * 32;
    int tx = threadIdx.x & 31, ty = threadIdx.x >> 5;
    #pragma unroll
    for (int r = ty; r < 32; r += 8)
        t[r][tx] = x[((size_t)n*CC + cb + r)*HW + pb + tx];
    __syncthreads();
    #pragma unroll
    for (int r = ty; r < 32; r += 8)
        g_xh[((size_t)n*HW + pb + r)*CC + cb + tx] = __float2half_rn(t[tx][r]);
}

// ---------------- weight prep: Weff -> fp16 A fragments (4-mf warp tile) ---
__global__ void wprep_kernel() {
    int idx = blockIdx.x * blockDim.x + threadIdx.x;
    if (idx >= 400*4096) return;
    int e    = idx & 4095;
    int tile = idx >> 12;
    int h     = e & 7;
    int lane  = (e >> 3) & 31;
    int wmmf  = e >> 8;
    int wm = wmmf >> 2, mf = wmmf & 3;
    int apair = h >> 1, half = h & 1;
    int o = wm*64 + mf*16 + (lane >> 2) + (apair & 1)*8;
    int c = 2*(lane & 3) + (apair >> 1)*8 + half;
    int ccv = tile & 15;
    int tap = tile >> 4;
    float v = g_weff[(((size_t)(ccv*16 + c))*25 + tap)*CC + o];
    g_wAh[idx] = __float2half_rn(v);
}

// ---------------- shared MMA macros ----------------
#define MMA16816(cacc, a, b0, b1) \
    asm volatile("mma.sync.aligned.m16n8k16.row.col.f32.f16.f16.f32 " \
        "{%0,%1,%2,%3}, {%4,%5,%6,%7}, {%8,%9}, {%0,%1,%2,%3};" \
        : "+f"((cacc)[0]),"+f"((cacc)[1]),"+f"((cacc)[2]),"+f"((cacc)[3]) \
        : "r"((a)[0]),"r"((a)[1]),"r"((a)[2]),"r"((a)[3]), "r"(b0),"r"(b1))

#define LDSM_X2(r0, r1, addr) \
    asm volatile("ldmatrix.sync.aligned.m8n8.x2.shared.b16 {%0,%1}, [%2];" \
        : "=r"(r0), "=r"(r1) : "r"(addr))

#define LDSM_X4(r0, r1, r2, r3, addr) \
    asm volatile("ldmatrix.sync.aligned.m8n8.x4.shared.b16 {%0,%1,%2,%3}, [%4];" \
        : "=r"(r0), "=r"(r1), "=r"(r2), "=r"(r3) : "r"(addr))

#define CP_ASYNC16(dst, src, sz) \
    asm volatile("cp.async.cg.shared.global [%0], [%1], 16, %2;" \
        :: "r"(dst), "l"(src), "r"(sz))
#define CP_COMMIT() asm volatile("cp.async.commit_group;" ::: "memory")
#define CP_WAIT0()  asm volatile("cp.async.wait_group 0;" ::: "memory")

#define STAGE_BYTES 17280   // 6*60*24 halfs * 2B

// ---------------- conv5: 4-mf warp tile mma.sync + cp.async staging --------
__device__ __forceinline__ void stage_cc(uint32_t shdst, const __half* __restrict__ xnp,
                                         int i0, int cc, int tid) {
    #pragma unroll
    for (int it = 0; it < 3; it++) {
        int e = tid + it*256;
        if (e < 720) {
            int chunk = e & 1, px = e >> 1;
            int col = px % 60, row = px / 60;
            int gi = i0 - 2 + row, gj = col - 2;
            bool inb = ((unsigned)gi < HH) && ((unsigned)gj < WW);
            const __half* src = inb
                ? xnp + ((size_t)gi*WW + gj)*CC + cc*16 + chunk*8
                : xnp;
            CP_ASYNC16(shdst + px*48 + chunk*16, src, inb ? 16 : 0);
        }
    }
}

__global__ void __launch_bounds__(256, 1) conv5_mma_kernel(const float* __restrict__ b1) {
    __shared__ __align__(16) __half SH[2*6*60*24];

    int tid  = threadIdx.x;
    int lane = tid & 31, wid = tid >> 5;
    int wm = wid & 3, wn = wid >> 2;
    int i0 = blockIdx.x * 2;
    int n  = blockIdx.y;
    const __half* xnp = g_xh + (size_t)n * HW * CC;

    float acc[4][7][4];
    #pragma unroll
    for (int mf = 0; mf < 4; mf++)
        #pragma unroll
        for (int nf = 0; nf < 7; nf++)
            #pragma unroll
            for (int q = 0; q < 4; q++) acc[mf][nf][q] = 0.f;

    uint32_t sh0 = smem_u32(SH);
    int rrow = lane & 7;
    int khalf = (lane >> 3) & 1;
    uint32_t lbase[7];
    #pragma unroll
    for (int nf = 0; nf < 7; nf++)
        lbase[nf] = sh0 + ((wn*60 + nf*8 + rrow)*24 + khalf*8)*2;

    const __half* aBase = g_wAh + wm*1024 + lane*8;

    stage_cc(sh0, xnp, i0, 0, tid);
    CP_COMMIT();
    CP_WAIT0();
    __syncthreads();

    #pragma unroll 1
    for (int cc = 0; cc < 16; cc++) {
        int buf = cc & 1;
        uint32_t bo = (uint32_t)(buf * STAGE_BYTES);

        if (cc < 15) {
            stage_cc(sh0 + (buf ^ 1)*STAGE_BYTES, xnp, i0, cc + 1, tid);
            CP_COMMIT();
        }

        uint32_t ahb[2][4][4];
        {
            const __half* tH = aBase + (size_t)cc*4096;
            #pragma unroll
            for (int mf = 0; mf < 4; mf++) {
                uint4 av = *(const uint4*)(tH + mf*256);
                ahb[0][mf][0] = av.x; ahb[0][mf][1] = av.y;
                ahb[0][mf][2] = av.z; ahb[0][mf][3] = av.w;
            }
        }

        #pragma unroll
        for (int tap = 0; tap < 25; tap++) {
            int cur = tap & 1, nxt = cur ^ 1;
            if (tap < 24) {
                const __half* tH = aBase + (size_t)((tap + 1)*16 + cc)*4096;
                #pragma unroll
                for (int mf = 0; mf < 4; mf++) {
                    uint4 av = *(const uint4*)(tH + mf*256);
                    ahb[nxt][mf][0] = av.x; ahb[nxt][mf][1] = av.y;
                    ahb[nxt][mf][2] = av.z; ahb[nxt][mf][3] = av.w;
                }
            }
            int du = tap / 5, dv = tap % 5;
            uint32_t taddr = bo + (uint32_t)((du*60 + dv)*48);
            uint32_t bm[7][2];
            #pragma unroll
            for (int nf = 0; nf < 7; nf++)
                LDSM_X2(bm[nf][0], bm[nf][1], lbase[nf] + taddr);
            #pragma unroll
            for (int nf = 0; nf < 7; nf++) {
                #pragma unroll
                for (int mf = 0; mf < 4; mf++)
                    MMA16816(acc[mf][nf], ahb[cur][mf], bm[nf][0], bm[nf][1]);
            }
        }

        if (cc < 15) {
            CP_WAIT0();
            __syncthreads();
        }
    }

    int r = lane >> 2, q = 2*(lane & 3);
    #pragma unroll
    for (int mf = 0; mf < 4; mf++) {
        int o0 = wm*64 + mf*16 + r;
        float bb0 = b1[o0], bb1 = b1[o0 + 8];
        float* h0 = g_h + ((size_t)n*CC + o0)*HW + (size_t)(i0 + wn)*WW;
        float* h1 = h0 + (size_t)8*HW;
        #pragma unroll
        for (int nf = 0; nf < 7; nf++) {
            int col = nf*8 + q;
            float2 v0 = make_float2(acc[mf][nf][0] + bb0, acc[mf][nf][1] + bb0);
            float2 v1 = make_float2(acc[mf][nf][2] + bb1, acc[mf][nf][3] + bb1);
            *(float2*)(h0 + col) = v0;
            *(float2*)(h1 + col) = v1;
        }
    }
}

// ---------------- border correction via HMMA (block = band pixel) ---------
__global__ void __launch_bounds__(256) corr_kernel() {
    __shared__ __align__(16) __half xs[32*264];   // [n][264 halfs], stride 528B
    int tid  = threadIdx.x;
    int lane = tid & 31, w = tid >> 5;            // 8 warps; warp = mf pair {2w,2w+1}
    int pi, pj; band_pos(blockIdx.x, pi, pj);
    int ci = pi < 2 ? pi : (pi > 53 ? pi - 51 : 2);
    int cj = pj < 2 ? pj : (pj > 53 ? pj - 51 : 2);
    int cls = ci*5 + cj;

    float acc[2][4][4];
    #pragma unroll
    for (int m = 0; m < 2; m++)
        #pragma unroll
        for (int nf = 0; nf < 4; nf++)
            #pragma unroll
            for (int q = 0; q < 4; q++) acc[m][nf][q] = 0.f;

    uint32_t sh0 = smem_u32(xs);
    int nfsel = (lane >> 4) & 1;
    int khalf = (lane >> 3) & 1;
    int row   = lane & 7;

    #pragma unroll 1
    for (int slot = 0; slot < 25; slot++) {
        int sc = cls*25 + slot;
        if (g_aggcnt[sc] == 0) continue;
        int si = pi + slot/5 - 2, sj = pj + slot%5 - 2;
        const __half* xsrc = g_xh + ((size_t)si*WW + sj)*CC;

        __syncthreads();
        #pragma unroll
        for (int it = 0; it < 4; it++) {
            int e = tid + it*256;
            int nn = e >> 5, ch = e & 31;
            uint4 v = *(const uint4*)(xsrc + (size_t)nn*HW*CC + ch*8);
            *(uint4*)(xs + nn*264 + ch*8) = v;
        }
        __syncthreads();

        const __half* aT = g_waggh + (size_t)sc*65536 + (2*w)*256 + lane*8;
        #pragma unroll 1
        for (int kc = 0; kc < 16; kc++) {
            uint4 a0v = *(const uint4*)(aT + kc*4096);
            uint4 a1v = *(const uint4*)(aT + kc*4096 + 256);
            uint32_t a0[4] = {a0v.x, a0v.y, a0v.z, a0v.w};
            uint32_t a1[4] = {a1v.x, a1v.y, a1v.z, a1v.w};
            uint32_t b[4][2];
            #pragma unroll
            for (int nfp = 0; nfp < 2; nfp++) {
                int nrow = (nfp*2 + nfsel)*8 + row;
                uint32_t addr = sh0 + (uint32_t)((nrow*264 + kc*16 + khalf*8)*2);
                uint32_t r0, r1, r2, r3;
                LDSM_X4(r0, r1, r2, r3, addr);
                b[nfp*2    ][0] = r0; b[nfp*2    ][1] = r1;
                b[nfp*2 + 1][0] = r2; b[nfp*2 + 1][1] = r3;
            }
            #pragma unroll
            for (int nf = 0; nf < 4; nf++) {
                MMA16816(acc[0][nf], a0, b[nf][0], b[nf][1]);
                MMA16816(acc[1][nf], a1, b[nf][0], b[nf][1]);
            }
        }
    }

    // epilogue: RMW into g_h
    int r = lane >> 2, q2 = 2*(lane & 3);
    size_t pix = (size_t)pi*WW + pj;
    #pragma unroll
    for (int m = 0; m < 2; m++) {
        int o0 = w*32 + m*16 + r;
        #pragma unroll
        for (int nf = 0; nf < 4; nf++) {
            int n0 = nf*8 + q2;
            g_h[((size_t)n0*CC + o0)*HW + pix]         += acc[m][nf][0];
            g_h[((size_t)(n0+1)*CC + o0)*HW + pix]     += acc[m][nf][1];
            g_h[((size_t)n0*CC + o0 + 8)*HW + pix]     += acc[m][nf][2];
            g_h[((size_t)(n0+1)*CC + o0 + 8)*HW + pix] += acc[m][nf][3];
        }
    }
}

// ---------------- 1x1 conv ----------------
__global__ void __launch_bounds__(256) conv1x1_kernel(const float* __restrict__ w2,
                                                      const float* __restrict__ b2,
                                                      float* __restrict__ out) {
    __shared__ __align__(16) float hs[32][128];
    __shared__ __align__(16) float ws2[32][80];
    int tid = threadIdx.x;
    int n = blockIdx.y;
    int pbase = blockIdx.x * 128;
    int pxg = tid % 32, ocg = tid / 32;
    int px0 = pxg * 4, oc0 = ocg * 10;

    float acc[10][4];
    #pragma unroll
    for (int k = 0; k < 10; k++)
        #pragma unroll
        for (int j = 0; j < 4; j++) acc[k][j] = 0.f;

    for (int cb = 0; cb < CC; cb += 32) {
        for (int e = tid; e < 32*128; e += 256) {
            int c = e / 128, p = e % 128;
            int gp = pbase + p;
            hs[c][p] = (gp < HW) ? g_h[((size_t)n*CC + cb + c)*HW + gp] : 0.f;
        }
        for (int e = tid; e < 32*80; e += 256) {
            int c = e / 80, oc = e % 80;
            ws2[c][oc] = w2[(size_t)oc*CC + cb + c];
        }
        __syncthreads();
        #pragma unroll 1
        for (int c = 0; c < 32; c++) {
            float4 hv = *(const float4*)&hs[c][px0];
            #pragma unroll
            for (int k = 0; k < 10; k++) {
                float wv = ws2[c][oc0 + k];
                acc[k][0] += wv * hv.x;
                acc[k][1] += wv * hv.y;
                acc[k][2] += wv * hv.z;
                acc[k][3] += wv * hv.w;
            }
        }
        __syncthreads();
    }

    #pragma unroll
    for (int k = 0; k < 10; k++) {
        int oc = oc0 + k;
        float bb = b2[oc];
        #pragma unroll
        for (int j = 0; j < 4; j++) {
            int gp = pbase + px0 + j;
            if (gp < HW)
                out[((size_t)n*OC2 + oc)*HW + gp] = acc[k][j] + bb;
        }
    }
}

extern "C" void kernel_launch(void* const* d_in, const int* in_sizes, int n_in,
                              void* d_out, int out_size) {
    const float *x = nullptr, *w1 = nullptr, *b1 = nullptr, *w2 = nullptr, *b2 = nullptr;
    for (int i = 0; i < n_in; i++) {
        long s = in_sizes[i];
        const float* p = (const float*)d_in[i];
        if      (s == (long)NN*CC*HW)   x  = p;
        else if (s == (long)CC*9*CC*9)  w1 = p;
        else if (s == CC)               b1 = p;
        else if (s == (long)OC2*CC)     w2 = p;
        else if (s == OC2)              b2 = p;
    }
    float* out = (float*)d_out;

    fold_kernel<<<(CC*25*CC + 255)/256, 256>>>(w1);
    wprep_kernel<<<(400*4096 + 255)/256, 256>>>();
    xprep_kernel<<<dim3(98, 8, NN), 256>>>(x);
    aggtab_kernel<<<1, 640>>>();
    wagg_kernel<<<dim3(625, 16), 256>>>(w1);
    conv5_mma_kernel<<<dim3(28, NN), 256>>>(b1);
    corr_kernel<<<NBAND, 256>>>();
    conv1x1_kernel<<<dim3(25, NN), 256>>>(w2, b2, out);
}

// round 15
// speedup vs baseline: 11.6312x; 1.1588x over previous
#include <cuda_runtime.h>
#include <cuda_fp16.h>
#include <cstdint>
#include <cstddef>

#define NN 32
#define CC 256
#define HH 56
#define WW 56
#define HW (HH*WW)
#define OC2 80
#define NBAND 432
#define INV_SQRT2 0.7071067811865476f

__constant__ int c_di[8] = {1,-1,0,0,1,1,-1,-1};
__constant__ int c_dj[8] = {0,0,1,-1,1,-1,1,-1};

// Scratch (static device globals)
__device__ float g_weff[(size_t)CC*25*CC];        // [c][tap5x5][o]
__device__ __half g_xh [(size_t)NN*HW*CC];        // x transposed: [n][px][c] fp16
__device__ __align__(16) __half g_wAh[(size_t)400*4096];    // conv5 A fragments
__device__ __align__(16) __half g_waggh[(size_t)625*65536]; // corr A fragments fp16
__device__ __align__(16) __half g_w2h[(size_t)16*2048];     // W2 fragments [kc][mf(8)*256]
__device__ float g_b2eff[OC2];
__device__ int   g_aggcnt[625];
__device__ int   g_aggcombo[625*20];
__device__ float g_aggcoef[625*20];

// ---------------- band helpers ----------------
__device__ __forceinline__ void band_pos(int id, int& i, int& j) {
    if (id < 112)      { i = id/WW;           j = id%WW; }
    else if (id < 224) { int t = id-112; i = 54 + t/WW; j = t%WW; }
    else               { int t = id-224; i = 2 + t/4; int k = t%4; j = (k<2)?k:(52+k); }
}

__device__ __forceinline__ uint32_t smem_u32(const void* p) {
    uint32_t a;
    asm("{ .reg .u64 t; cvta.to.shared.u64 t, %1; cvt.u32.u64 %0, t; }" : "=r"(a) : "l"(p));
    return a;
}

// ---------------- fold 9-group 3x3 -> effective 5x5 ----------------
__global__ void fold_kernel(const float* __restrict__ w1) {
    int idx = blockIdx.x * blockDim.x + threadIdx.x;
    if (idx >= CC*25*CC) return;
    int o   = idx % CC;
    int tap = (idx / CC) % 25;
    int c   = idx / (CC*25);
    int du = tap/5 - 2, dv = tap%5 - 2;
    float t = 0.f;
    if (du >= -1 && du <= 1 && dv >= -1 && dv <= 1) {
        int a = du + 1, b = dv + 1;
        t += w1[(((size_t)o*2304 + c)*3 + a)*3 + b];
        #pragma unroll
        for (int g = 0; g < 8; g++) {
            float s = (g < 4) ? 1.f : INV_SQRT2;
            t += s * w1[(((size_t)o*2304 + (g+1)*CC + c)*3 + a)*3 + b];
        }
    }
    #pragma unroll
    for (int g = 0; g < 8; g++) {
        int a = du + c_di[g] + 1, b = dv + c_dj[g] + 1;
        if (a >= 0 && a < 3 && b >= 0 && b < 3) {
            float s = (g < 4) ? 1.f : INV_SQRT2;
            t -= s * w1[(((size_t)o*2304 + (g+1)*CC + c)*3 + a)*3 + b];
        }
    }
    g_weff[((size_t)c*25 + tap)*CC + o] = t;
}

// ---------------- border-correction aggregation table ----------------
__global__ void aggtab_kernel() {
    int sc = threadIdx.x;
    if (sc >= 625) return;
    int cls = sc / 25, slot = sc % 25;
    int ci = cls / 5, cj = cls % 5;
    int oi = slot/5 - 2, oj = slot%5 - 2;
    const int rep[5] = {0, 1, 28, 54, 55};
    int pi = rep[ci], pj = rep[cj];
    int cnt = 0;
    if (!(ci == 2 && cj == 2)) {
        for (int g = 0; g < 8; g++) {
            int di = c_di[g], dj = c_dj[g];
            for (int a = 0; a < 3; a++) {
                for (int b = 0; b < 3; b++) {
                    int qi = pi + a - 1, qj = pj + b - 1;
                    int ui = qi - di,    uj = qj - dj;
                    bool qin = ((unsigned)qi < HH) && ((unsigned)qj < WW);
                    bool uin = ((unsigned)ui < HH) && ((unsigned)uj < WW);
                    float sgn; int si, sj;
                    if (qin && !uin)      { sgn = -1.f; si = qi; sj = qj; }
                    else if (!qin && uin) { sgn =  1.f; si = ui; sj = uj; }
                    else continue;
                    if (si - pi == oi && sj - pj == oj && cnt < 20) {
                        g_aggcombo[sc*20 + cnt] = g*9 + a*3 + b;
                        g_aggcoef [sc*20 + cnt] = sgn * ((g < 4) ? 1.f : INV_SQRT2);
                        cnt++;
                    }
                }
            }
        }
    }
    g_aggcnt[sc] = cnt;
}

// ---------------- materialize aggregated weights as fp16 MMA fragments ----
__global__ void wagg_kernel(const float* __restrict__ w1) {
    int sc = blockIdx.x;
    int kc = blockIdx.y;
    int cnt = g_aggcnt[sc];
    if (cnt == 0) return;
    int tid = threadIdx.x;
    #pragma unroll 1
    for (int h16 = 0; h16 < 16; h16++) {
        int e = tid*16 + h16;
        int h    = e & 7;
        int lane = (e >> 3) & 31;
        int mf   = e >> 8;
        int apair = h >> 1, half = h & 1;
        int o = mf*16 + (lane >> 2) + (apair & 1)*8;
        int c = kc*16 + 2*(lane & 3) + (apair >> 1)*8 + half;
        float t = 0.f;
        for (int k = 0; k < cnt; k++) {
            int combo = g_aggcombo[sc*20 + k];
            float cf  = g_aggcoef [sc*20 + k];
            int g = combo / 9, tap = combo % 9;
            t += cf * w1[((size_t)o*2304 + (g+1)*CC + c)*9 + tap];
        }
        g_waggh[(size_t)sc*65536 + kc*4096 + e] = __float2half_rn(t);
    }
}

// ---------------- W2 -> fp16 fragments: [kc][mf(8 slots, 5 used)*256] ------
// e within kc-tile: mf = e>>8 (0..7), lane = (e>>3)&31, h = e&7
//   m row (oc2) = mf*16 + (lane>>2) + (apair&1)*8 ; k (o_hidden) = kc*16 + 2*(lane&3)+(apair>>1)*8+half
__global__ void w2prep_kernel(const float* __restrict__ w2) {
    int idx = blockIdx.x * blockDim.x + threadIdx.x;
    if (idx >= 16*2048) return;
    int e  = idx & 2047;
    int kc = idx >> 11;
    int h    = e & 7;
    int lane = (e >> 3) & 31;
    int mf   = e >> 8;
    int apair = h >> 1, half = h & 1;
    int oc2 = mf*16 + (lane >> 2) + (apair & 1)*8;
    int ko  = kc*16 + 2*(lane & 3) + (apair >> 1)*8 + half;
    float v = (mf < 5) ? w2[(size_t)oc2*CC + ko] : 0.f;
    g_w2h[idx] = __float2half_rn(v);
}

// ---------------- b2eff = b2 + W2 . b1 ----------------
__global__ void b2eff_kernel(const float* __restrict__ w2, const float* __restrict__ b1,
                             const float* __restrict__ b2) {
    int oc = threadIdx.x;
    if (oc >= OC2) return;
    float t = b2[oc];
    for (int o = 0; o < CC; o++) t += w2[(size_t)oc*CC + o] * b1[o];
    g_b2eff[oc] = t;
}

// ---------------- x transpose: [n][c][px] fp32 -> [n][px][c] fp16 ----------
__global__ void xprep_kernel(const float* __restrict__ x) {
    __shared__ float t[32][33];
    int n  = blockIdx.z;
    int cb = blockIdx.y * 32;
    int pb = blockIdx.x * 32;
    int tx = threadIdx.x & 31, ty = threadIdx.x >> 5;
    #pragma unroll
    for (int r = ty; r < 32; r += 8)
        t[r][tx] = x[((size_t)n*CC + cb + r)*HW + pb + tx];
    __syncthreads();
    #pragma unroll
    for (int r = ty; r < 32; r += 8)
        g_xh[((size_t)n*HW + pb + r)*CC + cb + tx] = __float2half_rn(t[tx][r]);
}

// ---------------- weight prep: Weff -> fp16 A fragments (4-mf warp tile) ---
__global__ void wprep_kernel() {
    int idx = blockIdx.x * blockDim.x + threadIdx.x;
    if (idx >= 400*4096) return;
    int e    = idx & 4095;
    int tile = idx >> 12;
    int h     = e & 7;
    int lane  = (e >> 3) & 31;
    int wmmf  = e >> 8;
    int wm = wmmf >> 2, mf = wmmf & 3;
    int apair = h >> 1, half = h & 1;
    int o = wm*64 + mf*16 + (lane >> 2) + (apair & 1)*8;
    int c = 2*(lane & 3) + (apair >> 1)*8 + half;
    int ccv = tile & 15;
    int tap = tile >> 4;
    float v = g_weff[(((size_t)(ccv*16 + c))*25 + tap)*CC + o];
    g_wAh[idx] = __float2half_rn(v);
}

// ---------------- shared MMA macros ----------------
#define MMA16816(cacc, a, b0, b1) \
    asm volatile("mma.sync.aligned.m16n8k16.row.col.f32.f16.f16.f32 " \
        "{%0,%1,%2,%3}, {%4,%5,%6,%7}, {%8,%9}, {%0,%1,%2,%3};" \
        : "+f"((cacc)[0]),"+f"((cacc)[1]),"+f"((cacc)[2]),"+f"((cacc)[3]) \
        : "r"((a)[0]),"r"((a)[1]),"r"((a)[2]),"r"((a)[3]), "r"(b0),"r"(b1))

#define LDSM_X2(r0, r1, addr) \
    asm volatile("ldmatrix.sync.aligned.m8n8.x2.shared.b16 {%0,%1}, [%2];" \
        : "=r"(r0), "=r"(r1) : "r"(addr))

#define LDSM_X4(r0, r1, r2, r3, addr) \
    asm volatile("ldmatrix.sync.aligned.m8n8.x4.shared.b16 {%0,%1,%2,%3}, [%4];" \
        : "=r"(r0), "=r"(r1), "=r"(r2), "=r"(r3) : "r"(addr))

#define CP_ASYNC16(dst, src, sz) \
    asm volatile("cp.async.cg.shared.global [%0], [%1], 16, %2;" \
        :: "r"(dst), "l"(src), "r"(sz))
#define CP_COMMIT() asm volatile("cp.async.commit_group;" ::: "memory")
#define CP_WAIT0()  asm volatile("cp.async.wait_group 0;" ::: "memory")

#define STAGE_BYTES 17280           // 6*60*24 halfs * 2B
#define HS_OFF      (2*STAGE_BYTES) // h-tile offset in dynamic smem
#define HS_STRIDE   264             // halfs per px row
#define CONV5_SMEM  (HS_OFF + 112*HS_STRIDE*2)

// ---------------- conv5 fused with 1x1: mma.sync + cp.async ---------------
__device__ __forceinline__ void stage_cc(uint32_t shdst, const __half* __restrict__ xnp,
                                         int i0, int cc, int tid) {
    #pragma unroll
    for (int it = 0; it < 3; it++) {
        int e = tid + it*256;
        if (e < 720) {
            int chunk = e & 1, px = e >> 1;
            int col = px % 60, row = px / 60;
            int gi = i0 - 2 + row, gj = col - 2;
            bool inb = ((unsigned)gi < HH) && ((unsigned)gj < WW);
            const __half* src = inb
                ? xnp + ((size_t)gi*WW + gj)*CC + cc*16 + chunk*8
                : xnp;
            CP_ASYNC16(shdst + px*48 + chunk*16, src, inb ? 16 : 0);
        }
    }
}

__global__ void __launch_bounds__(256, 1) conv5_mma_kernel(float* __restrict__ out) {
    extern __shared__ __align__(16) char dsm[];
    __half* SH = (__half*)dsm;
    __half* hS = (__half*)(dsm + HS_OFF);

    int tid  = threadIdx.x;
    int lane = tid & 31, wid = tid >> 5;
    int wm = wid & 3, wn = wid >> 2;
    int i0 = blockIdx.x * 2;
    int n  = blockIdx.y;
    const __half* xnp = g_xh + (size_t)n * HW * CC;

    float acc[4][7][4];
    #pragma unroll
    for (int mf = 0; mf < 4; mf++)
        #pragma unroll
        for (int nf = 0; nf < 7; nf++)
            #pragma unroll
            for (int q = 0; q < 4; q++) acc[mf][nf][q] = 0.f;

    uint32_t sh0 = smem_u32(SH);
    int rrow = lane & 7;
    int khalf = (lane >> 3) & 1;
    uint32_t lbase[7];
    #pragma unroll
    for (int nf = 0; nf < 7; nf++)
        lbase[nf] = sh0 + ((wn*60 + nf*8 + rrow)*24 + khalf*8)*2;

    const __half* aBase = g_wAh + wm*1024 + lane*8;

    stage_cc(sh0, xnp, i0, 0, tid);
    CP_COMMIT();
    CP_WAIT0();
    __syncthreads();

    #pragma unroll 1
    for (int cc = 0; cc < 16; cc++) {
        int buf = cc & 1;
        uint32_t bo = (uint32_t)(buf * STAGE_BYTES);

        if (cc < 15) {
            stage_cc(sh0 + (buf ^ 1)*STAGE_BYTES, xnp, i0, cc + 1, tid);
            CP_COMMIT();
        }

        uint32_t ahb[2][4][4];
        {
            const __half* tH = aBase + (size_t)cc*4096;
            #pragma unroll
            for (int mf = 0; mf < 4; mf++) {
                uint4 av = *(const uint4*)(tH + mf*256);
                ahb[0][mf][0] = av.x; ahb[0][mf][1] = av.y;
                ahb[0][mf][2] = av.z; ahb[0][mf][3] = av.w;
            }
        }

        #pragma unroll
        for (int tap = 0; tap < 25; tap++) {
            int cur = tap & 1, nxt = cur ^ 1;
            if (tap < 24) {
                const __half* tH = aBase + (size_t)((tap + 1)*16 + cc)*4096;
                #pragma unroll
                for (int mf = 0; mf < 4; mf++) {
                    uint4 av = *(const uint4*)(tH + mf*256);
                    ahb[nxt][mf][0] = av.x; ahb[nxt][mf][1] = av.y;
                    ahb[nxt][mf][2] = av.z; ahb[nxt][mf][3] = av.w;
                }
            }
            int du = tap / 5, dv = tap % 5;
            uint32_t taddr = bo + (uint32_t)((du*60 + dv)*48);
            uint32_t bm[7][2];
            #pragma unroll
            for (int nf = 0; nf < 7; nf++)
                LDSM_X2(bm[nf][0], bm[nf][1], lbase[nf] + taddr);
            #pragma unroll
            for (int nf = 0; nf < 7; nf++) {
                #pragma unroll
                for (int mf = 0; mf < 4; mf++)
                    MMA16816(acc[mf][nf], ahb[cur][mf], bm[nf][0], bm[nf][1]);
            }
        }

        if (cc < 15) {
            CP_WAIT0();
            __syncthreads();
        }
    }

    // ---- spill h-tile to SMEM as fp16 [px 112][o stride 264] ----
    __syncthreads();
    {
        int r = lane >> 2, q = 2*(lane & 3);
        #pragma unroll
        for (int mf = 0; mf < 4; mf++) {
            int o0 = wm*64 + mf*16 + r;
            #pragma unroll
            for (int nf = 0; nf < 7; nf++) {
                int px = wn*56 + nf*8 + q;
                hS[px*HS_STRIDE + o0]           = __float2half_rn(acc[mf][nf][0]);
                hS[(px+1)*HS_STRIDE + o0]       = __float2half_rn(acc[mf][nf][1]);
                hS[px*HS_STRIDE + o0 + 8]       = __float2half_rn(acc[mf][nf][2]);
                hS[(px+1)*HS_STRIDE + o0 + 8]   = __float2half_rn(acc[mf][nf][3]);
            }
        }
    }
    __syncthreads();

    // ---- GEMM2: out[80,112] = W2 . h ; warps 0..6 take px frags {2w,2w+1} ----
    if (wid < 7) {
        uint32_t hbase = smem_u32(hS);
        float acc2[5][2][4];
        #pragma unroll
        for (int mf = 0; mf < 5; mf++)
            #pragma unroll
            for (int j = 0; j < 2; j++)
                #pragma unroll
                for (int q = 0; q < 4; q++) acc2[mf][j][q] = 0.f;

        #pragma unroll 1
        for (int kc = 0; kc < 16; kc++) {
            uint32_t a[5][4];
            #pragma unroll
            for (int mf = 0; mf < 5; mf++) {
                uint4 av = *(const uint4*)(g_w2h + (size_t)(kc*8 + mf)*256 + lane*8);
                a[mf][0] = av.x; a[mf][1] = av.y; a[mf][2] = av.z; a[mf][3] = av.w;
            }
            #pragma unroll
            for (int j = 0; j < 2; j++) {
                int nf2 = 2*wid + j;
                uint32_t addr = hbase + (uint32_t)(((nf2*8 + rrow)*HS_STRIDE + kc*16 + khalf*8)*2);
                uint32_t b0, b1v;
                LDSM_X2(b0, b1v, addr);
                #pragma unroll
                for (int mf = 0; mf < 5; mf++)
                    MMA16816(acc2[mf][j], a[mf], b0, b1v);
            }
        }

        int r = lane >> 2, q = 2*(lane & 3);
        #pragma unroll
        for (int mf = 0; mf < 5; mf++) {
            int oc0 = mf*16 + r;
            float bb0 = g_b2eff[oc0], bb1 = g_b2eff[oc0 + 8];
            #pragma unroll
            for (int j = 0; j < 2; j++) {
                int px = (2*wid + j)*8 + q;
                float* o0p = out + ((size_t)n*OC2 + oc0)*HW + (size_t)i0*WW + px;
                float* o1p = o0p + (size_t)8*HW;
                *(float2*)o0p = make_float2(acc2[mf][j][0] + bb0, acc2[mf][j][1] + bb0);
                *(float2*)o1p = make_float2(acc2[mf][j][2] + bb1, acc2[mf][j][3] + bb1);
            }
        }
    }
}

// ---------------- border correction: HMMA dH then W2.dH, RMW out ----------
__global__ void __launch_bounds__(256) corr_kernel(float* __restrict__ out) {
    __shared__ __align__(16) __half xs[32*264];
    __shared__ __align__(16) __half hC[32*264];
    int tid  = threadIdx.x;
    int lane = tid & 31, w = tid >> 5;
    int pi, pj; band_pos(blockIdx.x, pi, pj);
    int ci = pi < 2 ? pi : (pi > 53 ? pi - 51 : 2);
    int cj = pj < 2 ? pj : (pj > 53 ? pj - 51 : 2);
    int cls = ci*5 + cj;

    float acc[2][4][4];
    #pragma unroll
    for (int m = 0; m < 2; m++)
        #pragma unroll
        for (int nf = 0; nf < 4; nf++)
            #pragma unroll
            for (int q = 0; q < 4; q++) acc[m][nf][q] = 0.f;

    uint32_t sh0 = smem_u32(xs);
    int nfsel = (lane >> 4) & 1;
    int khalf = (lane >> 3) & 1;
    int row   = lane & 7;

    #pragma unroll 1
    for (int slot = 0; slot < 25; slot++) {
        int sc = cls*25 + slot;
        if (g_aggcnt[sc] == 0) continue;
        int si = pi + slot/5 - 2, sj = pj + slot%5 - 2;
        const __half* xsrc = g_xh + ((size_t)si*WW + sj)*CC;

        __syncthreads();
        #pragma unroll
        for (int it = 0; it < 4; it++) {
            int e = tid + it*256;
            int nn = e >> 5, ch = e & 31;
            uint4 v = *(const uint4*)(xsrc + (size_t)nn*HW*CC + ch*8);
            *(uint4*)(xs + nn*264 + ch*8) = v;
        }
        __syncthreads();

        const __half* aT = g_waggh + (size_t)sc*65536 + (2*w)*256 + lane*8;
        #pragma unroll 1
        for (int kc = 0; kc < 16; kc++) {
            uint4 a0v = *(const uint4*)(aT + kc*4096);
            uint4 a1v = *(const uint4*)(aT + kc*4096 + 256);
            uint32_t a0[4] = {a0v.x, a0v.y, a0v.z, a0v.w};
            uint32_t a1[4] = {a1v.x, a1v.y, a1v.z, a1v.w};
            uint32_t b[4][2];
            #pragma unroll
            for (int nfp = 0; nfp < 2; nfp++) {
                int nrow = (nfp*2 + nfsel)*8 + row;
                uint32_t addr = sh0 + (uint32_t)((nrow*264 + kc*16 + khalf*8)*2);
                uint32_t r0, r1, r2, r3;
                LDSM_X4(r0, r1, r2, r3, addr);
                b[nfp*2    ][0] = r0; b[nfp*2    ][1] = r1;
                b[nfp*2 + 1][0] = r2; b[nfp*2 + 1][1] = r3;
            }
            #pragma unroll
            for (int nf = 0; nf < 4; nf++) {
                MMA16816(acc[0][nf], a0, b[nf][0], b[nf][1]);
                MMA16816(acc[1][nf], a1, b[nf][0], b[nf][1]);
            }
        }
    }

    // spill dH to SMEM [n=32 rows][o stride 264] fp16
    __syncthreads();
    {
        int r = lane >> 2, q2 = 2*(lane & 3);
        #pragma unroll
        for (int m = 0; m < 2; m++) {
            int o0 = w*32 + m*16 + r;
            #pragma unroll
            for (int nf = 0; nf < 4; nf++) {
                int n0 = nf*8 + q2;
                hC[n0*264 + o0]           = __float2half_rn(acc[m][nf][0]);
                hC[(n0+1)*264 + o0]       = __float2half_rn(acc[m][nf][1]);
                hC[n0*264 + o0 + 8]       = __float2half_rn(acc[m][nf][2]);
                hC[(n0+1)*264 + o0 + 8]   = __float2half_rn(acc[m][nf][3]);
            }
        }
    }
    __syncthreads();

    // GEMM2: dOut[80,32] = W2 . dH ; warps 0..4 take mf = w
    if (w < 5) {
        uint32_t hbase = smem_u32(hC);
        float acc2[4][4];
        #pragma unroll
        for (int nf = 0; nf < 4; nf++)
            #pragma unroll
            for (int q = 0; q < 4; q++) acc2[nf][q] = 0.f;

        #pragma unroll 1
        for (int kc = 0; kc < 16; kc++) {
            uint4 av = *(const uint4*)(g_w2h + (size_t)(kc*8 + w)*256 + lane*8);
            uint32_t a[4] = {av.x, av.y, av.z, av.w};
            #pragma unroll
            for (int nf = 0; nf < 4; nf++) {
                uint32_t addr = hbase + (uint32_t)(((nf*8 + row)*264 + kc*16 + khalf*8)*2);
                uint32_t b0, b1v;
                LDSM_X2(b0, b1v, addr);
                MMA16816(acc2[nf], a, b0, b1v);
            }
        }

        // RMW into out (unique writer per element; ordered after conv5 kernel)
        int r = lane >> 2, q2 = 2*(lane & 3);
        size_t pix = (size_t)pi*WW + pj;
        #pragma unroll
        for (int nf = 0; nf < 4; nf++) {
            int n0 = nf*8 + q2;
            int oc0 = w*16 + r;
            float* p00 = out + ((size_t)n0*OC2 + oc0)*HW + pix;
            float* p10 = out + ((size_t)(n0+1)*OC2 + oc0)*HW + pix;
            p00[0]          += acc2[nf][0];
            p10[0]          += acc2[nf][1];
            p00[(size_t)8*HW] += acc2[nf][2];
            p10[(size_t)8*HW] += acc2[nf][3];
        }
    }
}

extern "C" void kernel_launch(void* const* d_in, const int* in_sizes, int n_in,
                              void* d_out, int out_size) {
    const float *x = nullptr, *w1 = nullptr, *b1 = nullptr, *w2 = nullptr, *b2 = nullptr;
    for (int i = 0; i < n_in; i++) {
        long s = in_sizes[i];
        const float* p = (const float*)d_in[i];
        if      (s == (long)NN*CC*HW)   x  = p;
        else if (s == (long)CC*9*CC*9)  w1 = p;
        else if (s == CC)               b1 = p;
        else if (s == (long)OC2*CC)     w2 = p;
        else if (s == OC2)              b2 = p;
    }
    float* out = (float*)d_out;

    cudaFuncSetAttribute(conv5_mma_kernel,
                         cudaFuncAttributeMaxDynamicSharedMemorySize, CONV5_SMEM);

    fold_kernel<<<(CC*25*CC + 255)/256, 256>>>(w1);
    wprep_kernel<<<(400*4096 + 255)/256, 256>>>();
    xprep_kernel<<<dim3(98, 8, NN), 256>>>(x);
    aggtab_kernel<<<1, 640>>>();
    wagg_kernel<<<dim3(625, 16), 256>>>(w1);
    w2prep_kernel<<<(16*2048 + 255)/256, 256>>>(w2);
    b2eff_kernel<<<1, 128>>>(w2, b1, b2);
    conv5_mma_kernel<<<dim3(28, NN), 256, CONV5_SMEM>>>(out);
    corr_kernel<<<NBAND, 256>>>(out);
}